// round 2
// baseline (speedup 1.0000x reference)
#include <cuda_runtime.h>
#include <stdint.h>
#include <math.h>

#define HDIM 256
#define BATCH 64
#define S_TOK 2048
#define S_OTH 512
#define NEGV (-1e9f)

// ---------------- scratch (no allocations allowed) ----------------
__device__ float g_scores[BATCH*S_TOK + 3*BATCH*S_OTH];   // tok | graph | da | dn
__device__ float g_pool[4][BATCH*HDIM];                    // tok, gr, da, dn (post-tanh applied)
__device__ float g_code[BATCH*HDIM];

// ---------------- score kernel: s[b,i] = v . tanh(feat_row @ W + b) + c ----------------
struct ScoreArgs {
    const float* feat;
    const float* W;
    const float* bv;
    const float* v;
    const float* c;
    float* sout;
    int pretanh;
    int blkStart;
};

__global__ __launch_bounds__(256) void score_kernel(ScoreArgs A0, ScoreArgs A1,
                                                    ScoreArgs A2, ScoreArgs A3) {
    ScoreArgs A;
    int blk = blockIdx.x;
    if (blk >= A3.blkStart)      A = A3;
    else if (blk >= A2.blkStart) A = A2;
    else if (blk >= A1.blkStart) A = A1;
    else                         A = A0;
    int row0 = (blk - A.blkStart) * 32;

    __shared__ float sf[32 * HDIM];     // 32 feature rows (32 KB)
    __shared__ float red[32][65];       // per-row partial score reduction

    // load 32 rows into smem (vectorized), apply pre-tanh for graph pool
    {
        const float4* f4 = (const float4*)A.feat + (size_t)row0 * (HDIM / 4);
        float4* s4 = (float4*)sf;
        for (int i = threadIdx.x; i < 32 * (HDIM / 4); i += 256) {
            float4 t = f4[i];
            if (A.pretanh) {
                t.x = tanhf(t.x); t.y = tanhf(t.y);
                t.z = tanhf(t.z); t.w = tanhf(t.w);
            }
            s4[i] = t;
        }
    }
    __syncthreads();

    const int ct = threadIdx.x & 63;   // column group: cols 4*ct .. 4*ct+3
    const int rt = threadIdx.x >> 6;   // row group: rows rt*8 .. rt*8+7

    float acc[8][4];
#pragma unroll
    for (int r = 0; r < 8; r++) {
        acc[r][0] = 0.f; acc[r][1] = 0.f; acc[r][2] = 0.f; acc[r][3] = 0.f;
    }

    const float4* W4 = (const float4*)A.W + ct;   // W[h][4ct..4ct+3]
    const float* sfr = sf + rt * 8 * HDIM;

#pragma unroll 4
    for (int h = 0; h < HDIM; h++) {
        float4 w = W4[h * (HDIM / 4)];
#pragma unroll
        for (int r = 0; r < 8; r++) {
            float f = sfr[r * HDIM + h];        // warp-uniform smem broadcast
            acc[r][0] += f * w.x;
            acc[r][1] += f * w.y;
            acc[r][2] += f * w.z;
            acc[r][3] += f * w.w;
        }
    }

    float4 bv = ((const float4*)A.bv)[ct];
    float4 vv = ((const float4*)A.v)[ct];
#pragma unroll
    for (int r = 0; r < 8; r++) {
        float p = tanhf(acc[r][0] + bv.x) * vv.x
                + tanhf(acc[r][1] + bv.y) * vv.y
                + tanhf(acc[r][2] + bv.z) * vv.z
                + tanhf(acc[r][3] + bv.w) * vv.w;
        red[rt * 8 + r][ct] = p;
    }
    __syncthreads();

    if (threadIdx.x < 32) {
        float s = A.c[0];
#pragma unroll 8
        for (int j = 0; j < 64; j++) s += red[threadIdx.x][j];
        A.sout[row0 + threadIdx.x] = s;
    }
}

// ---------------- softmax + weighted pool + post-tanh ----------------
struct PoolArgs {
    const float* feat;
    const int* mask;        // masks arrive as int32 (harness materializes bool as int32)
    const float* scores;
    float* out;
    int S;
    int pretanh;
    int posttanh;
};

__global__ __launch_bounds__(256) void pool_kernel(PoolArgs A0, PoolArgs A1,
                                                   PoolArgs A2, PoolArgs A3) {
    int pool = blockIdx.x & 3;
    int b    = blockIdx.x >> 2;
    PoolArgs A = (pool == 0) ? A0 : (pool == 1) ? A1 : (pool == 2) ? A2 : A3;

    __shared__ float w[S_TOK];
    __shared__ float red[256];

    const int tid = threadIdx.x;
    const int S = A.S;
    const float* sc = A.scores + (size_t)b * S;
    const int* mk = A.mask + (size_t)b * S;

    // pass 1: masked scores into smem, block max
    float m = -3.4e38f;
    for (int s = tid; s < S; s += 256) {
        float x = mk[s] ? sc[s] : NEGV;
        w[s] = x;
        m = fmaxf(m, x);
    }
    red[tid] = m;
    __syncthreads();
    for (int st = 128; st > 0; st >>= 1) {
        if (tid < st) red[tid] = fmaxf(red[tid], red[tid + st]);
        __syncthreads();
    }
    m = red[0];
    __syncthreads();

    // pass 2: exp + block sum
    float e = 0.f;
    for (int s = tid; s < S; s += 256) {
        float ex = __expf(w[s] - m);
        w[s] = ex;
        e += ex;
    }
    red[tid] = e;
    __syncthreads();
    for (int st = 128; st > 0; st >>= 1) {
        if (tid < st) red[tid] += red[tid + st];
        __syncthreads();
    }
    float inv = 1.f / red[0];
    __syncthreads();

    // pass 3: weighted sum over S for column h = tid
    const float* f = A.feat + (size_t)b * S * HDIM + tid;
    float acc = 0.f;
    for (int s = 0; s < S; s++) {
        float x = f[(size_t)s * HDIM];
        if (A.pretanh) x = tanhf(x);
        acc += w[s] * x;
    }
    acc *= inv;
    acc = tanhf(acc);
    if (A.posttanh == 2) acc = tanhf(acc);
    A.out[b * HDIM + tid] = acc;
}

// ---------------- code = tanh([tok, gr] @ Wf + bf) ----------------
__global__ __launch_bounds__(256) void code_kernel(const float* Wf, const float* bfv) {
    int b = blockIdx.x, k = threadIdx.x;
    __shared__ float cat[2 * HDIM];
    cat[k]        = g_pool[0][b * HDIM + k];
    cat[HDIM + k] = g_pool[1][b * HDIM + k];
    __syncthreads();
    float acc = bfv[k];
#pragma unroll 8
    for (int j = 0; j < 2 * HDIM; j++) acc += cat[j] * Wf[j * HDIM + k];
    g_code[b * HDIM + k] = tanhf(acc);
}

// ---------------- final cosine + hinge + mean (deterministic, 1 block) ----------------
__global__ __launch_bounds__(256) void loss_kernel(float* out) {
    __shared__ float red[256];
    __shared__ float sums[5];
    const int tid = threadIdx.x;
    float total = 0.f;
    for (int b = 0; b < BATCH; b++) {
        float c = g_code[b * HDIM + tid];
        float a = g_pool[2][b * HDIM + tid];
        float n = g_pool[3][b * HDIM + tid];
        float vals[5] = {c * c, a * a, n * n, c * a, c * n};
        for (int q = 0; q < 5; q++) {
            red[tid] = vals[q];
            __syncthreads();
            for (int st = 128; st > 0; st >>= 1) {
                if (tid < st) red[tid] += red[tid + st];
                __syncthreads();
            }
            if (tid == 0) sums[q] = red[0];
            __syncthreads();
        }
        if (tid == 0) {
            float nc = sqrtf(sums[0]);
            float sa = sums[3] / fmaxf(nc * sqrtf(sums[1]), 1e-8f);
            float sn = sums[4] / fmaxf(nc * sqrtf(sums[2]), 1e-8f);
            total += fmaxf(0.6f - sa + sn, 0.f);
        }
    }
    if (tid == 0) out[0] = total / (float)BATCH;
}

// ---------------- launch ----------------
extern "C" void kernel_launch(void* const* d_in, const int* in_sizes, int n_in,
                              void* d_out, int out_size) {
    const float* token_feat = (const float*)d_in[0];
    const int*   token_mask = (const int*)d_in[1];
    const float* graph_feat = (const float*)d_in[2];
    const int*   graph_mask = (const int*)d_in[3];
    const float* da_feat    = (const float*)d_in[4];
    const int*   da_mask    = (const int*)d_in[5];
    const float* dn_feat    = (const float*)d_in[6];
    const int*   dn_mask    = (const int*)d_in[7];
    const float* Wt = (const float*)d_in[8];
    const float* bt = (const float*)d_in[9];
    const float* vt = (const float*)d_in[10];
    const float* ct = (const float*)d_in[11];
    const float* Wg = (const float*)d_in[12];
    const float* bg = (const float*)d_in[13];
    const float* vg = (const float*)d_in[14];
    const float* cg = (const float*)d_in[15];
    const float* Wd = (const float*)d_in[16];
    const float* bd = (const float*)d_in[17];
    const float* vd = (const float*)d_in[18];
    const float* cd = (const float*)d_in[19];
    const float* Wf = (const float*)d_in[20];
    const float* bf = (const float*)d_in[21];

    float* scores = nullptr;
    float* poolp  = nullptr;
    cudaGetSymbolAddress((void**)&scores, g_scores);
    cudaGetSymbolAddress((void**)&poolp, g_pool);

    float* s_tok = scores;
    float* s_gr  = scores + BATCH * S_TOK;
    float* s_da  = s_gr + BATCH * S_OTH;
    float* s_dn  = s_da + BATCH * S_OTH;

    const int nTok = BATCH * S_TOK / 32;  // 4096
    const int nOth = BATCH * S_OTH / 32;  // 1024

    ScoreArgs sa0 = {token_feat, Wt, bt, vt, ct, s_tok, 0, 0};
    ScoreArgs sa1 = {graph_feat, Wg, bg, vg, cg, s_gr,  1, nTok};
    ScoreArgs sa2 = {da_feat,    Wd, bd, vd, cd, s_da,  0, nTok + nOth};
    ScoreArgs sa3 = {dn_feat,    Wd, bd, vd, cd, s_dn,  0, nTok + 2 * nOth};
    score_kernel<<<nTok + 3 * nOth, 256>>>(sa0, sa1, sa2, sa3);

    PoolArgs pa0 = {token_feat, token_mask, s_tok, poolp + 0 * BATCH * HDIM, S_TOK, 0, 1};
    PoolArgs pa1 = {graph_feat, graph_mask, s_gr,  poolp + 1 * BATCH * HDIM, S_OTH, 1, 1};
    PoolArgs pa2 = {da_feat,    da_mask,    s_da,  poolp + 2 * BATCH * HDIM, S_OTH, 0, 2};
    PoolArgs pa3 = {dn_feat,    dn_mask,    s_dn,  poolp + 3 * BATCH * HDIM, S_OTH, 0, 2};
    pool_kernel<<<4 * BATCH, 256>>>(pa0, pa1, pa2, pa3);

    code_kernel<<<BATCH, 256>>>(Wf, bf);
    loss_kernel<<<1, 256>>>((float*)d_out);
}

// round 3
// speedup vs baseline: 1.8066x; 1.8066x over previous
#include <cuda_runtime.h>
#include <cuda_bf16.h>
#include <stdint.h>
#include <math.h>

#define HDIM 256
#define BATCH 64
#define S_TOK 2048
#define S_OTH 512
#define NEGV (-1e9f)

#define A_STRIDE 264   // bf16 elems per A smem row (256 + 8 pad; 528B = 4-bank rotation)
#define W_STRIDE 136   // bf16 elems per W smem row (128 + 8 pad; 272B = 4-bank rotation)

// smem bytes: A hi/lo (2*128*264*2) + W hi/lo (2*64*136*2) + bias/v/part (3*256*4)
#define SCORE_SMEM (2*128*A_STRIDE*2 + 2*64*W_STRIDE*2 + 3*256*4)

// ---------------- scratch (no allocations allowed) ----------------
__device__ float g_scores[BATCH*S_TOK + 3*BATCH*S_OTH];
__device__ float g_pool[4][BATCH*HDIM];
__device__ float g_code[BATCH*HDIM];
__device__ float g_hinge[BATCH];

// ---------------- tensor-core score kernel ----------------
// s[b,i] = v . tanh(feat_row @ W + b) + c, via bf16 split GEMM (3 terms, fp32 accum)
struct ScoreArgs {
    const float* feat;
    const float* W;
    const float* bv;
    const float* v;
    const float* c;
    float* sout;
    int pretanh;
    int blkStart;
};

#define LDSM_X4(r0,r1,r2,r3,addr) \
    asm volatile("ldmatrix.sync.aligned.m8n8.x4.shared.b16 {%0,%1,%2,%3}, [%4];" \
        : "=r"(r0),"=r"(r1),"=r"(r2),"=r"(r3) : "r"(addr))

#define LDSM_X4_T(r0,r1,r2,r3,addr) \
    asm volatile("ldmatrix.sync.aligned.m8n8.x4.trans.shared.b16 {%0,%1,%2,%3}, [%4];" \
        : "=r"(r0),"=r"(r1),"=r"(r2),"=r"(r3) : "r"(addr))

#define MMA_BF16(c, a, b) \
    asm volatile("mma.sync.aligned.m16n8k16.row.col.f32.bf16.bf16.f32 " \
        "{%0,%1,%2,%3},{%4,%5,%6,%7},{%8,%9},{%0,%1,%2,%3};" \
        : "+f"((c)[0]),"+f"((c)[1]),"+f"((c)[2]),"+f"((c)[3]) \
        : "r"((a)[0]),"r"((a)[1]),"r"((a)[2]),"r"((a)[3]),"r"((b)[0]),"r"((b)[1]))

__global__ __launch_bounds__(256, 1) void score_kernel(ScoreArgs A0, ScoreArgs A1,
                                                       ScoreArgs A2, ScoreArgs A3) {
    ScoreArgs A;
    int blk = blockIdx.x;
    if (blk >= A3.blkStart)      A = A3;
    else if (blk >= A2.blkStart) A = A2;
    else if (blk >= A1.blkStart) A = A1;
    else                         A = A0;
    const int row0 = (blk - A.blkStart) * 128;

    extern __shared__ char smem[];
    __nv_bfloat16* sAhi = (__nv_bfloat16*)smem;
    __nv_bfloat16* sAlo = sAhi + 128 * A_STRIDE;
    __nv_bfloat16* sWhi = sAlo + 128 * A_STRIDE;
    __nv_bfloat16* sWlo = sWhi + 64 * W_STRIDE;
    float* sBias = (float*)(sWlo + 64 * W_STRIDE);
    float* sV    = sBias + 256;
    float* sPart = sV + 256;     // [128][2]

    const int tid  = threadIdx.x;
    const int warp = tid >> 5;
    const int lane = tid & 31;
    const int wm = warp & 3;     // 4 m-warps (32 rows each)
    const int wn = warp >> 2;    // 2 n-warps (64 cols each)
    const int tq = lane & 3;     // quad position
    const int gp = lane >> 2;    // group (row within 8)

    sBias[tid] = A.bv[tid];
    sV[tid]    = A.v[tid];
    sPart[tid] = 0.f;

    // ---- load A (128 rows x 256 cols fp32), split to bf16 hi/lo ----
    {
        const float4* f4 = (const float4*)A.feat + (size_t)row0 * (HDIM / 4);
        const int pt = A.pretanh;
        for (int i = tid; i < 128 * 64; i += 256) {
            float4 t = f4[i];
            if (pt) { t.x = tanhf(t.x); t.y = tanhf(t.y); t.z = tanhf(t.z); t.w = tanhf(t.w); }
            int r = i >> 6, c = (i & 63) << 2;
            __nv_bfloat16 h0 = __float2bfloat16(t.x);
            __nv_bfloat16 h1 = __float2bfloat16(t.y);
            __nv_bfloat16 h2 = __float2bfloat16(t.z);
            __nv_bfloat16 h3 = __float2bfloat16(t.w);
            __nv_bfloat16* ph = sAhi + r * A_STRIDE + c;
            ph[0] = h0; ph[1] = h1; ph[2] = h2; ph[3] = h3;
            __nv_bfloat16* pl = sAlo + r * A_STRIDE + c;
            pl[0] = __float2bfloat16(t.x - __bfloat162float(h0));
            pl[1] = __float2bfloat16(t.y - __bfloat162float(h1));
            pl[2] = __float2bfloat16(t.z - __bfloat162float(h2));
            pl[3] = __float2bfloat16(t.w - __bfloat162float(h3));
        }
    }
    __syncthreads();

    const uint32_t aHiBase = (uint32_t)__cvta_generic_to_shared(sAhi);
    const uint32_t aLoBase = (uint32_t)__cvta_generic_to_shared(sAlo);
    const uint32_t wHiBase = (uint32_t)__cvta_generic_to_shared(sWhi);
    const uint32_t wLoBase = (uint32_t)__cvta_generic_to_shared(sWlo);

    // lane-invariant address parts (bytes)
    const uint32_t aLaneOff = (uint32_t)(((wm * 32 + (lane & 15)) * A_STRIDE + ((lane >> 4) << 3)) * 2);
    const uint32_t bLaneOff = (uint32_t)(((lane & 15) * W_STRIDE + wn * 64 + ((lane >> 4) << 3)) * 2);

    for (int half = 0; half < 2; half++) {
        float acc[2][8][4];
#pragma unroll
        for (int mi = 0; mi < 2; mi++)
#pragma unroll
            for (int nj = 0; nj < 8; nj++) {
                acc[mi][nj][0] = 0.f; acc[mi][nj][1] = 0.f;
                acc[mi][nj][2] = 0.f; acc[mi][nj][3] = 0.f;
            }

        for (int kc = 0; kc < 4; kc++) {
            __syncthreads();   // protect W smem reuse
            // load W chunk [64 k][128 n] fp32 -> bf16 hi/lo
            {
                const float* Wg = A.W + (size_t)(kc * 64) * HDIM + half * 128;
                for (int i = tid; i < 64 * 32; i += 256) {
                    int r = i >> 5, c4 = i & 31;
                    float4 t = ((const float4*)(Wg + (size_t)r * HDIM))[c4];
                    int c = c4 << 2;
                    __nv_bfloat16 h0 = __float2bfloat16(t.x);
                    __nv_bfloat16 h1 = __float2bfloat16(t.y);
                    __nv_bfloat16 h2 = __float2bfloat16(t.z);
                    __nv_bfloat16 h3 = __float2bfloat16(t.w);
                    __nv_bfloat16* ph = sWhi + r * W_STRIDE + c;
                    ph[0] = h0; ph[1] = h1; ph[2] = h2; ph[3] = h3;
                    __nv_bfloat16* pl = sWlo + r * W_STRIDE + c;
                    pl[0] = __float2bfloat16(t.x - __bfloat162float(h0));
                    pl[1] = __float2bfloat16(t.y - __bfloat162float(h1));
                    pl[2] = __float2bfloat16(t.z - __bfloat162float(h2));
                    pl[3] = __float2bfloat16(t.w - __bfloat162float(h3));
                }
            }
            __syncthreads();

#pragma unroll
            for (int ks = 0; ks < 4; ks++) {
                const uint32_t kOffA = (uint32_t)((kc * 64 + ks * 16) * 2);
                const uint32_t kOffB = (uint32_t)((ks * 16) * W_STRIDE * 2);

                uint32_t aH[2][4], aL[2][4];
#pragma unroll
                for (int mi = 0; mi < 2; mi++) {
                    uint32_t ad = aLaneOff + (uint32_t)(mi * 16 * A_STRIDE * 2) + kOffA;
                    LDSM_X4(aH[mi][0], aH[mi][1], aH[mi][2], aH[mi][3], aHiBase + ad);
                    LDSM_X4(aL[mi][0], aL[mi][1], aL[mi][2], aL[mi][3], aLoBase + ad);
                }
                uint32_t bH[8][2], bL[8][2];
#pragma unroll
                for (int nt = 0; nt < 4; nt++) {
                    uint32_t bd = bLaneOff + kOffB + (uint32_t)(nt * 16 * 2);
                    uint32_t r0, r1, r2, r3;
                    LDSM_X4_T(r0, r1, r2, r3, wHiBase + bd);
                    bH[2*nt][0] = r0; bH[2*nt][1] = r1;
                    bH[2*nt+1][0] = r2; bH[2*nt+1][1] = r3;
                    LDSM_X4_T(r0, r1, r2, r3, wLoBase + bd);
                    bL[2*nt][0] = r0; bL[2*nt][1] = r1;
                    bL[2*nt+1][0] = r2; bL[2*nt+1][1] = r3;
                }
#pragma unroll
                for (int mi = 0; mi < 2; mi++)
#pragma unroll
                    for (int nj = 0; nj < 8; nj++) {
                        MMA_BF16(acc[mi][nj], aH[mi], bH[nj]);
                        MMA_BF16(acc[mi][nj], aL[mi], bH[nj]);
                        MMA_BF16(acc[mi][nj], aH[mi], bL[nj]);
                    }
            }
        }

        // epilogue for this N-half: tanh(acc+b)*v, reduce over cols
#pragma unroll
        for (int mi = 0; mi < 2; mi++) {
            float p0 = 0.f, p1 = 0.f;
#pragma unroll
            for (int nj = 0; nj < 8; nj++) {
                int col = half * 128 + wn * 64 + nj * 8 + tq * 2;
                float b0 = sBias[col], b1 = sBias[col + 1];
                float v0 = sV[col],    v1 = sV[col + 1];
                p0 += tanhf(acc[mi][nj][0] + b0) * v0 + tanhf(acc[mi][nj][1] + b1) * v1;
                p1 += tanhf(acc[mi][nj][2] + b0) * v0 + tanhf(acc[mi][nj][3] + b1) * v1;
            }
            p0 += __shfl_xor_sync(0xffffffffu, p0, 1);
            p0 += __shfl_xor_sync(0xffffffffu, p0, 2);
            p1 += __shfl_xor_sync(0xffffffffu, p1, 1);
            p1 += __shfl_xor_sync(0xffffffffu, p1, 2);
            if (tq == 0) {
                int r0 = wm * 32 + mi * 16 + gp;
                sPart[r0 * 2 + wn]       += p0;
                sPart[(r0 + 8) * 2 + wn] += p1;
            }
        }
    }
    __syncthreads();
    if (tid < 128)
        A.sout[row0 + tid] = sPart[tid * 2] + sPart[tid * 2 + 1] + A.c[0];
}

// ---------------- softmax + weighted pool + post-tanh (512 threads) ----------------
struct PoolArgs {
    const float* feat;
    const int* mask;
    const float* scores;
    float* out;
    int S;
    int pretanh;
    int posttanh;
};

__global__ __launch_bounds__(512) void pool_kernel(PoolArgs A0, PoolArgs A1,
                                                   PoolArgs A2, PoolArgs A3) {
    int pool = blockIdx.x & 3;
    int b    = blockIdx.x >> 2;
    PoolArgs A = (pool == 0) ? A0 : (pool == 1) ? A1 : (pool == 2) ? A2 : A3;

    __shared__ float w[S_TOK];
    __shared__ float red[512];

    const int tid = threadIdx.x;
    const int S = A.S;
    const float* sc = A.scores + (size_t)b * S;
    const int* mk = A.mask + (size_t)b * S;

    float m = -3.4e38f;
    for (int s = tid; s < S; s += 512) {
        float x = mk[s] ? sc[s] : NEGV;
        w[s] = x;
        m = fmaxf(m, x);
    }
    red[tid] = m;
    __syncthreads();
    for (int st = 256; st > 0; st >>= 1) {
        if (tid < st) red[tid] = fmaxf(red[tid], red[tid + st]);
        __syncthreads();
    }
    m = red[0];
    __syncthreads();

    float e = 0.f;
    for (int s = tid; s < S; s += 512) {
        float ex = __expf(w[s] - m);
        w[s] = ex;
        e += ex;
    }
    red[tid] = e;
    __syncthreads();
    for (int st = 256; st > 0; st >>= 1) {
        if (tid < st) red[tid] += red[tid + st];
        __syncthreads();
    }
    float inv = 1.f / red[0];
    __syncthreads();

    // weighted sum: col = tid&255, two s-stripes
    const int col = tid & 255;
    const int so  = tid >> 8;
    const float* f = A.feat + (size_t)b * S * HDIM + col;
    float acc = 0.f;
    if (A.pretanh) {
        for (int s = so; s < S; s += 2)
            acc += w[s] * tanhf(f[(size_t)s * HDIM]);
    } else {
#pragma unroll 4
        for (int s = so; s < S; s += 2)
            acc += w[s] * f[(size_t)s * HDIM];
    }
    red[tid] = acc;
    __syncthreads();
    if (tid < 256) {
        float r = (red[tid] + red[tid + 256]) * inv;
        r = tanhf(r);
        if (A.posttanh == 2) r = tanhf(r);
        A.out[b * HDIM + tid] = r;
    }
}

// ---------------- code = tanh([tok, gr] @ Wf + bf) ----------------
__global__ __launch_bounds__(256) void code_kernel(const float* Wf, const float* bfv) {
    int b = blockIdx.x, k = threadIdx.x;
    __shared__ float cat[2 * HDIM];
    cat[k]        = g_pool[0][b * HDIM + k];
    cat[HDIM + k] = g_pool[1][b * HDIM + k];
    __syncthreads();
    float acc = bfv[k];
#pragma unroll 8
    for (int j = 0; j < 2 * HDIM; j++) acc += cat[j] * Wf[j * HDIM + k];
    g_code[b * HDIM + k] = tanhf(acc);
}

// ---------------- per-batch hinge (64 blocks, warp-shuffle reduce) ----------------
__global__ __launch_bounds__(256) void loss1_kernel() {
    const int b = blockIdx.x;
    const int tid = threadIdx.x;
    const int warp = tid >> 5, lane = tid & 31;
    __shared__ float sm[8][5];

    float c = g_code[b * HDIM + tid];
    float a = g_pool[2][b * HDIM + tid];
    float n = g_pool[3][b * HDIM + tid];
    float s0 = c * c, s1 = a * a, s2 = n * n, s3 = c * a, s4 = c * n;
#pragma unroll
    for (int o = 16; o > 0; o >>= 1) {
        s0 += __shfl_xor_sync(0xffffffffu, s0, o);
        s1 += __shfl_xor_sync(0xffffffffu, s1, o);
        s2 += __shfl_xor_sync(0xffffffffu, s2, o);
        s3 += __shfl_xor_sync(0xffffffffu, s3, o);
        s4 += __shfl_xor_sync(0xffffffffu, s4, o);
    }
    if (lane == 0) {
        sm[warp][0] = s0; sm[warp][1] = s1; sm[warp][2] = s2;
        sm[warp][3] = s3; sm[warp][4] = s4;
    }
    __syncthreads();
    if (tid == 0) {
        float t0 = 0, t1 = 0, t2 = 0, t3 = 0, t4 = 0;
#pragma unroll
        for (int wv = 0; wv < 8; wv++) {
            t0 += sm[wv][0]; t1 += sm[wv][1]; t2 += sm[wv][2];
            t3 += sm[wv][3]; t4 += sm[wv][4];
        }
        float nc = sqrtf(t0);
        float sa = t3 / fmaxf(nc * sqrtf(t1), 1e-8f);
        float sn = t4 / fmaxf(nc * sqrtf(t2), 1e-8f);
        g_hinge[b] = fmaxf(0.6f - sa + sn, 0.f);
    }
}

__global__ void loss2_kernel(float* out) {
    int t = threadIdx.x;   // 32 threads
    float v = g_hinge[t] + g_hinge[t + 32];
#pragma unroll
    for (int o = 16; o > 0; o >>= 1) v += __shfl_xor_sync(0xffffffffu, v, o);
    if (t == 0) out[0] = v / (float)BATCH;
}

// ---------------- launch ----------------
extern "C" void kernel_launch(void* const* d_in, const int* in_sizes, int n_in,
                              void* d_out, int out_size) {
    const float* token_feat = (const float*)d_in[0];
    const int*   token_mask = (const int*)d_in[1];
    const float* graph_feat = (const float*)d_in[2];
    const int*   graph_mask = (const int*)d_in[3];
    const float* da_feat    = (const float*)d_in[4];
    const int*   da_mask    = (const int*)d_in[5];
    const float* dn_feat    = (const float*)d_in[6];
    const int*   dn_mask    = (const int*)d_in[7];
    const float* Wt = (const float*)d_in[8];
    const float* bt = (const float*)d_in[9];
    const float* vt = (const float*)d_in[10];
    const float* ct = (const float*)d_in[11];
    const float* Wg = (const float*)d_in[12];
    const float* bg = (const float*)d_in[13];
    const float* vg = (const float*)d_in[14];
    const float* cg = (const float*)d_in[15];
    const float* Wd = (const float*)d_in[16];
    const float* bd = (const float*)d_in[17];
    const float* vd = (const float*)d_in[18];
    const float* cd = (const float*)d_in[19];
    const float* Wf = (const float*)d_in[20];
    const float* bf = (const float*)d_in[21];

    cudaFuncSetAttribute(score_kernel, cudaFuncAttributeMaxDynamicSharedMemorySize, SCORE_SMEM);

    float* scores = nullptr;
    float* poolp  = nullptr;
    cudaGetSymbolAddress((void**)&scores, g_scores);
    cudaGetSymbolAddress((void**)&poolp, g_pool);

    float* s_tok = scores;
    float* s_gr  = scores + BATCH * S_TOK;
    float* s_da  = s_gr + BATCH * S_OTH;
    float* s_dn  = s_da + BATCH * S_OTH;

    const int nTok = BATCH * S_TOK / 128;   // 1024
    const int nOth = BATCH * S_OTH / 128;   // 256

    ScoreArgs sa0 = {token_feat, Wt, bt, vt, ct, s_tok, 0, 0};
    ScoreArgs sa1 = {graph_feat, Wg, bg, vg, cg, s_gr,  1, nTok};
    ScoreArgs sa2 = {da_feat,    Wd, bd, vd, cd, s_da,  0, nTok + nOth};
    ScoreArgs sa3 = {dn_feat,    Wd, bd, vd, cd, s_dn,  0, nTok + 2 * nOth};
    score_kernel<<<nTok + 3 * nOth, 256, SCORE_SMEM>>>(sa0, sa1, sa2, sa3);

    PoolArgs pa0 = {token_feat, token_mask, s_tok, poolp + 0 * BATCH * HDIM, S_TOK, 0, 1};
    PoolArgs pa1 = {graph_feat, graph_mask, s_gr,  poolp + 1 * BATCH * HDIM, S_OTH, 1, 1};
    PoolArgs pa2 = {da_feat,    da_mask,    s_da,  poolp + 2 * BATCH * HDIM, S_OTH, 0, 2};
    PoolArgs pa3 = {dn_feat,    dn_mask,    s_dn,  poolp + 3 * BATCH * HDIM, S_OTH, 0, 2};
    pool_kernel<<<4 * BATCH, 512>>>(pa0, pa1, pa2, pa3);

    code_kernel<<<BATCH, 256>>>(Wf, bf);
    loss1_kernel<<<BATCH, 256>>>();
    loss2_kernel<<<1, 32>>>((float*)d_out);
}

// round 5
// speedup vs baseline: 1.8730x; 1.0368x over previous
#include <cuda_runtime.h>
#include <cuda_bf16.h>
#include <stdint.h>
#include <math.h>

#define HDIM 256
#define BATCH 64
#define S_TOK 2048
#define S_OTH 512
#define NEGV (-1e9f)

// ---------------- scratch (no allocations allowed) ----------------
__device__ float g_scores[BATCH*S_TOK + 3*BATCH*S_OTH];
__device__ float g_pool[4][BATCH*HDIM];
__device__ float g_code[BATCH*HDIM];
__device__ float g_hinge[BATCH];
// W transposed + bf16-split: [mat 0..2][hi(0)/lo(1)][n*256+k]
__device__ __nv_bfloat16 g_WT[3 * 2 * 65536];

// ---------------- PTX helpers ----------------
__device__ __forceinline__ uint32_t smem_to_u32(const void* p) {
    uint32_t a;
    asm("{ .reg .u64 tmp; cvta.to.shared.u64 tmp, %1; cvt.u32.u64 %0, tmp; }" : "=r"(a) : "l"(p));
    return a;
}
#define LDSM_X4(r0,r1,r2,r3,addr) \
    asm volatile("ldmatrix.sync.aligned.m8n8.x4.shared.b16 {%0,%1,%2,%3}, [%4];" \
        : "=r"(r0),"=r"(r1),"=r"(r2),"=r"(r3) : "r"(addr))
#define MMA_BF16(c, a, b) \
    asm volatile("mma.sync.aligned.m16n8k16.row.col.f32.bf16.bf16.f32 " \
        "{%0,%1,%2,%3},{%4,%5,%6,%7},{%8,%9},{%0,%1,%2,%3};" \
        : "+f"((c)[0]),"+f"((c)[1]),"+f"((c)[2]),"+f"((c)[3]) \
        : "r"((a)[0]),"r"((a)[1]),"r"((a)[2]),"r"((a)[3]),"r"((b)[0]),"r"((b)[1]))
#define CP_ASYNC16(dst, src) \
    asm volatile("cp.async.cg.shared.global [%0], [%1], 16;" :: "r"(dst), "l"(src) : "memory")
#define CP_COMMIT() asm volatile("cp.async.commit_group;" ::: "memory")
#define CP_WAIT(n)  asm volatile("cp.async.wait_group %0;" :: "n"(n) : "memory")

// ---------------- W transpose + bf16 hi/lo split ----------------
__global__ void wconv_kernel(const float* Wt, const float* Wg, const float* Wd) {
    int mat = blockIdx.y;
    const float* W = (mat == 0) ? Wt : (mat == 1) ? Wg : Wd;
    int k = blockIdx.x, n = threadIdx.x;
    float f = W[k * 256 + n];
    __nv_bfloat16 h = __float2bfloat16(f);
    g_WT[mat * 131072 + n * 256 + k] = h;                                      // hi: WT[n][k]
    g_WT[mat * 131072 + 65536 + n * 256 + k] = __float2bfloat16(f - __bfloat162float(h)); // lo
}

// ---------------- score kernel: mma.sync bf16, 3-term split, cp.async dbl-buffer ----------------
#define A_ST 264                 // bf16 elems per A smem row (528B -> 16B bank rotation)
#define WB_ST_B 144              // bytes per W smem row (128 data + 16 pad)
#define SA_HI 0
#define SA_LO 67584              // 128*264*2
#define SW_OFF 135168            // 4 tiles of 18432: buf0{hi,lo}, buf1{hi,lo}
#define SW_TILE 18432            // 128*144
#define SW_BUF 36864
#define SBIAS 208896
#define SVV   209920
#define SPART 210944             // 128*2 floats
#define SCORE_SMEM 211968

struct ScoreArgs {
    const float* feat;
    const float* bv;
    const float* v;
    const float* c;
    float* sout;
    int pretanh;
    int blkStart;
    int wtOff;   // element offset into g_WT
};

__global__ __launch_bounds__(256, 1) void score_tc(ScoreArgs A0, ScoreArgs A1,
                                                   ScoreArgs A2, ScoreArgs A3,
                                                   const __nv_bfloat16* WTg) {
    ScoreArgs A;
    int blk = blockIdx.x;
    if (blk >= A3.blkStart)      A = A3;
    else if (blk >= A2.blkStart) A = A2;
    else if (blk >= A1.blkStart) A = A1;
    else                         A = A0;
    const int row0 = (blk - A.blkStart) * 128;

    extern __shared__ char smem[];
    const uint32_t sbase = smem_to_u32(smem);
    float* sBias = (float*)(smem + SBIAS);
    float* sV    = (float*)(smem + SVV);
    float* sPart = (float*)(smem + SPART);

    const int tid  = threadIdx.x;
    const int warp = tid >> 5;
    const int lane = tid & 31;
    const int wm = warp & 3;        // 4 m-warps (32 rows each)
    const int wn = warp >> 2;       // 2 n-warps (64 cols each within a 128-col half)
    const int tq = lane & 3;
    const int gp = lane >> 2;

    const __nv_bfloat16* WT = WTg + A.wtOff;

    // prefetch W chunk q=0 (half 0, kc 0) — overlaps with A conversion below
    {
        for (int i = tid; i < 2048; i += 256) {
            int hl = i >> 10, r = (i >> 3) & 127, j = i & 7;
            const __nv_bfloat16* src = WT + hl * 65536 + (size_t)r * 256 + j * 8;
            uint32_t dst = sbase + SW_OFF + hl * SW_TILE + (uint32_t)(r * WB_ST_B + j * 16);
            CP_ASYNC16(dst, src);
        }
        CP_COMMIT();
    }

    sBias[tid] = A.bv[tid];
    sV[tid]    = A.v[tid];
    if (tid < 128) { sPart[tid * 2] = 0.f; sPart[tid * 2 + 1] = 0.f; }

    // ---- A: 128 rows x 256 cols fp32 -> bf16 hi/lo into smem ----
    {
        const float4* f4 = (const float4*)A.feat + (size_t)row0 * (HDIM / 4);
        const int pt = A.pretanh;
        for (int i = tid; i < 128 * 64; i += 256) {
            float4 t = f4[i];
            if (pt) { t.x = tanhf(t.x); t.y = tanhf(t.y); t.z = tanhf(t.z); t.w = tanhf(t.w); }
            int r = i >> 6, c = (i & 63) << 2;
            __nv_bfloat162 h0 = __floats2bfloat162_rn(t.x, t.y);
            __nv_bfloat162 h1 = __floats2bfloat162_rn(t.z, t.w);
            __nv_bfloat162 l0 = __floats2bfloat162_rn(t.x - __bfloat162float(__low2bfloat16(h0)),
                                                      t.y - __bfloat162float(__high2bfloat16(h0)));
            __nv_bfloat162 l1 = __floats2bfloat162_rn(t.z - __bfloat162float(__low2bfloat16(h1)),
                                                      t.w - __bfloat162float(__high2bfloat16(h1)));
            uint2 hu, lu;
            hu.x = *(uint32_t*)&h0; hu.y = *(uint32_t*)&h1;
            lu.x = *(uint32_t*)&l0; lu.y = *(uint32_t*)&l1;
            *(uint2*)(smem + SA_HI + (size_t)(r * A_ST + c) * 2) = hu;
            *(uint2*)(smem + SA_LO + (size_t)(r * A_ST + c) * 2) = lu;
        }
    }
    __syncthreads();

    const uint32_t aHiBase = sbase + SA_HI;
    const uint32_t aLoBase = sbase + SA_LO;
    const uint32_t aLaneOff = (uint32_t)(((wm * 32 + (lane & 15)) * A_ST + ((lane >> 4) << 3)) * 2);
    const uint32_t bLane = (uint32_t)(((lane & 7) + ((lane >> 4) << 3)) * WB_ST_B + (((lane >> 3) & 1) << 4));

    for (int half = 0; half < 2; half++) {
        float acc[2][8][4];
#pragma unroll
        for (int mi = 0; mi < 2; mi++)
#pragma unroll
            for (int nj = 0; nj < 8; nj++) {
                acc[mi][nj][0] = 0.f; acc[mi][nj][1] = 0.f;
                acc[mi][nj][2] = 0.f; acc[mi][nj][3] = 0.f;
            }

        for (int kc = 0; kc < 4; kc++) {
            const int q = half * 4 + kc;
            const int buf = q & 1;
            if (q < 7) {
                // prefetch chunk q+1 into the other buffer
                const int nh = (q + 1) >> 2, nkc = (q + 1) & 3, nb2 = (q + 1) & 1;
                for (int i = tid; i < 2048; i += 256) {
                    int hl = i >> 10, r = (i >> 3) & 127, j = i & 7;
                    const __nv_bfloat16* src = WT + hl * 65536
                        + (size_t)(nh * 128 + r) * 256 + nkc * 64 + j * 8;
                    uint32_t dst = sbase + SW_OFF + nb2 * SW_BUF + hl * SW_TILE
                        + (uint32_t)(r * WB_ST_B + j * 16);
                    CP_ASYNC16(dst, src);
                }
                CP_COMMIT();
                CP_WAIT(1);
            } else {
                CP_WAIT(0);
            }
            __syncthreads();

            const uint32_t wbHi = sbase + SW_OFF + buf * SW_BUF + bLane;
            const uint32_t wbLo = wbHi + SW_TILE;

#pragma unroll
            for (int ks = 0; ks < 4; ks++) {
                const uint32_t kOffA = (uint32_t)(kc * 128 + ks * 32);
                uint32_t aH[2][4], aL[2][4];
#pragma unroll
                for (int mi = 0; mi < 2; mi++) {
                    uint32_t ad = aLaneOff + (uint32_t)(mi * 16 * A_ST * 2) + kOffA;
                    LDSM_X4(aH[mi][0], aH[mi][1], aH[mi][2], aH[mi][3], aHiBase + ad);
                    LDSM_X4(aL[mi][0], aL[mi][1], aL[mi][2], aL[mi][3], aLoBase + ad);
                }
                uint32_t bH[8][2], bL[8][2];
#pragma unroll
                for (int nb = 0; nb < 4; nb++) {
                    uint32_t bd = (uint32_t)((wn * 64 + nb * 16) * WB_ST_B + ks * 32);
                    uint32_t r0, r1, r2, r3;
                    LDSM_X4(r0, r1, r2, r3, wbHi + bd);
                    bH[2*nb][0] = r0; bH[2*nb][1] = r1;
                    bH[2*nb+1][0] = r2; bH[2*nb+1][1] = r3;
                    LDSM_X4(r0, r1, r2, r3, wbLo + bd);
                    bL[2*nb][0] = r0; bL[2*nb][1] = r1;
                    bL[2*nb+1][0] = r2; bL[2*nb+1][1] = r3;
                }
#pragma unroll
                for (int mi = 0; mi < 2; mi++)
#pragma unroll
                    for (int nj = 0; nj < 8; nj++) {
                        MMA_BF16(acc[mi][nj], aH[mi], bH[nj]);
                        MMA_BF16(acc[mi][nj], aL[mi], bH[nj]);
                        MMA_BF16(acc[mi][nj], aH[mi], bL[nj]);
                    }
            }
            __syncthreads();   // all warps done with buf before it is overwritten
        }

        // epilogue for this half: tanh(acc+b)*v, reduce over owned cols
#pragma unroll
        for (int mi = 0; mi < 2; mi++) {
            float p0 = 0.f, p1 = 0.f;
#pragma unroll
            for (int nj = 0; nj < 8; nj++) {
                int col = half * 128 + wn * 64 + nj * 8 + tq * 2;
                float b0 = sBias[col], b1 = sBias[col + 1];
                float v0 = sV[col],    v1 = sV[col + 1];
                p0 += tanhf(acc[mi][nj][0] + b0) * v0 + tanhf(acc[mi][nj][1] + b1) * v1;
                p1 += tanhf(acc[mi][nj][2] + b0) * v0 + tanhf(acc[mi][nj][3] + b1) * v1;
            }
            p0 += __shfl_xor_sync(0xffffffffu, p0, 1);
            p0 += __shfl_xor_sync(0xffffffffu, p0, 2);
            p1 += __shfl_xor_sync(0xffffffffu, p1, 1);
            p1 += __shfl_xor_sync(0xffffffffu, p1, 2);
            if (tq == 0) {
                int r0 = wm * 32 + mi * 16 + gp;
                sPart[r0 * 2 + wn]       += p0;
                sPart[(r0 + 8) * 2 + wn] += p1;
            }
        }
    }
    __syncthreads();
    if (tid < 128)
        A.sout[row0 + tid] = sPart[tid * 2] + sPart[tid * 2 + 1] + A.c[0];
}

// ---------------- softmax + weighted pool + post-tanh (512 threads) ----------------
struct PoolArgs {
    const float* feat;
    const int* mask;
    const float* scores;
    float* out;
    int S;
    int pretanh;
    int posttanh;
};

__global__ __launch_bounds__(512) void pool_kernel(PoolArgs A0, PoolArgs A1,
                                                   PoolArgs A2, PoolArgs A3) {
    int pool = blockIdx.x & 3;
    int b    = blockIdx.x >> 2;
    PoolArgs A = (pool == 0) ? A0 : (pool == 1) ? A1 : (pool == 2) ? A2 : A3;

    __shared__ float w[S_TOK];
    __shared__ float red[512];

    const int tid = threadIdx.x;
    const int S = A.S;
    const float* sc = A.scores + (size_t)b * S;
    const int* mk = A.mask + (size_t)b * S;

    float m = -3.4e38f;
    for (int s = tid; s < S; s += 512) {
        float x = mk[s] ? sc[s] : NEGV;
        w[s] = x;
        m = fmaxf(m, x);
    }
    red[tid] = m;
    __syncthreads();
    for (int st = 256; st > 0; st >>= 1) {
        if (tid < st) red[tid] = fmaxf(red[tid], red[tid + st]);
        __syncthreads();
    }
    m = red[0];
    __syncthreads();

    float e = 0.f;
    for (int s = tid; s < S; s += 512) {
        float ex = __expf(w[s] - m);
        w[s] = ex;
        e += ex;
    }
    red[tid] = e;
    __syncthreads();
    for (int st = 256; st > 0; st >>= 1) {
        if (tid < st) red[tid] += red[tid + st];
        __syncthreads();
    }
    float inv = 1.f / red[0];
    __syncthreads();

    const int col = tid & 255;
    const int so  = tid >> 8;
    const float* f = A.feat + (size_t)b * S * HDIM + col;
    float acc = 0.f;
    if (A.pretanh) {
        for (int s = so; s < S; s += 2)
            acc += w[s] * tanhf(f[(size_t)s * HDIM]);
    } else {
#pragma unroll 4
        for (int s = so; s < S; s += 2)
            acc += w[s] * f[(size_t)s * HDIM];
    }
    red[tid] = acc;
    __syncthreads();
    if (tid < 256) {
        float r = (red[tid] + red[tid + 256]) * inv;
        r = tanhf(r);
        if (A.posttanh == 2) r = tanhf(r);
        A.out[b * HDIM + tid] = r;
    }
}

// ---------------- code = tanh([tok, gr] @ Wf + bf) ----------------
__global__ __launch_bounds__(256) void code_kernel(const float* Wf, const float* bfv) {
    int b = blockIdx.x, k = threadIdx.x;
    __shared__ float cat[2 * HDIM];
    cat[k]        = g_pool[0][b * HDIM + k];
    cat[HDIM + k] = g_pool[1][b * HDIM + k];
    __syncthreads();
    float acc = bfv[k];
#pragma unroll 8
    for (int j = 0; j < 2 * HDIM; j++) acc += cat[j] * Wf[j * HDIM + k];
    g_code[b * HDIM + k] = tanhf(acc);
}

// ---------------- per-batch hinge ----------------
__global__ __launch_bounds__(256) void loss1_kernel() {
    const int b = blockIdx.x;
    const int tid = threadIdx.x;
    const int warp = tid >> 5, lane = tid & 31;
    __shared__ float sm[8][5];

    float c = g_code[b * HDIM + tid];
    float a = g_pool[2][b * HDIM + tid];
    float n = g_pool[3][b * HDIM + tid];
    float s0 = c * c, s1 = a * a, s2 = n * n, s3 = c * a, s4 = c * n;
#pragma unroll
    for (int o = 16; o > 0; o >>= 1) {
        s0 += __shfl_xor_sync(0xffffffffu, s0, o);
        s1 += __shfl_xor_sync(0xffffffffu, s1, o);
        s2 += __shfl_xor_sync(0xffffffffu, s2, o);
        s3 += __shfl_xor_sync(0xffffffffu, s3, o);
        s4 += __shfl_xor_sync(0xffffffffu, s4, o);
    }
    if (lane == 0) {
        sm[warp][0] = s0; sm[warp][1] = s1; sm[warp][2] = s2;
        sm[warp][3] = s3; sm[warp][4] = s4;
    }
    __syncthreads();
    if (tid == 0) {
        float t0 = 0, t1 = 0, t2 = 0, t3 = 0, t4 = 0;
#pragma unroll
        for (int wv = 0; wv < 8; wv++) {
            t0 += sm[wv][0]; t1 += sm[wv][1]; t2 += sm[wv][2];
            t3 += sm[wv][3]; t4 += sm[wv][4];
        }
        float nc = sqrtf(t0);
        float sa = t3 / fmaxf(nc * sqrtf(t1), 1e-8f);
        float sn = t4 / fmaxf(nc * sqrtf(t2), 1e-8f);
        g_hinge[b] = fmaxf(0.6f - sa + sn, 0.f);
    }
}

__global__ void loss2_kernel(float* out) {
    int t = threadIdx.x;
    float v = g_hinge[t] + g_hinge[t + 32];
#pragma unroll
    for (int o = 16; o > 0; o >>= 1) v += __shfl_xor_sync(0xffffffffu, v, o);
    if (t == 0) out[0] = v / (float)BATCH;
}

// ---------------- launch ----------------
extern "C" void kernel_launch(void* const* d_in, const int* in_sizes, int n_in,
                              void* d_out, int out_size) {
    const float* token_feat = (const float*)d_in[0];
    const int*   token_mask = (const int*)d_in[1];
    const float* graph_feat = (const float*)d_in[2];
    const int*   graph_mask = (const int*)d_in[3];
    const float* da_feat    = (const float*)d_in[4];
    const int*   da_mask    = (const int*)d_in[5];
    const float* dn_feat    = (const float*)d_in[6];
    const int*   dn_mask    = (const int*)d_in[7];
    const float* Wt = (const float*)d_in[8];
    const float* bt = (const float*)d_in[9];
    const float* vt = (const float*)d_in[10];
    const float* ct = (const float*)d_in[11];
    const float* Wg = (const float*)d_in[12];
    const float* bg = (const float*)d_in[13];
    const float* vg = (const float*)d_in[14];
    const float* cg = (const float*)d_in[15];
    const float* Wd = (const float*)d_in[16];
    const float* bd = (const float*)d_in[17];
    const float* vd = (const float*)d_in[18];
    const float* cd = (const float*)d_in[19];
    const float* Wf = (const float*)d_in[20];
    const float* bf = (const float*)d_in[21];

    cudaFuncSetAttribute(score_tc, cudaFuncAttributeMaxDynamicSharedMemorySize, SCORE_SMEM);

    float* scores = nullptr;
    float* poolp  = nullptr;
    __nv_bfloat16* wtp = nullptr;
    cudaGetSymbolAddress((void**)&scores, g_scores);
    cudaGetSymbolAddress((void**)&poolp, g_pool);
    cudaGetSymbolAddress((void**)&wtp, g_WT);

    float* s_tok = scores;
    float* s_gr  = scores + BATCH * S_TOK;
    float* s_da  = s_gr + BATCH * S_OTH;
    float* s_dn  = s_da + BATCH * S_OTH;

    wconv_kernel<<<dim3(256, 3), 256>>>(Wt, Wg, Wd);

    const int nTok = BATCH * S_TOK / 128;   // 1024
    const int nOth = BATCH * S_OTH / 128;   // 256

    ScoreArgs sa0 = {token_feat, bt, vt, ct, s_tok, 0, 0,               0};
    ScoreArgs sa1 = {graph_feat, bg, vg, cg, s_gr,  1, nTok,            131072};
    ScoreArgs sa2 = {da_feat,    bd, vd, cd, s_da,  0, nTok + nOth,     262144};
    ScoreArgs sa3 = {dn_feat,    bd, vd, cd, s_dn,  0, nTok + 2 * nOth, 262144};
    score_tc<<<nTok + 3 * nOth, 256, SCORE_SMEM>>>(sa0, sa1, sa2, sa3, wtp);

    PoolArgs pa0 = {token_feat, token_mask, s_tok, poolp + 0 * BATCH * HDIM, S_TOK, 0, 1};
    PoolArgs pa1 = {graph_feat, graph_mask, s_gr,  poolp + 1 * BATCH * HDIM, S_OTH, 1, 1};
    PoolArgs pa2 = {da_feat,    da_mask,    s_da,  poolp + 2 * BATCH * HDIM, S_OTH, 0, 2};
    PoolArgs pa3 = {dn_feat,    dn_mask,    s_dn,  poolp + 3 * BATCH * HDIM, S_OTH, 0, 2};
    pool_kernel<<<4 * BATCH, 512>>>(pa0, pa1, pa2, pa3);

    code_kernel<<<BATCH, 256>>>(Wf, bf);
    loss1_kernel<<<BATCH, 256>>>();
    loss2_kernel<<<1, 32>>>((float*)d_out);
}

// round 6
// speedup vs baseline: 2.5141x; 1.3423x over previous
#include <cuda_runtime.h>
#include <cuda_fp16.h>
#include <stdint.h>
#include <math.h>

#define HDIM 256
#define BATCH 64
#define S_TOK 2048
#define S_OTH 512
#define NEGV (-1e9f)

// ---------------- scratch (no allocations allowed) ----------------
__device__ float g_scores[BATCH*S_TOK + 3*BATCH*S_OTH];
__device__ float g_pool[4][BATCH*HDIM];
__device__ float g_code[BATCH*HDIM];
__device__ float g_hinge[BATCH];
// W transposed, fp16: [mat 0..2][n*256+k]
__device__ __half g_WT[3 * 65536];

// ---------------- PTX helpers ----------------
__device__ __forceinline__ uint32_t smem_to_u32(const void* p) {
    uint32_t a;
    asm("{ .reg .u64 tmp; cvta.to.shared.u64 tmp, %1; cvt.u32.u64 %0, tmp; }" : "=r"(a) : "l"(p));
    return a;
}
#define LDSM_X4(r0,r1,r2,r3,addr) \
    asm volatile("ldmatrix.sync.aligned.m8n8.x4.shared.b16 {%0,%1,%2,%3}, [%4];" \
        : "=r"(r0),"=r"(r1),"=r"(r2),"=r"(r3) : "r"(addr))
#define MMA_F16(c, a, b) \
    asm volatile("mma.sync.aligned.m16n8k16.row.col.f32.f16.f16.f32 " \
        "{%0,%1,%2,%3},{%4,%5,%6,%7},{%8,%9},{%0,%1,%2,%3};" \
        : "+f"((c)[0]),"+f"((c)[1]),"+f"((c)[2]),"+f"((c)[3]) \
        : "r"((a)[0]),"r"((a)[1]),"r"((a)[2]),"r"((a)[3]),"r"((b)[0]),"r"((b)[1]))
#define CP_ASYNC16(dst, src) \
    asm volatile("cp.async.cg.shared.global [%0], [%1], 16;" :: "r"(dst), "l"(src) : "memory")
#define CP_COMMIT() asm volatile("cp.async.commit_group;" ::: "memory")
#define CP_WAIT(n)  asm volatile("cp.async.wait_group %0;" :: "n"(n) : "memory")

// ---------------- W transpose to fp16 ----------------
__global__ void wconv_kernel(const float* Wt, const float* Wg, const float* Wd) {
    int mat = blockIdx.y;
    const float* W = (mat == 0) ? Wt : (mat == 1) ? Wg : Wd;
    int k = blockIdx.x, n = threadIdx.x;
    g_WT[mat * 65536 + n * 256 + k] = __float2half_rn(W[k * 256 + n]);
}

// ---------------- score kernel: mma.sync fp16, 2-term A-split ----------------
#define A_ST 264                 // fp16 elems per A smem row (528B)
#define WB_ST 272                // bytes per W smem row (256 data + 16 pad)
#define SA_HI 0
#define SA_LO 67584              // 128*264*2
#define SW_OFF 135168            // 2 buffers of 34816 (128 rows x 272B)
#define SW_BUF 34816
#define SBIAS 204800
#define SVV   205824
#define SPART 206848             // 128*2 floats
#define SCORE_SMEM 207872

struct ScoreArgs {
    const float* feat;
    const float* bv;
    const float* v;
    const float* c;
    float* sout;
    int pretanh;
    int blkStart;
    int wtOff;   // element offset into g_WT
};

__global__ __launch_bounds__(256, 1) void score_tc(ScoreArgs A0, ScoreArgs A1,
                                                   ScoreArgs A2, ScoreArgs A3,
                                                   const __half* WTg) {
    ScoreArgs A;
    int blk = blockIdx.x;
    if (blk >= A3.blkStart)      A = A3;
    else if (blk >= A2.blkStart) A = A2;
    else if (blk >= A1.blkStart) A = A1;
    else                         A = A0;
    const int row0 = (blk - A.blkStart) * 128;

    extern __shared__ char smem[];
    const uint32_t sbase = smem_to_u32(smem);
    float* sBias = (float*)(smem + SBIAS);
    float* sV    = (float*)(smem + SVV);
    float* sPart = (float*)(smem + SPART);

    const int tid  = threadIdx.x;
    const int warp = tid >> 5;
    const int lane = tid & 31;
    const int wm = warp & 3;        // 4 m-warps (32 rows each)
    const int wn = warp >> 2;       // 2 n-warps (64 cols each within a 128-col half)
    const int tq = lane & 3;
    const int gp = lane >> 2;

    const __half* WT = WTg + A.wtOff;

    // prefetch W chunk q=0 (half 0, k-half 0): 128 n-rows x 128 k (256B)
    for (int i = tid; i < 2048; i += 256) {
        int r = i >> 4, j = i & 15;
        const __half* src = WT + (size_t)r * 256 + j * 8;
        uint32_t dst = sbase + SW_OFF + (uint32_t)(r * WB_ST + j * 16);
        CP_ASYNC16(dst, src);
    }
    CP_COMMIT();

    sBias[tid] = A.bv[tid];
    sV[tid]    = A.v[tid];
    if (tid < 128) { sPart[tid * 2] = 0.f; sPart[tid * 2 + 1] = 0.f; }

    // ---- A: 128 rows x 256 cols fp32 -> fp16 hi/lo into smem ----
    {
        const float4* f4 = (const float4*)A.feat + (size_t)row0 * (HDIM / 4);
        const int pt = A.pretanh;
        for (int i = tid; i < 128 * 64; i += 256) {
            float4 t = f4[i];
            if (pt) { t.x = tanhf(t.x); t.y = tanhf(t.y); t.z = tanhf(t.z); t.w = tanhf(t.w); }
            int r = i >> 6, c = (i & 63) << 2;
            __half2 h0 = __float22half2_rn(make_float2(t.x, t.y));
            __half2 h1 = __float22half2_rn(make_float2(t.z, t.w));
            __half2 l0 = __float22half2_rn(make_float2(t.x - __half2float(__low2half(h0)),
                                                       t.y - __half2float(__high2half(h0))));
            __half2 l1 = __float22half2_rn(make_float2(t.z - __half2float(__low2half(h1)),
                                                       t.w - __half2float(__high2half(h1))));
            uint2 hu, lu;
            hu.x = *(uint32_t*)&h0; hu.y = *(uint32_t*)&h1;
            lu.x = *(uint32_t*)&l0; lu.y = *(uint32_t*)&l1;
            *(uint2*)(smem + SA_HI + (size_t)(r * A_ST + c) * 2) = hu;
            *(uint2*)(smem + SA_LO + (size_t)(r * A_ST + c) * 2) = lu;
        }
    }
    __syncthreads();

    const uint32_t aHiBase = sbase + SA_HI;
    const uint32_t aLoBase = sbase + SA_LO;
    const uint32_t aLaneOff = (uint32_t)(((wm * 32 + (lane & 15)) * A_ST + ((lane >> 4) << 3)) * 2);
    const uint32_t bLane = (uint32_t)(((lane & 7) + ((lane >> 4) << 3)) * WB_ST + (((lane >> 3) & 1) << 4));

    for (int half = 0; half < 2; half++) {
        float acc[2][8][4];
#pragma unroll
        for (int mi = 0; mi < 2; mi++)
#pragma unroll
            for (int nj = 0; nj < 8; nj++) {
                acc[mi][nj][0] = 0.f; acc[mi][nj][1] = 0.f;
                acc[mi][nj][2] = 0.f; acc[mi][nj][3] = 0.f;
            }

        for (int kh = 0; kh < 2; kh++) {
            const int q = half * 2 + kh;
            const int buf = q & 1;
            if (q < 3) {
                // prefetch chunk q+1 into the other buffer
                const int nh = (q + 1) >> 1, nkh = (q + 1) & 1, nb2 = (q + 1) & 1;
                for (int i = tid; i < 2048; i += 256) {
                    int r = i >> 4, j = i & 15;
                    const __half* src = WT + (size_t)(nh * 128 + r) * 256 + nkh * 128 + j * 8;
                    uint32_t dst = sbase + SW_OFF + nb2 * SW_BUF + (uint32_t)(r * WB_ST + j * 16);
                    CP_ASYNC16(dst, src);
                }
                CP_COMMIT();
                CP_WAIT(1);
            } else {
                CP_WAIT(0);
            }
            __syncthreads();

            const uint32_t wbBase = sbase + SW_OFF + buf * SW_BUF + bLane;

#pragma unroll
            for (int ks = 0; ks < 8; ks++) {
                const uint32_t kOffA = (uint32_t)(kh * 256 + ks * 32);
                uint32_t aH[2][4], aL[2][4];
#pragma unroll
                for (int mi = 0; mi < 2; mi++) {
                    uint32_t ad = aLaneOff + (uint32_t)(mi * 16 * A_ST * 2) + kOffA;
                    LDSM_X4(aH[mi][0], aH[mi][1], aH[mi][2], aH[mi][3], aHiBase + ad);
                    LDSM_X4(aL[mi][0], aL[mi][1], aL[mi][2], aL[mi][3], aLoBase + ad);
                }
                uint32_t bF[8][2];
#pragma unroll
                for (int nb = 0; nb < 4; nb++) {
                    uint32_t bd = (uint32_t)((wn * 64 + nb * 16) * WB_ST + ks * 32);
                    uint32_t r0, r1, r2, r3;
                    LDSM_X4(r0, r1, r2, r3, wbBase + bd);
                    bF[2*nb][0] = r0; bF[2*nb][1] = r1;
                    bF[2*nb+1][0] = r2; bF[2*nb+1][1] = r3;
                }
#pragma unroll
                for (int mi = 0; mi < 2; mi++)
#pragma unroll
                    for (int nj = 0; nj < 8; nj++) {
                        MMA_F16(acc[mi][nj], aH[mi], bF[nj]);
                        MMA_F16(acc[mi][nj], aL[mi], bF[nj]);
                    }
            }
            __syncthreads();   // all warps done with buf before it is overwritten
        }

        // epilogue for this half: tanh(acc+b)*v, reduce over owned cols
#pragma unroll
        for (int mi = 0; mi < 2; mi++) {
            float p0 = 0.f, p1 = 0.f;
#pragma unroll
            for (int nj = 0; nj < 8; nj++) {
                int col = half * 128 + wn * 64 + nj * 8 + tq * 2;
                float b0 = sBias[col], b1 = sBias[col + 1];
                float v0 = sV[col],    v1 = sV[col + 1];
                p0 += tanhf(acc[mi][nj][0] + b0) * v0 + tanhf(acc[mi][nj][1] + b1) * v1;
                p1 += tanhf(acc[mi][nj][2] + b0) * v0 + tanhf(acc[mi][nj][3] + b1) * v1;
            }
            p0 += __shfl_xor_sync(0xffffffffu, p0, 1);
            p0 += __shfl_xor_sync(0xffffffffu, p0, 2);
            p1 += __shfl_xor_sync(0xffffffffu, p1, 1);
            p1 += __shfl_xor_sync(0xffffffffu, p1, 2);
            if (tq == 0) {
                int r0 = wm * 32 + mi * 16 + gp;
                sPart[r0 * 2 + wn]       += p0;
                sPart[(r0 + 8) * 2 + wn] += p1;
            }
        }
    }
    __syncthreads();
    if (tid < 128)
        A.sout[row0 + tid] = sPart[tid * 2] + sPart[tid * 2 + 1] + A.c[0];
}

// ---------------- softmax + weighted pool + post-tanh (512 threads) ----------------
struct PoolArgs {
    const float* feat;
    const int* mask;
    const float* scores;
    float* out;
    int S;
    int pretanh;
    int posttanh;
};

__global__ __launch_bounds__(512) void pool_kernel(PoolArgs A0, PoolArgs A1,
                                                   PoolArgs A2, PoolArgs A3) {
    int pool = blockIdx.x & 3;
    int b    = blockIdx.x >> 2;
    PoolArgs A = (pool == 0) ? A0 : (pool == 1) ? A1 : (pool == 2) ? A2 : A3;

    __shared__ float w[S_TOK];
    __shared__ float red0[512];
    __shared__ float red1[512];

    const int tid = threadIdx.x;
    const int S = A.S;
    const float* sc = A.scores + (size_t)b * S;
    const int* mk = A.mask + (size_t)b * S;

    float m = -3.4e38f;
    for (int s = tid; s < S; s += 512) {
        float x = mk[s] ? sc[s] : NEGV;
        w[s] = x;
        m = fmaxf(m, x);
    }
    red0[tid] = m;
    __syncthreads();
    for (int st = 256; st > 0; st >>= 1) {
        if (tid < st) red0[tid] = fmaxf(red0[tid], red0[tid + st]);
        __syncthreads();
    }
    m = red0[0];
    __syncthreads();

    float e = 0.f;
    for (int s = tid; s < S; s += 512) {
        float ex = __expf(w[s] - m);
        w[s] = ex;
        e += ex;
    }
    red0[tid] = e;
    __syncthreads();
    for (int st = 256; st > 0; st >>= 1) {
        if (tid < st) red0[tid] += red0[tid + st];
        __syncthreads();
    }
    float inv = 1.f / red0[0];
    __syncthreads();

    // pass 3: 4 s-stripes x 128 cols, 2 cols per thread (col, col+128)
    const int col = tid & 127;
    const int stripe = tid >> 7;
    const float* f = A.feat + (size_t)b * S * HDIM + col;
    float acc0 = 0.f, acc1 = 0.f;
    if (A.pretanh) {
        for (int s = stripe; s < S; s += 4) {
            float ws = w[s];
            acc0 += ws * tanhf(f[(size_t)s * HDIM]);
            acc1 += ws * tanhf(f[(size_t)s * HDIM + 128]);
        }
    } else {
#pragma unroll 4
        for (int s = stripe; s < S; s += 4) {
            float ws = w[s];
            acc0 += ws * f[(size_t)s * HDIM];
            acc1 += ws * f[(size_t)s * HDIM + 128];
        }
    }
    red0[tid] = acc0;
    red1[tid] = acc1;
    __syncthreads();
    if (tid < 128) {
        float r0 = (red0[tid] + red0[tid + 128] + red0[tid + 256] + red0[tid + 384]) * inv;
        float r1 = (red1[tid] + red1[tid + 128] + red1[tid + 256] + red1[tid + 384]) * inv;
        r0 = tanhf(r0); r1 = tanhf(r1);
        if (A.posttanh == 2) { r0 = tanhf(r0); r1 = tanhf(r1); }
        A.out[b * HDIM + tid]       = r0;
        A.out[b * HDIM + tid + 128] = r1;
    }
}

// ---------------- code = tanh([tok, gr] @ Wf + bf), warp-parallel over j ----------------
__global__ __launch_bounds__(256) void code_kernel(const float* Wf, const float* bfv) {
    int b = blockIdx.x;
    int tid = threadIdx.x, wp = tid >> 5, lane = tid & 31;
    __shared__ float cat[2 * HDIM];
    __shared__ float part[8][256];
    cat[tid]        = g_pool[0][b * HDIM + tid];
    cat[HDIM + tid] = g_pool[1][b * HDIM + tid];
    __syncthreads();

    float acc[8] = {0.f, 0.f, 0.f, 0.f, 0.f, 0.f, 0.f, 0.f};
    const float* wbase = Wf + (size_t)(wp * 64) * HDIM + lane * 8;
#pragma unroll 4
    for (int jj = 0; jj < 64; jj++) {
        float cj = cat[wp * 64 + jj];
        float4 a4 = *(const float4*)(wbase + (size_t)jj * HDIM);
        float4 b4 = *(const float4*)(wbase + (size_t)jj * HDIM + 4);
        acc[0] += cj * a4.x; acc[1] += cj * a4.y; acc[2] += cj * a4.z; acc[3] += cj * a4.w;
        acc[4] += cj * b4.x; acc[5] += cj * b4.y; acc[6] += cj * b4.z; acc[7] += cj * b4.w;
    }
#pragma unroll
    for (int q = 0; q < 8; q++) part[wp][lane * 8 + q] = acc[q];
    __syncthreads();

    float s = bfv[tid];
#pragma unroll
    for (int w2 = 0; w2 < 8; w2++) s += part[w2][tid];
    g_code[b * HDIM + tid] = tanhf(s);
}

// ---------------- per-batch hinge ----------------
__global__ __launch_bounds__(256) void loss1_kernel() {
    const int b = blockIdx.x;
    const int tid = threadIdx.x;
    const int warp = tid >> 5, lane = tid & 31;
    __shared__ float sm[8][5];

    float c = g_code[b * HDIM + tid];
    float a = g_pool[2][b * HDIM + tid];
    float n = g_pool[3][b * HDIM + tid];
    float s0 = c * c, s1 = a * a, s2 = n * n, s3 = c * a, s4 = c * n;
#pragma unroll
    for (int o = 16; o > 0; o >>= 1) {
        s0 += __shfl_xor_sync(0xffffffffu, s0, o);
        s1 += __shfl_xor_sync(0xffffffffu, s1, o);
        s2 += __shfl_xor_sync(0xffffffffu, s2, o);
        s3 += __shfl_xor_sync(0xffffffffu, s3, o);
        s4 += __shfl_xor_sync(0xffffffffu, s4, o);
    }
    if (lane == 0) {
        sm[warp][0] = s0; sm[warp][1] = s1; sm[warp][2] = s2;
        sm[warp][3] = s3; sm[warp][4] = s4;
    }
    __syncthreads();
    if (tid == 0) {
        float t0 = 0, t1 = 0, t2 = 0, t3 = 0, t4 = 0;
#pragma unroll
        for (int wv = 0; wv < 8; wv++) {
            t0 += sm[wv][0]; t1 += sm[wv][1]; t2 += sm[wv][2];
            t3 += sm[wv][3]; t4 += sm[wv][4];
        }
        float nc = sqrtf(t0);
        float sa = t3 / fmaxf(nc * sqrtf(t1), 1e-8f);
        float sn = t4 / fmaxf(nc * sqrtf(t2), 1e-8f);
        g_hinge[b] = fmaxf(0.6f - sa + sn, 0.f);
    }
}

__global__ void loss2_kernel(float* out) {
    int t = threadIdx.x;
    float v = g_hinge[t] + g_hinge[t + 32];
#pragma unroll
    for (int o = 16; o > 0; o >>= 1) v += __shfl_xor_sync(0xffffffffu, v, o);
    if (t == 0) out[0] = v / (float)BATCH;
}

// ---------------- launch ----------------
extern "C" void kernel_launch(void* const* d_in, const int* in_sizes, int n_in,
                              void* d_out, int out_size) {
    const float* token_feat = (const float*)d_in[0];
    const int*   token_mask = (const int*)d_in[1];
    const float* graph_feat = (const float*)d_in[2];
    const int*   graph_mask = (const int*)d_in[3];
    const float* da_feat    = (const float*)d_in[4];
    const int*   da_mask    = (const int*)d_in[5];
    const float* dn_feat    = (const float*)d_in[6];
    const int*   dn_mask    = (const int*)d_in[7];
    const float* Wt = (const float*)d_in[8];
    const float* bt = (const float*)d_in[9];
    const float* vt = (const float*)d_in[10];
    const float* ct = (const float*)d_in[11];
    const float* Wg = (const float*)d_in[12];
    const float* bg = (const float*)d_in[13];
    const float* vg = (const float*)d_in[14];
    const float* cg = (const float*)d_in[15];
    const float* Wd = (const float*)d_in[16];
    const float* bd = (const float*)d_in[17];
    const float* vd = (const float*)d_in[18];
    const float* cd = (const float*)d_in[19];
    const float* Wf = (const float*)d_in[20];
    const float* bf = (const float*)d_in[21];

    cudaFuncSetAttribute(score_tc, cudaFuncAttributeMaxDynamicSharedMemorySize, SCORE_SMEM);

    float* scores = nullptr;
    float* poolp  = nullptr;
    __half* wtp = nullptr;
    cudaGetSymbolAddress((void**)&scores, g_scores);
    cudaGetSymbolAddress((void**)&poolp, g_pool);
    cudaGetSymbolAddress((void**)&wtp, g_WT);

    float* s_tok = scores;
    float* s_gr  = scores + BATCH * S_TOK;
    float* s_da  = s_gr + BATCH * S_OTH;
    float* s_dn  = s_da + BATCH * S_OTH;

    wconv_kernel<<<dim3(256, 3), 256>>>(Wt, Wg, Wd);

    const int nTok = BATCH * S_TOK / 128;   // 1024
    const int nOth = BATCH * S_OTH / 128;   // 256

    ScoreArgs sa0 = {token_feat, bt, vt, ct, s_tok, 0, 0,               0};
    ScoreArgs sa1 = {graph_feat, bg, vg, cg, s_gr,  1, nTok,            65536};
    ScoreArgs sa2 = {da_feat,    bd, vd, cd, s_da,  0, nTok + nOth,     131072};
    ScoreArgs sa3 = {dn_feat,    bd, vd, cd, s_dn,  0, nTok + 2 * nOth, 131072};
    score_tc<<<nTok + 3 * nOth, 256, SCORE_SMEM>>>(sa0, sa1, sa2, sa3, wtp);

    PoolArgs pa0 = {token_feat, token_mask, s_tok, poolp + 0 * BATCH * HDIM, S_TOK, 0, 1};
    PoolArgs pa1 = {graph_feat, graph_mask, s_gr,  poolp + 1 * BATCH * HDIM, S_OTH, 1, 1};
    PoolArgs pa2 = {da_feat,    da_mask,    s_da,  poolp + 2 * BATCH * HDIM, S_OTH, 0, 2};
    PoolArgs pa3 = {dn_feat,    dn_mask,    s_dn,  poolp + 3 * BATCH * HDIM, S_OTH, 0, 2};
    pool_kernel<<<4 * BATCH, 512>>>(pa0, pa1, pa2, pa3);

    code_kernel<<<BATCH, 256>>>(Wf, bf);
    loss1_kernel<<<BATCH, 256>>>();
    loss2_kernel<<<1, 32>>>((float*)d_out);
}

// round 7
// speedup vs baseline: 3.3735x; 1.3418x over previous
#include <cuda_runtime.h>
#include <cuda_fp16.h>
#include <stdint.h>
#include <math.h>

#define HDIM 256
#define BATCH 64
#define S_TOK 2048
#define S_OTH 512
#define NEGV (-1e9f)

// ---------------- scratch (no allocations allowed) ----------------
__device__ float g_scores[BATCH*S_TOK + 3*BATCH*S_OTH];
__device__ float g_pool[4][BATCH*HDIM];
__device__ float g_hinge[BATCH];
// W transposed, fp16: [mat 0..2][n*256+k]
__device__ __half g_WT[3 * 65536];

// ---------------- PTX helpers ----------------
__device__ __forceinline__ uint32_t smem_to_u32(const void* p) {
    uint32_t a;
    asm("{ .reg .u64 tmp; cvta.to.shared.u64 tmp, %1; cvt.u32.u64 %0, tmp; }" : "=r"(a) : "l"(p));
    return a;
}
#define LDSM_X4(r0,r1,r2,r3,addr) \
    asm volatile("ldmatrix.sync.aligned.m8n8.x4.shared.b16 {%0,%1,%2,%3}, [%4];" \
        : "=r"(r0),"=r"(r1),"=r"(r2),"=r"(r3) : "r"(addr))
#define MMA_F16(c, a, b) \
    asm volatile("mma.sync.aligned.m16n8k16.row.col.f32.f16.f16.f32 " \
        "{%0,%1,%2,%3},{%4,%5,%6,%7},{%8,%9},{%0,%1,%2,%3};" \
        : "+f"((c)[0]),"+f"((c)[1]),"+f"((c)[2]),"+f"((c)[3]) \
        : "r"((a)[0]),"r"((a)[1]),"r"((a)[2]),"r"((a)[3]),"r"((b)[0]),"r"((b)[1]))
#define CP_ASYNC16(dst, src) \
    asm volatile("cp.async.cg.shared.global [%0], [%1], 16;" :: "r"(dst), "l"(src) : "memory")
#define CP_COMMIT() asm volatile("cp.async.commit_group;" ::: "memory")
#define CP_WAIT(n)  asm volatile("cp.async.wait_group %0;" :: "n"(n) : "memory")

// ---------------- W transpose to fp16 ----------------
__global__ void wconv_kernel(const float* Wt, const float* Wg, const float* Wd) {
    int mat = blockIdx.y;
    const float* W = (mat == 0) ? Wt : (mat == 1) ? Wg : Wd;
    int k = blockIdx.x, n = threadIdx.x;
    g_WT[mat * 65536 + n * 256 + k] = __float2half_rn(W[k * 256 + n]);
}

// ---------------- score kernel: mma.sync fp16, single-term ----------------
#define A_ST 264                 // fp16 elems per A smem row (528B)
#define WB_ST 528                // bytes per W smem row (512 data + 16 pad)
#define SA_OFF 0                 // 128*264*2 = 67584
#define SW_OFF 67584             // 2 chunks of 67584 (128 rows x 528B)
#define SW_CHN 67584
#define SBIAS 202752
#define SVV   203776
#define SPART 204800             // 128*2 floats
#define SCORE_SMEM 205824

struct ScoreArgs {
    const float* feat;
    const float* bv;
    const float* v;
    const float* c;
    float* sout;
    int pretanh;
    int blkStart;
    int wtOff;   // element offset into g_WT
};

__global__ __launch_bounds__(256, 1) void score_tc(ScoreArgs A0, ScoreArgs A1,
                                                   ScoreArgs A2, ScoreArgs A3,
                                                   const __half* WTg) {
    ScoreArgs A;
    int blk = blockIdx.x;
    if (blk >= A3.blkStart)      A = A3;
    else if (blk >= A2.blkStart) A = A2;
    else if (blk >= A1.blkStart) A = A1;
    else                         A = A0;
    const int row0 = (blk - A.blkStart) * 128;

    extern __shared__ char smem[];
    const uint32_t sbase = smem_to_u32(smem);
    float* sBias = (float*)(smem + SBIAS);
    float* sV    = (float*)(smem + SVV);
    float* sPart = (float*)(smem + SPART);

    const int tid  = threadIdx.x;
    const int warp = tid >> 5;
    const int lane = tid & 31;
    const int wm = warp & 3;        // 4 m-warps (32 rows each)
    const int wn = warp >> 2;       // 2 n-warps (64 cols each within a 128-col half)
    const int tq = lane & 3;
    const int gp = lane >> 2;

    const __half* WT = WTg + A.wtOff;

    // prefetch both W chunks (half 0 group, half 1 group): 128 n-rows x 256 k each
#pragma unroll
    for (int hf = 0; hf < 2; hf++) {
        for (int i = tid; i < 4096; i += 256) {
            int r = i >> 5, j = i & 31;
            const __half* src = WT + (size_t)(hf * 128 + r) * 256 + j * 8;
            uint32_t dst = sbase + SW_OFF + hf * SW_CHN + (uint32_t)(r * WB_ST + j * 16);
            CP_ASYNC16(dst, src);
        }
        CP_COMMIT();
    }

    sBias[tid] = A.bv[tid];
    sV[tid]    = A.v[tid];
    if (tid < 128) { sPart[tid * 2] = 0.f; sPart[tid * 2 + 1] = 0.f; }

    // ---- A: 128 rows x 256 cols fp32 -> fp16 into smem ----
    {
        const float4* f4 = (const float4*)A.feat + (size_t)row0 * (HDIM / 4);
        const int pt = A.pretanh;
        for (int i = tid; i < 128 * 64; i += 256) {
            float4 t = f4[i];
            if (pt) { t.x = tanhf(t.x); t.y = tanhf(t.y); t.z = tanhf(t.z); t.w = tanhf(t.w); }
            int r = i >> 6, c = (i & 63) << 2;
            __half2 h0 = __float22half2_rn(make_float2(t.x, t.y));
            __half2 h1 = __float22half2_rn(make_float2(t.z, t.w));
            uint2 hu;
            hu.x = *(uint32_t*)&h0; hu.y = *(uint32_t*)&h1;
            *(uint2*)(smem + SA_OFF + (size_t)(r * A_ST + c) * 2) = hu;
        }
    }
    __syncthreads();

    const uint32_t aBase = sbase + SA_OFF;
    const uint32_t aLaneOff = (uint32_t)(((wm * 32 + (lane & 15)) * A_ST + ((lane >> 4) << 3)) * 2);
    const uint32_t bLane = (uint32_t)(((lane & 7) + ((lane >> 4) << 3)) * WB_ST + (((lane >> 3) & 1) << 4));

    for (int half = 0; half < 2; half++) {
        float acc[2][8][4];
#pragma unroll
        for (int mi = 0; mi < 2; mi++)
#pragma unroll
            for (int nj = 0; nj < 8; nj++) {
                acc[mi][nj][0] = 0.f; acc[mi][nj][1] = 0.f;
                acc[mi][nj][2] = 0.f; acc[mi][nj][3] = 0.f;
            }

        if (half == 0) CP_WAIT(1); else CP_WAIT(0);
        __syncthreads();

        const uint32_t wbBase = sbase + SW_OFF + half * SW_CHN + bLane;

#pragma unroll
        for (int ks = 0; ks < 16; ks++) {
            const uint32_t kOffA = (uint32_t)(ks * 32);
            uint32_t aF[2][4];
#pragma unroll
            for (int mi = 0; mi < 2; mi++) {
                uint32_t ad = aLaneOff + (uint32_t)(mi * 16 * A_ST * 2) + kOffA;
                LDSM_X4(aF[mi][0], aF[mi][1], aF[mi][2], aF[mi][3], aBase + ad);
            }
            uint32_t bF[8][2];
#pragma unroll
            for (int nb = 0; nb < 4; nb++) {
                uint32_t bd = (uint32_t)((wn * 64 + nb * 16) * WB_ST + ks * 32);
                uint32_t r0, r1, r2, r3;
                LDSM_X4(r0, r1, r2, r3, wbBase + bd);
                bF[2*nb][0] = r0; bF[2*nb][1] = r1;
                bF[2*nb+1][0] = r2; bF[2*nb+1][1] = r3;
            }
#pragma unroll
            for (int mi = 0; mi < 2; mi++)
#pragma unroll
                for (int nj = 0; nj < 8; nj++)
                    MMA_F16(acc[mi][nj], aF[mi], bF[nj]);
        }

        // epilogue for this half: tanh(acc+b)*v, reduce over owned cols
#pragma unroll
        for (int mi = 0; mi < 2; mi++) {
            float p0 = 0.f, p1 = 0.f;
#pragma unroll
            for (int nj = 0; nj < 8; nj++) {
                int col = half * 128 + wn * 64 + nj * 8 + tq * 2;
                float b0 = sBias[col], b1 = sBias[col + 1];
                float v0 = sV[col],    v1 = sV[col + 1];
                p0 += tanhf(acc[mi][nj][0] + b0) * v0 + tanhf(acc[mi][nj][1] + b1) * v1;
                p1 += tanhf(acc[mi][nj][2] + b0) * v0 + tanhf(acc[mi][nj][3] + b1) * v1;
            }
            p0 += __shfl_xor_sync(0xffffffffu, p0, 1);
            p0 += __shfl_xor_sync(0xffffffffu, p0, 2);
            p1 += __shfl_xor_sync(0xffffffffu, p1, 1);
            p1 += __shfl_xor_sync(0xffffffffu, p1, 2);
            if (tq == 0) {
                int r0 = wm * 32 + mi * 16 + gp;
                sPart[r0 * 2 + wn]       += p0;
                sPart[(r0 + 8) * 2 + wn] += p1;
            }
        }
    }
    __syncthreads();
    if (tid < 128)
        A.sout[row0 + tid] = sPart[tid * 2] + sPart[tid * 2 + 1] + A.c[0];
}

// ---------------- softmax + weighted pool + post-tanh (512 threads) ----------------
struct PoolArgs {
    const float* feat;
    const int* mask;
    const float* scores;
    float* out;
    int S;
    int pretanh;
    int posttanh;
};

__global__ __launch_bounds__(512) void pool_kernel(PoolArgs A0, PoolArgs A1,
                                                   PoolArgs A2, PoolArgs A3) {
    int pool = blockIdx.x & 3;
    int b    = blockIdx.x >> 2;
    PoolArgs A = (pool == 0) ? A0 : (pool == 1) ? A1 : (pool == 2) ? A2 : A3;

    __shared__ float w[S_TOK];
    __shared__ float red0[512];
    __shared__ float red1[512];

    const int tid = threadIdx.x;
    const int S = A.S;
    const float* sc = A.scores + (size_t)b * S;
    const int* mk = A.mask + (size_t)b * S;

    float m = -3.4e38f;
    for (int s = tid; s < S; s += 512) {
        float x = mk[s] ? sc[s] : NEGV;
        w[s] = x;
        m = fmaxf(m, x);
    }
    red0[tid] = m;
    __syncthreads();
    for (int st = 256; st > 0; st >>= 1) {
        if (tid < st) red0[tid] = fmaxf(red0[tid], red0[tid + st]);
        __syncthreads();
    }
    m = red0[0];
    __syncthreads();

    float e = 0.f;
    for (int s = tid; s < S; s += 512) {
        float ex = __expf(w[s] - m);
        w[s] = ex;
        e += ex;
    }
    red0[tid] = e;
    __syncthreads();
    for (int st = 256; st > 0; st >>= 1) {
        if (tid < st) red0[tid] += red0[tid + st];
        __syncthreads();
    }
    float inv = 1.f / red0[0];
    __syncthreads();

    // pass 3: 4 s-stripes x 128 cols, 2 cols per thread (col, col+128)
    const int col = tid & 127;
    const int stripe = tid >> 7;
    const float* f = A.feat + (size_t)b * S * HDIM + col;
    float acc0 = 0.f, acc1 = 0.f;
    if (A.pretanh) {
        for (int s = stripe; s < S; s += 4) {
            float ws = w[s];
            acc0 += ws * tanhf(f[(size_t)s * HDIM]);
            acc1 += ws * tanhf(f[(size_t)s * HDIM + 128]);
        }
    } else {
#pragma unroll 4
        for (int s = stripe; s < S; s += 4) {
            float ws = w[s];
            acc0 += ws * f[(size_t)s * HDIM];
            acc1 += ws * f[(size_t)s * HDIM + 128];
        }
    }
    red0[tid] = acc0;
    red1[tid] = acc1;
    __syncthreads();
    if (tid < 128) {
        float r0 = (red0[tid] + red0[tid + 128] + red0[tid + 256] + red0[tid + 384]) * inv;
        float r1 = (red1[tid] + red1[tid + 128] + red1[tid + 256] + red1[tid + 384]) * inv;
        r0 = tanhf(r0); r1 = tanhf(r1);
        if (A.posttanh == 2) { r0 = tanhf(r0); r1 = tanhf(r1); }
        A.out[b * HDIM + tid]       = r0;
        A.out[b * HDIM + tid + 128] = r1;
    }
}

// ---------------- code + per-batch hinge (merged) ----------------
__global__ __launch_bounds__(256) void loss1_kernel(const float* Wf, const float* bfv) {
    const int b = blockIdx.x;
    const int tid = threadIdx.x;
    const int warp = tid >> 5, lane = tid & 31;
    __shared__ float cat[2 * HDIM];
    __shared__ float sm[8][5];

    cat[tid]        = g_pool[0][b * HDIM + tid];
    cat[HDIM + tid] = g_pool[1][b * HDIM + tid];
    __syncthreads();

    // code[tid] = tanh(sum_j cat[j] * Wf[j*256+tid] + bf[tid]) -- 4-way split acc for MLP
    float a0 = 0.f, a1 = 0.f, a2 = 0.f, a3 = 0.f;
    const float* wp = Wf + tid;
#pragma unroll 8
    for (int j = 0; j < 2 * HDIM; j += 4) {
        a0 += cat[j]     * wp[(size_t)j * HDIM];
        a1 += cat[j + 1] * wp[(size_t)(j + 1) * HDIM];
        a2 += cat[j + 2] * wp[(size_t)(j + 2) * HDIM];
        a3 += cat[j + 3] * wp[(size_t)(j + 3) * HDIM];
    }
    float c = tanhf(a0 + a1 + a2 + a3 + bfv[tid]);

    float a = g_pool[2][b * HDIM + tid];
    float n = g_pool[3][b * HDIM + tid];
    float s0 = c * c, s1 = a * a, s2 = n * n, s3 = c * a, s4 = c * n;
#pragma unroll
    for (int o = 16; o > 0; o >>= 1) {
        s0 += __shfl_xor_sync(0xffffffffu, s0, o);
        s1 += __shfl_xor_sync(0xffffffffu, s1, o);
        s2 += __shfl_xor_sync(0xffffffffu, s2, o);
        s3 += __shfl_xor_sync(0xffffffffu, s3, o);
        s4 += __shfl_xor_sync(0xffffffffu, s4, o);
    }
    if (lane == 0) {
        sm[warp][0] = s0; sm[warp][1] = s1; sm[warp][2] = s2;
        sm[warp][3] = s3; sm[warp][4] = s4;
    }
    __syncthreads();
    if (tid == 0) {
        float t0 = 0, t1 = 0, t2 = 0, t3 = 0, t4 = 0;
#pragma unroll
        for (int wv = 0; wv < 8; wv++) {
            t0 += sm[wv][0]; t1 += sm[wv][1]; t2 += sm[wv][2];
            t3 += sm[wv][3]; t4 += sm[wv][4];
        }
        float nc = sqrtf(t0);
        float sa = t3 / fmaxf(nc * sqrtf(t1), 1e-8f);
        float sn = t4 / fmaxf(nc * sqrtf(t2), 1e-8f);
        g_hinge[b] = fmaxf(0.6f - sa + sn, 0.f);
    }
}

__global__ void loss2_kernel(float* out) {
    int t = threadIdx.x;
    float v = g_hinge[t] + g_hinge[t + 32];
#pragma unroll
    for (int o = 16; o > 0; o >>= 1) v += __shfl_xor_sync(0xffffffffu, v, o);
    if (t == 0) out[0] = v / (float)BATCH;
}

// ---------------- launch ----------------
extern "C" void kernel_launch(void* const* d_in, const int* in_sizes, int n_in,
                              void* d_out, int out_size) {
    const float* token_feat = (const float*)d_in[0];
    const int*   token_mask = (const int*)d_in[1];
    const float* graph_feat = (const float*)d_in[2];
    const int*   graph_mask = (const int*)d_in[3];
    const float* da_feat    = (const float*)d_in[4];
    const int*   da_mask    = (const int*)d_in[5];
    const float* dn_feat    = (const float*)d_in[6];
    const int*   dn_mask    = (const int*)d_in[7];
    const float* Wt = (const float*)d_in[8];
    const float* bt = (const float*)d_in[9];
    const float* vt = (const float*)d_in[10];
    const float* ct = (const float*)d_in[11];
    const float* Wg = (const float*)d_in[12];
    const float* bg = (const float*)d_in[13];
    const float* vg = (const float*)d_in[14];
    const float* cg = (const float*)d_in[15];
    const float* Wd = (const float*)d_in[16];
    const float* bd = (const float*)d_in[17];
    const float* vd = (const float*)d_in[18];
    const float* cd = (const float*)d_in[19];
    const float* Wf = (const float*)d_in[20];
    const float* bf = (const float*)d_in[21];

    cudaFuncSetAttribute(score_tc, cudaFuncAttributeMaxDynamicSharedMemorySize, SCORE_SMEM);

    float* scores = nullptr;
    float* poolp  = nullptr;
    __half* wtp = nullptr;
    cudaGetSymbolAddress((void**)&scores, g_scores);
    cudaGetSymbolAddress((void**)&poolp, g_pool);
    cudaGetSymbolAddress((void**)&wtp, g_WT);

    float* s_tok = scores;
    float* s_gr  = scores + BATCH * S_TOK;
    float* s_da  = s_gr + BATCH * S_OTH;
    float* s_dn  = s_da + BATCH * S_OTH;

    wconv_kernel<<<dim3(256, 3), 256>>>(Wt, Wg, Wd);

    const int nTok = BATCH * S_TOK / 128;   // 1024
    const int nOth = BATCH * S_OTH / 128;   // 256

    ScoreArgs sa0 = {token_feat, bt, vt, ct, s_tok, 0, 0,               0};
    ScoreArgs sa1 = {graph_feat, bg, vg, cg, s_gr,  1, nTok,            65536};
    ScoreArgs sa2 = {da_feat,    bd, vd, cd, s_da,  0, nTok + nOth,     131072};
    ScoreArgs sa3 = {dn_feat,    bd, vd, cd, s_dn,  0, nTok + 2 * nOth, 131072};
    score_tc<<<nTok + 3 * nOth, 256, SCORE_SMEM>>>(sa0, sa1, sa2, sa3, wtp);

    PoolArgs pa0 = {token_feat, token_mask, s_tok, poolp + 0 * BATCH * HDIM, S_TOK, 0, 1};
    PoolArgs pa1 = {graph_feat, graph_mask, s_gr,  poolp + 1 * BATCH * HDIM, S_OTH, 1, 1};
    PoolArgs pa2 = {da_feat,    da_mask,    s_da,  poolp + 2 * BATCH * HDIM, S_OTH, 0, 2};
    PoolArgs pa3 = {dn_feat,    dn_mask,    s_dn,  poolp + 3 * BATCH * HDIM, S_OTH, 0, 2};
    pool_kernel<<<4 * BATCH, 512>>>(pa0, pa1, pa2, pa3);

    loss1_kernel<<<BATCH, 256>>>(Wf, bf);
    loss2_kernel<<<1, 32>>>((float*)d_out);
}

// round 8
// speedup vs baseline: 3.7778x; 1.1198x over previous
#include <cuda_runtime.h>
#include <cuda_fp16.h>
#include <stdint.h>
#include <math.h>

#define HDIM 256
#define BATCH 64
#define S_TOK 2048
#define S_OTH 512
#define NEGV (-1e9f)

// ---------------- scratch (no allocations allowed) ----------------
__device__ float g_scores[BATCH*S_TOK + 3*BATCH*S_OTH];
__device__ float g_pool[4][BATCH*HDIM];
__device__ float g_code[BATCH*HDIM];
__device__ float g_hinge[BATCH];
__device__ float g_msum[2][4][BATCH];        // [0]=max, [1]=expsum
__device__ float g_part[4*BATCH*4*HDIM];     // [pool][b][chunk][col]
// W transposed, fp16: [mat 0..2][n*256+k]
__device__ __half g_WT[3 * 65536];

// ---------------- PTX helpers ----------------
__device__ __forceinline__ uint32_t smem_to_u32(const void* p) {
    uint32_t a;
    asm("{ .reg .u64 tmp; cvta.to.shared.u64 tmp, %1; cvt.u32.u64 %0, tmp; }" : "=r"(a) : "l"(p));
    return a;
}
#define LDSM_X4(r0,r1,r2,r3,addr) \
    asm volatile("ldmatrix.sync.aligned.m8n8.x4.shared.b16 {%0,%1,%2,%3}, [%4];" \
        : "=r"(r0),"=r"(r1),"=r"(r2),"=r"(r3) : "r"(addr))
#define MMA_F16(c, a, b) \
    asm volatile("mma.sync.aligned.m16n8k16.row.col.f32.f16.f16.f32 " \
        "{%0,%1,%2,%3},{%4,%5,%6,%7},{%8,%9},{%0,%1,%2,%3};" \
        : "+f"((c)[0]),"+f"((c)[1]),"+f"((c)[2]),"+f"((c)[3]) \
        : "r"((a)[0]),"r"((a)[1]),"r"((a)[2]),"r"((a)[3]),"r"((b)[0]),"r"((b)[1]))
#define CP_ASYNC16(dst, src) \
    asm volatile("cp.async.cg.shared.global [%0], [%1], 16;" :: "r"(dst), "l"(src) : "memory")
#define CP_COMMIT() asm volatile("cp.async.commit_group;" ::: "memory")
#define CP_WAIT(n)  asm volatile("cp.async.wait_group %0;" :: "n"(n) : "memory")

// ---------------- W transpose to fp16 ----------------
__global__ void wconv_kernel(const float* Wt, const float* Wg, const float* Wd) {
    int mat = blockIdx.y;
    const float* W = (mat == 0) ? Wt : (mat == 1) ? Wg : Wd;
    int k = blockIdx.x, n = threadIdx.x;
    g_WT[mat * 65536 + n * 256 + k] = __float2half_rn(W[k * 256 + n]);
}

// ---------------- score kernel: mma.sync fp16, single-term ----------------
#define A_ST 264
#define WB_ST 528
#define SA_OFF 0
#define SW_OFF 67584
#define SW_CHN 67584
#define SBIAS 202752
#define SVV   203776
#define SPART 204800
#define SCORE_SMEM 205824

struct ScoreArgs {
    const float* feat;
    const float* bv;
    const float* v;
    const float* c;
    float* sout;
    int pretanh;
    int blkStart;
    int wtOff;
};

__global__ __launch_bounds__(256, 1) void score_tc(ScoreArgs A0, ScoreArgs A1,
                                                   ScoreArgs A2, ScoreArgs A3,
                                                   const __half* WTg) {
    ScoreArgs A;
    int blk = blockIdx.x;
    if (blk >= A3.blkStart)      A = A3;
    else if (blk >= A2.blkStart) A = A2;
    else if (blk >= A1.blkStart) A = A1;
    else                         A = A0;
    const int row0 = (blk - A.blkStart) * 128;

    extern __shared__ char smem[];
    const uint32_t sbase = smem_to_u32(smem);
    float* sBias = (float*)(smem + SBIAS);
    float* sV    = (float*)(smem + SVV);
    float* sPart = (float*)(smem + SPART);

    const int tid  = threadIdx.x;
    const int warp = tid >> 5;
    const int lane = tid & 31;
    const int wm = warp & 3;
    const int wn = warp >> 2;
    const int tq = lane & 3;
    const int gp = lane >> 2;

    const __half* WT = WTg + A.wtOff;

#pragma unroll
    for (int hf = 0; hf < 2; hf++) {
        for (int i = tid; i < 4096; i += 256) {
            int r = i >> 5, j = i & 31;
            const __half* src = WT + (size_t)(hf * 128 + r) * 256 + j * 8;
            uint32_t dst = sbase + SW_OFF + hf * SW_CHN + (uint32_t)(r * WB_ST + j * 16);
            CP_ASYNC16(dst, src);
        }
        CP_COMMIT();
    }

    sBias[tid] = A.bv[tid];
    sV[tid]    = A.v[tid];
    if (tid < 128) { sPart[tid * 2] = 0.f; sPart[tid * 2 + 1] = 0.f; }

    {
        const float4* f4 = (const float4*)A.feat + (size_t)row0 * (HDIM / 4);
        const int pt = A.pretanh;
        for (int i = tid; i < 128 * 64; i += 256) {
            float4 t = f4[i];
            if (pt) { t.x = tanhf(t.x); t.y = tanhf(t.y); t.z = tanhf(t.z); t.w = tanhf(t.w); }
            int r = i >> 6, c = (i & 63) << 2;
            __half2 h0 = __float22half2_rn(make_float2(t.x, t.y));
            __half2 h1 = __float22half2_rn(make_float2(t.z, t.w));
            uint2 hu;
            hu.x = *(uint32_t*)&h0; hu.y = *(uint32_t*)&h1;
            *(uint2*)(smem + SA_OFF + (size_t)(r * A_ST + c) * 2) = hu;
        }
    }
    __syncthreads();

    const uint32_t aBase = sbase + SA_OFF;
    const uint32_t aLaneOff = (uint32_t)(((wm * 32 + (lane & 15)) * A_ST + ((lane >> 4) << 3)) * 2);
    const uint32_t bLane = (uint32_t)(((lane & 7) + ((lane >> 4) << 3)) * WB_ST + (((lane >> 3) & 1) << 4));

    for (int half = 0; half < 2; half++) {
        float acc[2][8][4];
#pragma unroll
        for (int mi = 0; mi < 2; mi++)
#pragma unroll
            for (int nj = 0; nj < 8; nj++) {
                acc[mi][nj][0] = 0.f; acc[mi][nj][1] = 0.f;
                acc[mi][nj][2] = 0.f; acc[mi][nj][3] = 0.f;
            }

        if (half == 0) CP_WAIT(1); else CP_WAIT(0);
        __syncthreads();

        const uint32_t wbBase = sbase + SW_OFF + half * SW_CHN + bLane;

#pragma unroll
        for (int ks = 0; ks < 16; ks++) {
            const uint32_t kOffA = (uint32_t)(ks * 32);
            uint32_t aF[2][4];
#pragma unroll
            for (int mi = 0; mi < 2; mi++) {
                uint32_t ad = aLaneOff + (uint32_t)(mi * 16 * A_ST * 2) + kOffA;
                LDSM_X4(aF[mi][0], aF[mi][1], aF[mi][2], aF[mi][3], aBase + ad);
            }
            uint32_t bF[8][2];
#pragma unroll
            for (int nb = 0; nb < 4; nb++) {
                uint32_t bd = (uint32_t)((wn * 64 + nb * 16) * WB_ST + ks * 32);
                uint32_t r0, r1, r2, r3;
                LDSM_X4(r0, r1, r2, r3, wbBase + bd);
                bF[2*nb][0] = r0; bF[2*nb][1] = r1;
                bF[2*nb+1][0] = r2; bF[2*nb+1][1] = r3;
            }
#pragma unroll
            for (int mi = 0; mi < 2; mi++)
#pragma unroll
                for (int nj = 0; nj < 8; nj++)
                    MMA_F16(acc[mi][nj], aF[mi], bF[nj]);
        }

#pragma unroll
        for (int mi = 0; mi < 2; mi++) {
            float p0 = 0.f, p1 = 0.f;
#pragma unroll
            for (int nj = 0; nj < 8; nj++) {
                int col = half * 128 + wn * 64 + nj * 8 + tq * 2;
                float b0 = sBias[col], b1 = sBias[col + 1];
                float v0 = sV[col],    v1 = sV[col + 1];
                p0 += tanhf(acc[mi][nj][0] + b0) * v0 + tanhf(acc[mi][nj][1] + b1) * v1;
                p1 += tanhf(acc[mi][nj][2] + b0) * v0 + tanhf(acc[mi][nj][3] + b1) * v1;
            }
            p0 += __shfl_xor_sync(0xffffffffu, p0, 1);
            p0 += __shfl_xor_sync(0xffffffffu, p0, 2);
            p1 += __shfl_xor_sync(0xffffffffu, p1, 1);
            p1 += __shfl_xor_sync(0xffffffffu, p1, 2);
            if (tq == 0) {
                int r0 = wm * 32 + mi * 16 + gp;
                sPart[r0 * 2 + wn]       += p0;
                sPart[(r0 + 8) * 2 + wn] += p1;
            }
        }
    }
    __syncthreads();
    if (tid < 128)
        A.sout[row0 + tid] = sPart[tid * 2] + sPart[tid * 2 + 1] + A.c[0];
}

// ---------------- pool phase 1: masked max + expsum per (pool, b) ----------------
struct PoolPtr {
    const float* feat;
    const int* mask;
    const float* scores;
    int S;
    int pretanh;
    int posttanh;
};

__global__ __launch_bounds__(256) void pool_p1(PoolPtr P0, PoolPtr P1, PoolPtr P2, PoolPtr P3) {
    int pool = blockIdx.x & 3;
    int b    = blockIdx.x >> 2;
    PoolPtr P = (pool == 0) ? P0 : (pool == 1) ? P1 : (pool == 2) ? P2 : P3;
    __shared__ float red[256];
    const int tid = threadIdx.x;
    const int S = P.S;
    const float* sc = P.scores + (size_t)b * S;
    const int* mk = P.mask + (size_t)b * S;

    float m = -3.4e38f;
    for (int s = tid; s < S; s += 256)
        m = fmaxf(m, mk[s] ? sc[s] : NEGV);
    red[tid] = m;
    __syncthreads();
    for (int st = 128; st > 0; st >>= 1) {
        if (tid < st) red[tid] = fmaxf(red[tid], red[tid + st]);
        __syncthreads();
    }
    m = red[0];
    __syncthreads();

    float e = 0.f;
    for (int s = tid; s < S; s += 256)
        e += mk[s] ? __expf(sc[s] - m) : 0.f;
    red[tid] = e;
    __syncthreads();
    for (int st = 128; st > 0; st >>= 1) {
        if (tid < st) red[tid] += red[tid + st];
        __syncthreads();
    }
    if (tid == 0) {
        g_msum[0][pool][b] = m;
        g_msum[1][pool][b] = red[0];
    }
}

// ---------------- pool phase 2: weighted partial sums over 512-pos chunks ----------------
// blocks 0..255: pool 0 (token), b=blk>>2, chunk=blk&3
// blocks 256..447: pool 1+((blk-256)>>6), b=(blk-256)&63, chunk=0
__global__ __launch_bounds__(512) void pool_p2(PoolPtr P0, PoolPtr P1, PoolPtr P2, PoolPtr P3) {
    int blk = blockIdx.x;
    int pool, b, chunk;
    if (blk < 256) { pool = 0; b = blk >> 2; chunk = blk & 3; }
    else { int r = blk - 256; pool = 1 + (r >> 6); b = r & 63; chunk = 0; }
    PoolPtr P = (pool == 0) ? P0 : (pool == 1) ? P1 : (pool == 2) ? P2 : P3;

    __shared__ float w[512];
    __shared__ float red[512];
    const int tid = threadIdx.x;
    const int s0 = chunk * 512;
    const float m = g_msum[0][pool][b];

    {
        const float* sc = P.scores + (size_t)b * P.S + s0;
        const int* mk = P.mask + (size_t)b * P.S + s0;
        w[tid] = mk[tid] ? __expf(sc[tid] - m) : 0.f;
    }
    __syncthreads();

    const int col = tid & 255;
    const int stripe = tid >> 8;
    const float* f = P.feat + (size_t)b * P.S * HDIM + (size_t)s0 * HDIM + col;
    float acc = 0.f;
    if (P.pretanh) {
        for (int s = stripe; s < 512; s += 2)
            acc += w[s] * tanhf(f[(size_t)s * HDIM]);
    } else {
#pragma unroll 8
        for (int s = stripe; s < 512; s += 2)
            acc += w[s] * f[(size_t)s * HDIM];
    }
    red[tid] = acc;
    __syncthreads();
    if (tid < 256)
        g_part[(((pool * BATCH) + b) * 4 + chunk) * HDIM + tid] = red[tid] + red[tid + 256];
}

// ---------------- pool phase 3: combine chunks, normalize, tanh ----------------
__global__ __launch_bounds__(256) void pool_p3() {
    int pool = blockIdx.x & 3;
    int b    = blockIdx.x >> 2;
    const int tid = threadIdx.x;
    const int nch = (pool == 0) ? 4 : 1;
    const float* pp = g_part + (((pool * BATCH) + b) * 4) * HDIM + tid;
    float s = 0.f;
    for (int c = 0; c < nch; c++) s += pp[c * HDIM];
    s /= g_msum[1][pool][b];
    s = tanhf(s);
    if (pool >= 2) s = tanhf(s);   // desc pools: double tanh
    g_pool[pool][b * HDIM + tid] = s;
}

// ---------------- code = tanh([tok, gr] @ Wf + bf); 512 blocks ----------------
__global__ __launch_bounds__(256) void code_kernel(const float* Wf, const float* bfv) {
    int b  = blockIdx.x >> 3;
    int cg = blockIdx.x & 7;         // 8 col groups of 32
    const int tid = threadIdx.x;
    const int jg = tid >> 5;         // 8 j-groups of 64
    const int ci = tid & 31;
    const int col = cg * 32 + ci;
    __shared__ float cat[2 * HDIM];
    __shared__ float part[256];

    cat[tid]        = g_pool[0][b * HDIM + tid];
    cat[HDIM + tid] = g_pool[1][b * HDIM + tid];
    __syncthreads();

    float acc = 0.f;
    const float* wp = Wf + col;
    const int j0 = jg * 64;
#pragma unroll 8
    for (int j = 0; j < 64; j++)
        acc += cat[j0 + j] * wp[(size_t)(j0 + j) * HDIM];
    part[tid] = acc;
    __syncthreads();
    if (tid < 32) {
        float s = bfv[col - ci + tid];
#pragma unroll
        for (int g = 0; g < 8; g++) s += part[g * 32 + tid];
        g_code[b * HDIM + cg * 32 + tid] = tanhf(s);
    }
}

// ---------------- per-batch hinge ----------------
__global__ __launch_bounds__(256) void loss1_kernel() {
    const int b = blockIdx.x;
    const int tid = threadIdx.x;
    const int warp = tid >> 5, lane = tid & 31;
    __shared__ float sm[8][5];

    float c = g_code[b * HDIM + tid];
    float a = g_pool[2][b * HDIM + tid];
    float n = g_pool[3][b * HDIM + tid];
    float s0 = c * c, s1 = a * a, s2 = n * n, s3 = c * a, s4 = c * n;
#pragma unroll
    for (int o = 16; o > 0; o >>= 1) {
        s0 += __shfl_xor_sync(0xffffffffu, s0, o);
        s1 += __shfl_xor_sync(0xffffffffu, s1, o);
        s2 += __shfl_xor_sync(0xffffffffu, s2, o);
        s3 += __shfl_xor_sync(0xffffffffu, s3, o);
        s4 += __shfl_xor_sync(0xffffffffu, s4, o);
    }
    if (lane == 0) {
        sm[warp][0] = s0; sm[warp][1] = s1; sm[warp][2] = s2;
        sm[warp][3] = s3; sm[warp][4] = s4;
    }
    __syncthreads();
    if (tid == 0) {
        float t0 = 0, t1 = 0, t2 = 0, t3 = 0, t4 = 0;
#pragma unroll
        for (int wv = 0; wv < 8; wv++) {
            t0 += sm[wv][0]; t1 += sm[wv][1]; t2 += sm[wv][2];
            t3 += sm[wv][3]; t4 += sm[wv][4];
        }
        float nc = sqrtf(t0);
        float sa = t3 / fmaxf(nc * sqrtf(t1), 1e-8f);
        float sn = t4 / fmaxf(nc * sqrtf(t2), 1e-8f);
        g_hinge[b] = fmaxf(0.6f - sa + sn, 0.f);
    }
}

__global__ void loss2_kernel(float* out) {
    int t = threadIdx.x;
    float v = g_hinge[t] + g_hinge[t + 32];
#pragma unroll
    for (int o = 16; o > 0; o >>= 1) v += __shfl_xor_sync(0xffffffffu, v, o);
    if (t == 0) out[0] = v / (float)BATCH;
}

// ---------------- launch ----------------
extern "C" void kernel_launch(void* const* d_in, const int* in_sizes, int n_in,
                              void* d_out, int out_size) {
    const float* token_feat = (const float*)d_in[0];
    const int*   token_mask = (const int*)d_in[1];
    const float* graph_feat = (const float*)d_in[2];
    const int*   graph_mask = (const int*)d_in[3];
    const float* da_feat    = (const float*)d_in[4];
    const int*   da_mask    = (const int*)d_in[5];
    const float* dn_feat    = (const float*)d_in[6];
    const int*   dn_mask    = (const int*)d_in[7];
    const float* Wt = (const float*)d_in[8];
    const float* bt = (const float*)d_in[9];
    const float* vt = (const float*)d_in[10];
    const float* ct = (const float*)d_in[11];
    const float* Wg = (const float*)d_in[12];
    const float* bg = (const float*)d_in[13];
    const float* vg = (const float*)d_in[14];
    const float* cg = (const float*)d_in[15];
    const float* Wd = (const float*)d_in[16];
    const float* bd = (const float*)d_in[17];
    const float* vd = (const float*)d_in[18];
    const float* cd = (const float*)d_in[19];
    const float* Wf = (const float*)d_in[20];
    const float* bf = (const float*)d_in[21];

    cudaFuncSetAttribute(score_tc, cudaFuncAttributeMaxDynamicSharedMemorySize, SCORE_SMEM);

    float* scores = nullptr;
    __half* wtp = nullptr;
    cudaGetSymbolAddress((void**)&scores, g_scores);
    cudaGetSymbolAddress((void**)&wtp, g_WT);

    float* s_tok = scores;
    float* s_gr  = scores + BATCH * S_TOK;
    float* s_da  = s_gr + BATCH * S_OTH;
    float* s_dn  = s_da + BATCH * S_OTH;

    wconv_kernel<<<dim3(256, 3), 256>>>(Wt, Wg, Wd);

    const int nTok = BATCH * S_TOK / 128;   // 1024
    const int nOth = BATCH * S_OTH / 128;   // 256

    ScoreArgs sa0 = {token_feat, bt, vt, ct, s_tok, 0, 0,               0};
    ScoreArgs sa1 = {graph_feat, bg, vg, cg, s_gr,  1, nTok,            65536};
    ScoreArgs sa2 = {da_feat,    bd, vd, cd, s_da,  0, nTok + nOth,     131072};
    ScoreArgs sa3 = {dn_feat,    bd, vd, cd, s_dn,  0, nTok + 2 * nOth, 131072};
    score_tc<<<nTok + 3 * nOth, 256, SCORE_SMEM>>>(sa0, sa1, sa2, sa3, wtp);

    PoolPtr p0 = {token_feat, token_mask, s_tok, S_TOK, 0, 1};
    PoolPtr p1 = {graph_feat, graph_mask, s_gr,  S_OTH, 1, 1};
    PoolPtr p2 = {da_feat,    da_mask,    s_da,  S_OTH, 0, 2};
    PoolPtr p3 = {dn_feat,    dn_mask,    s_dn,  S_OTH, 0, 2};

    pool_p1<<<4 * BATCH, 256>>>(p0, p1, p2, p3);
    pool_p2<<<448, 512>>>(p0, p1, p2, p3);
    pool_p3<<<4 * BATCH, 256>>>();

    code_kernel<<<8 * BATCH, 256>>>(Wf, bf);
    loss1_kernel<<<BATCH, 256>>>();
    loss2_kernel<<<1, 32>>>((float*)d_out);
}

// round 9
// speedup vs baseline: 4.2316x; 1.1201x over previous
#include <cuda_runtime.h>
#include <cuda_fp16.h>
#include <stdint.h>
#include <math.h>

#define HDIM 256
#define BATCH 64
#define S_TOK 2048
#define S_OTH 512
#define NEGV (-1e9f)

// ---------------- scratch (no allocations allowed) ----------------
__device__ float g_scores[BATCH*S_TOK + 3*BATCH*S_OTH];
__device__ float g_pool[4][BATCH*HDIM];
__device__ float g_code[BATCH*HDIM];
__device__ float g_hinge[BATCH];
__device__ float g_msum[2][4][BATCH];        // [0]=max, [1]=expsum
__device__ float g_part[4*BATCH*4*HDIM];     // [pool][b][chunk][col]
__device__ __half g_WT[3 * 65536];           // W transposed fp16: [mat][n*256+k]

// ---------------- PTX helpers ----------------
__device__ __forceinline__ uint32_t smem_to_u32(const void* p) {
    uint32_t a;
    asm("{ .reg .u64 tmp; cvta.to.shared.u64 tmp, %1; cvt.u32.u64 %0, tmp; }" : "=r"(a) : "l"(p));
    return a;
}
#define LDSM_X4(r0,r1,r2,r3,addr) \
    asm volatile("ldmatrix.sync.aligned.m8n8.x4.shared.b16 {%0,%1,%2,%3}, [%4];" \
        : "=r"(r0),"=r"(r1),"=r"(r2),"=r"(r3) : "r"(addr))
#define MMA_F16(c, a, b) \
    asm volatile("mma.sync.aligned.m16n8k16.row.col.f32.f16.f16.f32 " \
        "{%0,%1,%2,%3},{%4,%5,%6,%7},{%8,%9},{%0,%1,%2,%3};" \
        : "+f"((c)[0]),"+f"((c)[1]),"+f"((c)[2]),"+f"((c)[3]) \
        : "r"((a)[0]),"r"((a)[1]),"r"((a)[2]),"r"((a)[3]),"r"((b)[0]),"r"((b)[1]))
#define CP_ASYNC16(dst, src) \
    asm volatile("cp.async.cg.shared.global [%0], [%1], 16;" :: "r"(dst), "l"(src) : "memory")
#define CP_COMMIT() asm volatile("cp.async.commit_group;" ::: "memory")
#define CP_WAIT(n)  asm volatile("cp.async.wait_group %0;" :: "n"(n) : "memory")

// ---------------- W transpose to fp16 ----------------
__global__ void wconv_kernel(const float* Wt, const float* Wg, const float* Wd) {
    int mat = blockIdx.y;
    const float* W = (mat == 0) ? Wt : (mat == 1) ? Wg : Wd;
    int k = blockIdx.x, n = threadIdx.x;
    g_WT[mat * 65536 + n * 256 + k] = __float2half_rn(W[k * 256 + n]);
}

// ---------------- score kernel: fp16 mma, A register-pipelined by K-chunk ----------------
#define A_ST 264
#define WB_ST 528
#define SA_OFF 0
#define SW_OFF 67584
#define SW_CHN 67584
#define SBIAS 202752
#define SVV   203776
#define SPART 204800
#define SCORE_SMEM 205824

struct ScoreArgs {
    const float* feat;
    const float* bv;
    const float* v;
    const float* c;
    float* sout;
    int pretanh;
    int blkStart;
    int wtOff;
};

__device__ __forceinline__ void convert_sts_chunk(char* smem, const float4* av,
                                                  int r, int cbase, int pt) {
#pragma unroll
    for (int j = 0; j < 8; j++) {
        float4 t = av[j];
        if (pt) { t.x = tanhf(t.x); t.y = tanhf(t.y); t.z = tanhf(t.z); t.w = tanhf(t.w); }
        __half2 h0 = __float22half2_rn(make_float2(t.x, t.y));
        __half2 h1 = __float22half2_rn(make_float2(t.z, t.w));
        uint2 hu;
        hu.x = *(uint32_t*)&h0; hu.y = *(uint32_t*)&h1;
        *(uint2*)(smem + SA_OFF + (size_t)(r * A_ST + cbase + j * 4) * 2) = hu;
    }
}

__global__ __launch_bounds__(256, 1) void score_tc(ScoreArgs A0, ScoreArgs A1,
                                                   ScoreArgs A2, ScoreArgs A3,
                                                   const __half* WTg) {
    ScoreArgs A;
    int blk = blockIdx.x;
    if (blk >= A3.blkStart)      A = A3;
    else if (blk >= A2.blkStart) A = A2;
    else if (blk >= A1.blkStart) A = A1;
    else                         A = A0;
    const int row0 = (blk - A.blkStart) * 128;

    extern __shared__ char smem[];
    const uint32_t sbase = smem_to_u32(smem);
    float* sBias = (float*)(smem + SBIAS);
    float* sV    = (float*)(smem + SVV);
    float* sPart = (float*)(smem + SPART);

    const int tid  = threadIdx.x;
    const int warp = tid >> 5;
    const int lane = tid & 31;
    const int wm = warp & 3;
    const int wn = warp >> 2;
    const int tq = lane & 3;
    const int gp = lane >> 2;

    const __half* WT = WTg + A.wtOff;
    const int pt = A.pretanh;

    // W prefetch: both N-halves (each 128 n-rows x 256 k fp16)
#pragma unroll
    for (int hf = 0; hf < 2; hf++) {
        for (int i = tid; i < 4096; i += 256) {
            int r = i >> 5, j = i & 31;
            const __half* src = WT + (size_t)(hf * 128 + r) * 256 + j * 8;
            uint32_t dst = sbase + SW_OFF + hf * SW_CHN + (uint32_t)(r * WB_ST + j * 16);
            CP_ASYNC16(dst, src);
        }
        CP_COMMIT();
    }

    sBias[tid] = A.bv[tid];
    sV[tid]    = A.v[tid];
    if (tid < 128) { sPart[tid * 2] = 0.f; sPart[tid * 2 + 1] = 0.f; }

    // A chunk layout: thread t covers row r=t>>1, cols h2*32..h2*32+31 of the chunk
    const int ar = tid >> 1;
    const int ac = (tid & 1) * 32;
    const float* arow = A.feat + (size_t)(row0 + ar) * HDIM + ac;

    // prologue: chunk 0 (k 0..63)
    {
        float4 av[8];
#pragma unroll
        for (int j = 0; j < 8; j++) av[j] = ((const float4*)arow)[j];
        convert_sts_chunk(smem, av, ar, ac, pt);
    }

    CP_WAIT(1);            // W half0 ready
    __syncthreads();       // A chunk0 + W half0 visible

    const uint32_t aBase = sbase + SA_OFF;
    const uint32_t aLaneOff = (uint32_t)(((wm * 32 + (lane & 15)) * A_ST + ((lane >> 4) << 3)) * 2);
    const uint32_t bLane = (uint32_t)(((lane & 7) + ((lane >> 4) << 3)) * WB_ST + (((lane >> 3) & 1) << 4));

    float acc[2][8][4];

    // ---------------- half 0: MMA pipelined with A chunk streaming ----------------
#pragma unroll
    for (int mi = 0; mi < 2; mi++)
#pragma unroll
        for (int nj = 0; nj < 8; nj++) {
            acc[mi][nj][0] = 0.f; acc[mi][nj][1] = 0.f;
            acc[mi][nj][2] = 0.f; acc[mi][nj][3] = 0.f;
        }
    {
        const uint32_t wbBase = sbase + SW_OFF + bLane;
        for (int kc = 0; kc < 4; kc++) {
            float4 av[8];
            if (kc < 3) {      // issue LDGs for chunk kc+1 before MMA of chunk kc
                const float4* src = (const float4*)(arow + (kc + 1) * 64);
#pragma unroll
                for (int j = 0; j < 8; j++) av[j] = src[j];
            }
#pragma unroll
            for (int ks = 0; ks < 4; ks++) {
                const uint32_t kOffA = (uint32_t)((kc * 64 + ks * 16) * 2);
                const int ksab = kc * 4 + ks;
                uint32_t aF[2][4];
#pragma unroll
                for (int mi = 0; mi < 2; mi++) {
                    uint32_t ad = aLaneOff + (uint32_t)(mi * 16 * A_ST * 2) + kOffA;
                    LDSM_X4(aF[mi][0], aF[mi][1], aF[mi][2], aF[mi][3], aBase + ad);
                }
                uint32_t bF[8][2];
#pragma unroll
                for (int nb = 0; nb < 4; nb++) {
                    uint32_t bd = (uint32_t)((wn * 64 + nb * 16) * WB_ST + ksab * 32);
                    uint32_t r0, r1, r2, r3;
                    LDSM_X4(r0, r1, r2, r3, wbBase + bd);
                    bF[2*nb][0] = r0; bF[2*nb][1] = r1;
                    bF[2*nb+1][0] = r2; bF[2*nb+1][1] = r3;
                }
#pragma unroll
                for (int mi = 0; mi < 2; mi++)
#pragma unroll
                    for (int nj = 0; nj < 8; nj++)
                        MMA_F16(acc[mi][nj], aF[mi], bF[nj]);
            }
            if (kc < 3) {
                convert_sts_chunk(smem, av, ar, (kc + 1) * 64 + ac - (tid & 1) * 32 + (tid & 1) * 32, pt);
                __syncthreads();   // chunk kc+1 visible for next iteration
            }
        }
    }
    // epilogue half 0
#pragma unroll
    for (int mi = 0; mi < 2; mi++) {
        float p0 = 0.f, p1 = 0.f;
#pragma unroll
        for (int nj = 0; nj < 8; nj++) {
            int col = wn * 64 + nj * 8 + tq * 2;
            float b0 = sBias[col], b1 = sBias[col + 1];
            float v0 = sV[col],    v1 = sV[col + 1];
            p0 += tanhf(acc[mi][nj][0] + b0) * v0 + tanhf(acc[mi][nj][1] + b1) * v1;
            p1 += tanhf(acc[mi][nj][2] + b0) * v0 + tanhf(acc[mi][nj][3] + b1) * v1;
        }
        p0 += __shfl_xor_sync(0xffffffffu, p0, 1);
        p0 += __shfl_xor_sync(0xffffffffu, p0, 2);
        p1 += __shfl_xor_sync(0xffffffffu, p1, 1);
        p1 += __shfl_xor_sync(0xffffffffu, p1, 2);
        if (tq == 0) {
            int r0 = wm * 32 + mi * 16 + gp;
            sPart[r0 * 2 + wn]       += p0;
            sPart[(r0 + 8) * 2 + wn] += p1;
        }
    }

    // ---------------- half 1: A fully resident ----------------
    CP_WAIT(0);
    __syncthreads();
#pragma unroll
    for (int mi = 0; mi < 2; mi++)
#pragma unroll
        for (int nj = 0; nj < 8; nj++) {
            acc[mi][nj][0] = 0.f; acc[mi][nj][1] = 0.f;
            acc[mi][nj][2] = 0.f; acc[mi][nj][3] = 0.f;
        }
    {
        const uint32_t wbBase = sbase + SW_OFF + SW_CHN + bLane;
#pragma unroll
        for (int ks = 0; ks < 16; ks++) {
            const uint32_t kOffA = (uint32_t)(ks * 32);
            uint32_t aF[2][4];
#pragma unroll
            for (int mi = 0; mi < 2; mi++) {
                uint32_t ad = aLaneOff + (uint32_t)(mi * 16 * A_ST * 2) + kOffA;
                LDSM_X4(aF[mi][0], aF[mi][1], aF[mi][2], aF[mi][3], aBase + ad);
            }
            uint32_t bF[8][2];
#pragma unroll
            for (int nb = 0; nb < 4; nb++) {
                uint32_t bd = (uint32_t)((wn * 64 + nb * 16) * WB_ST + ks * 32);
                uint32_t r0, r1, r2, r3;
                LDSM_X4(r0, r1, r2, r3, wbBase + bd);
                bF[2*nb][0] = r0; bF[2*nb][1] = r1;
                bF[2*nb+1][0] = r2; bF[2*nb+1][1] = r3;
            }
#pragma unroll
            for (int mi = 0; mi < 2; mi++)
#pragma unroll
                for (int nj = 0; nj < 8; nj++)
                    MMA_F16(acc[mi][nj], aF[mi], bF[nj]);
        }
    }
    // epilogue half 1
#pragma unroll
    for (int mi = 0; mi < 2; mi++) {
        float p0 = 0.f, p1 = 0.f;
#pragma unroll
        for (int nj = 0; nj < 8; nj++) {
            int col = 128 + wn * 64 + nj * 8 + tq * 2;
            float b0 = sBias[col], b1 = sBias[col + 1];
            float v0 = sV[col],    v1 = sV[col + 1];
            p0 += tanhf(acc[mi][nj][0] + b0) * v0 + tanhf(acc[mi][nj][1] + b1) * v1;
            p1 += tanhf(acc[mi][nj][2] + b0) * v0 + tanhf(acc[mi][nj][3] + b1) * v1;
        }
        p0 += __shfl_xor_sync(0xffffffffu, p0, 1);
        p0 += __shfl_xor_sync(0xffffffffu, p0, 2);
        p1 += __shfl_xor_sync(0xffffffffu, p1, 1);
        p1 += __shfl_xor_sync(0xffffffffu, p1, 2);
        if (tq == 0) {
            int r0 = wm * 32 + mi * 16 + gp;
            sPart[r0 * 2 + wn]       += p0;
            sPart[(r0 + 8) * 2 + wn] += p1;
        }
    }

    __syncthreads();
    if (tid < 128)
        A.sout[row0 + tid] = sPart[tid * 2] + sPart[tid * 2 + 1] + A.c[0];
}

// ---------------- pool phase 1: masked max + expsum per (pool, b) ----------------
struct PoolPtr {
    const float* feat;
    const int* mask;
    const float* scores;
    int S;
    int pretanh;
    int posttanh;
};

__global__ __launch_bounds__(256) void pool_p1(PoolPtr P0, PoolPtr P1, PoolPtr P2, PoolPtr P3) {
    int pool = blockIdx.x & 3;
    int b    = blockIdx.x >> 2;
    PoolPtr P = (pool == 0) ? P0 : (pool == 1) ? P1 : (pool == 2) ? P2 : P3;
    __shared__ float red[256];
    const int tid = threadIdx.x;
    const int S = P.S;
    const float* sc = P.scores + (size_t)b * S;
    const int* mk = P.mask + (size_t)b * S;

    float m = -3.4e38f;
    for (int s = tid; s < S; s += 256)
        m = fmaxf(m, mk[s] ? sc[s] : NEGV);
    red[tid] = m;
    __syncthreads();
    for (int st = 128; st > 0; st >>= 1) {
        if (tid < st) red[tid] = fmaxf(red[tid], red[tid + st]);
        __syncthreads();
    }
    m = red[0];
    __syncthreads();

    float e = 0.f;
    for (int s = tid; s < S; s += 256)
        e += mk[s] ? __expf(sc[s] - m) : 0.f;
    red[tid] = e;
    __syncthreads();
    for (int st = 128; st > 0; st >>= 1) {
        if (tid < st) red[tid] += red[tid + st];
        __syncthreads();
    }
    if (tid == 0) {
        g_msum[0][pool][b] = m;
        g_msum[1][pool][b] = red[0];
    }
}

// ---------------- pool phase 2: weighted partial sums, float4 per thread ----------------
__global__ __launch_bounds__(512) void pool_p2(PoolPtr P0, PoolPtr P1, PoolPtr P2, PoolPtr P3) {
    int blk = blockIdx.x;
    int pool, b, chunk;
    if (blk < 256) { pool = 0; b = blk >> 2; chunk = blk & 3; }
    else { int r = blk - 256; pool = 1 + (r >> 6); b = r & 63; chunk = 0; }
    PoolPtr P = (pool == 0) ? P0 : (pool == 1) ? P1 : (pool == 2) ? P2 : P3;

    __shared__ float w[512];
    __shared__ float4 red4[512];
    const int tid = threadIdx.x;
    const int s0 = chunk * 512;
    const float m = g_msum[0][pool][b];

    {
        const float* sc = P.scores + (size_t)b * P.S + s0;
        const int* mk = P.mask + (size_t)b * P.S + s0;
        w[tid] = mk[tid] ? __expf(sc[tid] - m) : 0.f;
    }
    __syncthreads();

    const int col4 = (tid & 63) * 4;      // 4 consecutive cols
    const int stripe = tid >> 6;          // 8 s-stripes
    const float4* f = (const float4*)(P.feat + (size_t)b * P.S * HDIM + (size_t)s0 * HDIM + col4);
    float4 acc = make_float4(0.f, 0.f, 0.f, 0.f);
    if (P.pretanh) {
        for (int s = stripe; s < 512; s += 8) {
            float ws = w[s];
            float4 t = f[(size_t)s * (HDIM / 4)];
            acc.x += ws * tanhf(t.x); acc.y += ws * tanhf(t.y);
            acc.z += ws * tanhf(t.z); acc.w += ws * tanhf(t.w);
        }
    } else {
#pragma unroll 8
        for (int s = stripe; s < 512; s += 8) {
            float ws = w[s];
            float4 t = f[(size_t)s * (HDIM / 4)];
            acc.x += ws * t.x; acc.y += ws * t.y;
            acc.z += ws * t.z; acc.w += ws * t.w;
        }
    }
    red4[tid] = acc;
    __syncthreads();
    if (tid < 64) {
        float4 s = red4[tid];
#pragma unroll
        for (int g = 1; g < 8; g++) {
            float4 t = red4[tid + g * 64];
            s.x += t.x; s.y += t.y; s.z += t.z; s.w += t.w;
        }
        *(float4*)(g_part + (((pool * BATCH) + b) * 4 + chunk) * HDIM + tid * 4) = s;
    }
}

// ---------------- pool phase 3: combine chunks, normalize, tanh ----------------
__global__ __launch_bounds__(256) void pool_p3() {
    int pool = blockIdx.x & 3;
    int b    = blockIdx.x >> 2;
    const int tid = threadIdx.x;
    const int nch = (pool == 0) ? 4 : 1;
    const float* pp = g_part + (((pool * BATCH) + b) * 4) * HDIM + tid;
    float s = 0.f;
    for (int c = 0; c < nch; c++) s += pp[c * HDIM];
    s /= g_msum[1][pool][b];
    s = tanhf(s);
    if (pool >= 2) s = tanhf(s);
    g_pool[pool][b * HDIM + tid] = s;
}

// ---------------- code = tanh([tok, gr] @ Wf + bf); 512 blocks ----------------
__global__ __launch_bounds__(256) void code_kernel(const float* Wf, const float* bfv) {
    int b  = blockIdx.x >> 3;
    int cg = blockIdx.x & 7;
    const int tid = threadIdx.x;
    const int jg = tid >> 5;
    const int ci = tid & 31;
    const int col = cg * 32 + ci;
    __shared__ float cat[2 * HDIM];
    __shared__ float part[256];

    cat[tid]        = g_pool[0][b * HDIM + tid];
    cat[HDIM + tid] = g_pool[1][b * HDIM + tid];
    __syncthreads();

    float acc = 0.f;
    const float* wp = Wf + col;
    const int j0 = jg * 64;
#pragma unroll 8
    for (int j = 0; j < 64; j++)
        acc += cat[j0 + j] * wp[(size_t)(j0 + j) * HDIM];
    part[tid] = acc;
    __syncthreads();
    if (tid < 32) {
        float s = bfv[cg * 32 + tid];
#pragma unroll
        for (int g = 0; g < 8; g++) s += part[g * 32 + tid];
        g_code[b * HDIM + cg * 32 + tid] = tanhf(s);
    }
}

// ---------------- per-batch hinge ----------------
__global__ __launch_bounds__(256) void loss1_kernel() {
    const int b = blockIdx.x;
    const int tid = threadIdx.x;
    const int warp = tid >> 5, lane = tid & 31;
    __shared__ float sm[8][5];

    float c = g_code[b * HDIM + tid];
    float a = g_pool[2][b * HDIM + tid];
    float n = g_pool[3][b * HDIM + tid];
    float s0 = c * c, s1 = a * a, s2 = n * n, s3 = c * a, s4 = c * n;
#pragma unroll
    for (int o = 16; o > 0; o >>= 1) {
        s0 += __shfl_xor_sync(0xffffffffu, s0, o);
        s1 += __shfl_xor_sync(0xffffffffu, s1, o);
        s2 += __shfl_xor_sync(0xffffffffu, s2, o);
        s3 += __shfl_xor_sync(0xffffffffu, s3, o);
        s4 += __shfl_xor_sync(0xffffffffu, s4, o);
    }
    if (lane == 0) {
        sm[warp][0] = s0; sm[warp][1] = s1; sm[warp][2] = s2;
        sm[warp][3] = s3; sm[warp][4] = s4;
    }
    __syncthreads();
    if (tid == 0) {
        float t0 = 0, t1 = 0, t2 = 0, t3 = 0, t4 = 0;
#pragma unroll
        for (int wv = 0; wv < 8; wv++) {
            t0 += sm[wv][0]; t1 += sm[wv][1]; t2 += sm[wv][2];
            t3 += sm[wv][3]; t4 += sm[wv][4];
        }
        float nc = sqrtf(t0);
        float sa = t3 / fmaxf(nc * sqrtf(t1), 1e-8f);
        float sn = t4 / fmaxf(nc * sqrtf(t2), 1e-8f);
        g_hinge[b] = fmaxf(0.6f - sa + sn, 0.f);
    }
}

__global__ void loss2_kernel(float* out) {
    int t = threadIdx.x;
    float v = g_hinge[t] + g_hinge[t + 32];
#pragma unroll
    for (int o = 16; o > 0; o >>= 1) v += __shfl_xor_sync(0xffffffffu, v, o);
    if (t == 0) out[0] = v / (float)BATCH;
}

// ---------------- launch ----------------
extern "C" void kernel_launch(void* const* d_in, const int* in_sizes, int n_in,
                              void* d_out, int out_size) {
    const float* token_feat = (const float*)d_in[0];
    const int*   token_mask = (const int*)d_in[1];
    const float* graph_feat = (const float*)d_in[2];
    const int*   graph_mask = (const int*)d_in[3];
    const float* da_feat    = (const float*)d_in[4];
    const int*   da_mask    = (const int*)d_in[5];
    const float* dn_feat    = (const float*)d_in[6];
    const int*   dn_mask    = (const int*)d_in[7];
    const float* Wt = (const float*)d_in[8];
    const float* bt = (const float*)d_in[9];
    const float* vt = (const float*)d_in[10];
    const float* ct = (const float*)d_in[11];
    const float* Wg = (const float*)d_in[12];
    const float* bg = (const float*)d_in[13];
    const float* vg = (const float*)d_in[14];
    const float* cg = (const float*)d_in[15];
    const float* Wd = (const float*)d_in[16];
    const float* bd = (const float*)d_in[17];
    const float* vd = (const float*)d_in[18];
    const float* cd = (const float*)d_in[19];
    const float* Wf = (const float*)d_in[20];
    const float* bf = (const float*)d_in[21];

    cudaFuncSetAttribute(score_tc, cudaFuncAttributeMaxDynamicSharedMemorySize, SCORE_SMEM);

    float* scores = nullptr;
    __half* wtp = nullptr;
    cudaGetSymbolAddress((void**)&scores, g_scores);
    cudaGetSymbolAddress((void**)&wtp, g_WT);

    float* s_tok = scores;
    float* s_gr  = scores + BATCH * S_TOK;
    float* s_da  = s_gr + BATCH * S_OTH;
    float* s_dn  = s_da + BATCH * S_OTH;

    wconv_kernel<<<dim3(256, 3), 256>>>(Wt, Wg, Wd);

    const int nTok = BATCH * S_TOK / 128;   // 1024
    const int nOth = BATCH * S_OTH / 128;   // 256

    ScoreArgs sa0 = {token_feat, bt, vt, ct, s_tok, 0, 0,               0};
    ScoreArgs sa1 = {graph_feat, bg, vg, cg, s_gr,  1, nTok,            65536};
    ScoreArgs sa2 = {da_feat,    bd, vd, cd, s_da,  0, nTok + nOth,     131072};
    ScoreArgs sa3 = {dn_feat,    bd, vd, cd, s_dn,  0, nTok + 2 * nOth, 131072};
    score_tc<<<nTok + 3 * nOth, 256, SCORE_SMEM>>>(sa0, sa1, sa2, sa3, wtp);

    PoolPtr p0 = {token_feat, token_mask, s_tok, S_TOK, 0, 1};
    PoolPtr p1 = {graph_feat, graph_mask, s_gr,  S_OTH, 1, 1};
    PoolPtr p2 = {da_feat,    da_mask,    s_da,  S_OTH, 0, 2};
    PoolPtr p3 = {dn_feat,    dn_mask,    s_dn,  S_OTH, 0, 2};

    pool_p1<<<4 * BATCH, 256>>>(p0, p1, p2, p3);
    pool_p2<<<448, 512>>>(p0, p1, p2, p3);
    pool_p3<<<4 * BATCH, 256>>>();

    code_kernel<<<8 * BATCH, 256>>>(Wf, bf);
    loss1_kernel<<<BATCH, 256>>>();
    loss2_kernel<<<1, 32>>>((float*)d_out);
}

// round 10
// speedup vs baseline: 4.6069x; 1.0887x over previous
#include <cuda_runtime.h>
#include <cuda_fp16.h>
#include <stdint.h>
#include <math.h>

#define HDIM 256
#define BATCH 64
#define S_TOK 2048
#define S_OTH 512
#define NEGV (-1e9f)

// ---------------- scratch (no allocations allowed) ----------------
__device__ float g_scores[BATCH*S_TOK + 3*BATCH*S_OTH];
__device__ float g_code[BATCH*HDIM];
__device__ float g_hinge[BATCH];
__device__ float g_msum[2][4][BATCH];            // [0]=max, [1]=expsum
__device__ float g_part[4*BATCH*8*HDIM];         // [pool][b][chunk<8][col]
__device__ __half g_WT[3 * 65536];               // W transposed fp16: [mat][n*256+k]

// ---------------- PTX helpers ----------------
__device__ __forceinline__ uint32_t smem_to_u32(const void* p) {
    uint32_t a;
    asm("{ .reg .u64 tmp; cvta.to.shared.u64 tmp, %1; cvt.u32.u64 %0, tmp; }" : "=r"(a) : "l"(p));
    return a;
}
__device__ __forceinline__ float tanh_fast(float x) {
    float y;
    asm("tanh.approx.f32 %0, %1;" : "=f"(y) : "f"(x));
    return y;
}
#define LDSM_X4(r0,r1,r2,r3,addr) \
    asm volatile("ldmatrix.sync.aligned.m8n8.x4.shared.b16 {%0,%1,%2,%3}, [%4];" \
        : "=r"(r0),"=r"(r1),"=r"(r2),"=r"(r3) : "r"(addr))
#define MMA_F16(c, a, b) \
    asm volatile("mma.sync.aligned.m16n8k16.row.col.f32.f16.f16.f32 " \
        "{%0,%1,%2,%3},{%4,%5,%6,%7},{%8,%9},{%0,%1,%2,%3};" \
        : "+f"((c)[0]),"+f"((c)[1]),"+f"((c)[2]),"+f"((c)[3]) \
        : "r"((a)[0]),"r"((a)[1]),"r"((a)[2]),"r"((a)[3]),"r"((b)[0]),"r"((b)[1]))
#define CP_ASYNC16(dst, src) \
    asm volatile("cp.async.cg.shared.global [%0], [%1], 16;" :: "r"(dst), "l"(src) : "memory")
#define CP_COMMIT() asm volatile("cp.async.commit_group;" ::: "memory")
#define CP_WAIT(n)  asm volatile("cp.async.wait_group %0;" :: "n"(n) : "memory")

// ---------------- W transpose to fp16 ----------------
__global__ void wconv_kernel(const float* Wt, const float* Wg, const float* Wd) {
    int mat = blockIdx.y;
    const float* W = (mat == 0) ? Wt : (mat == 1) ? Wg : Wd;
    int k = blockIdx.x, n = threadIdx.x;
    g_WT[mat * 65536 + n * 256 + k] = __float2half_rn(W[k * 256 + n]);
}

// ---------------- score kernel: fp16 mma, A register-pipelined by K-chunk ----------------
#define A_ST 264
#define WB_ST 528
#define SA_OFF 0
#define SW_OFF 67584
#define SW_CHN 67584
#define SBIAS 202752
#define SVV   203776
#define SPART 204800
#define SCORE_SMEM 205824

struct ScoreArgs {
    const float* feat;
    const float* bv;
    const float* v;
    const float* c;
    float* sout;
    int pretanh;
    int blkStart;
    int wtOff;
};

__device__ __forceinline__ void convert_sts_chunk(char* smem, const float4* av,
                                                  int r, int cbase, int pt) {
#pragma unroll
    for (int j = 0; j < 8; j++) {
        float4 t = av[j];
        if (pt) {
            t.x = tanh_fast(t.x); t.y = tanh_fast(t.y);
            t.z = tanh_fast(t.z); t.w = tanh_fast(t.w);
        }
        __half2 h0 = __float22half2_rn(make_float2(t.x, t.y));
        __half2 h1 = __float22half2_rn(make_float2(t.z, t.w));
        uint2 hu;
        hu.x = *(uint32_t*)&h0; hu.y = *(uint32_t*)&h1;
        *(uint2*)(smem + SA_OFF + (size_t)(r * A_ST + cbase + j * 4) * 2) = hu;
    }
}

__global__ __launch_bounds__(256, 1) void score_tc(ScoreArgs A0, ScoreArgs A1,
                                                   ScoreArgs A2, ScoreArgs A3,
                                                   const __half* WTg) {
    ScoreArgs A;
    int blk = blockIdx.x;
    if (blk >= A3.blkStart)      A = A3;
    else if (blk >= A2.blkStart) A = A2;
    else if (blk >= A1.blkStart) A = A1;
    else                         A = A0;
    const int row0 = (blk - A.blkStart) * 128;

    extern __shared__ char smem[];
    const uint32_t sbase = smem_to_u32(smem);
    float* sBias = (float*)(smem + SBIAS);
    float* sV    = (float*)(smem + SVV);
    float* sPart = (float*)(smem + SPART);

    const int tid  = threadIdx.x;
    const int warp = tid >> 5;
    const int lane = tid & 31;
    const int wm = warp & 3;
    const int wn = warp >> 2;
    const int tq = lane & 3;
    const int gp = lane >> 2;

    const __half* WT = WTg + A.wtOff;
    const int pt = A.pretanh;

#pragma unroll
    for (int hf = 0; hf < 2; hf++) {
        for (int i = tid; i < 4096; i += 256) {
            int r = i >> 5, j = i & 31;
            const __half* src = WT + (size_t)(hf * 128 + r) * 256 + j * 8;
            uint32_t dst = sbase + SW_OFF + hf * SW_CHN + (uint32_t)(r * WB_ST + j * 16);
            CP_ASYNC16(dst, src);
        }
        CP_COMMIT();
    }

    sBias[tid] = A.bv[tid];
    sV[tid]    = A.v[tid];
    if (tid < 128) { sPart[tid * 2] = 0.f; sPart[tid * 2 + 1] = 0.f; }

    const int ar = tid >> 1;
    const int ac = (tid & 1) * 32;
    const float* arow = A.feat + (size_t)(row0 + ar) * HDIM + ac;

    {
        float4 av[8];
#pragma unroll
        for (int j = 0; j < 8; j++) av[j] = ((const float4*)arow)[j];
        convert_sts_chunk(smem, av, ar, ac, pt);
    }

    CP_WAIT(1);
    __syncthreads();

    const uint32_t aBase = sbase + SA_OFF;
    const uint32_t aLaneOff = (uint32_t)(((wm * 32 + (lane & 15)) * A_ST + ((lane >> 4) << 3)) * 2);
    const uint32_t bLane = (uint32_t)(((lane & 7) + ((lane >> 4) << 3)) * WB_ST + (((lane >> 3) & 1) << 4));

    float acc[2][8][4];

    // ---------------- half 0: MMA pipelined with A chunk streaming ----------------
#pragma unroll
    for (int mi = 0; mi < 2; mi++)
#pragma unroll
        for (int nj = 0; nj < 8; nj++) {
            acc[mi][nj][0] = 0.f; acc[mi][nj][1] = 0.f;
            acc[mi][nj][2] = 0.f; acc[mi][nj][3] = 0.f;
        }
    {
        const uint32_t wbBase = sbase + SW_OFF + bLane;
        for (int kc = 0; kc < 4; kc++) {
            float4 av[8];
            if (kc < 3) {
                const float4* src = (const float4*)(arow + (kc + 1) * 64);
#pragma unroll
                for (int j = 0; j < 8; j++) av[j] = src[j];
            }
#pragma unroll
            for (int ks = 0; ks < 4; ks++) {
                const uint32_t kOffA = (uint32_t)((kc * 64 + ks * 16) * 2);
                const int ksab = kc * 4 + ks;
                uint32_t aF[2][4];
#pragma unroll
                for (int mi = 0; mi < 2; mi++) {
                    uint32_t ad = aLaneOff + (uint32_t)(mi * 16 * A_ST * 2) + kOffA;
                    LDSM_X4(aF[mi][0], aF[mi][1], aF[mi][2], aF[mi][3], aBase + ad);
                }
                uint32_t bF[8][2];
#pragma unroll
                for (int nb = 0; nb < 4; nb++) {
                    uint32_t bd = (uint32_t)((wn * 64 + nb * 16) * WB_ST + ksab * 32);
                    uint32_t r0, r1, r2, r3;
                    LDSM_X4(r0, r1, r2, r3, wbBase + bd);
                    bF[2*nb][0] = r0; bF[2*nb][1] = r1;
                    bF[2*nb+1][0] = r2; bF[2*nb+1][1] = r3;
                }
#pragma unroll
                for (int mi = 0; mi < 2; mi++)
#pragma unroll
                    for (int nj = 0; nj < 8; nj++)
                        MMA_F16(acc[mi][nj], aF[mi], bF[nj]);
            }
            if (kc < 3) {
                convert_sts_chunk(smem, av, ar, (kc + 1) * 64 + ac, pt);
                __syncthreads();
            }
        }
    }
#pragma unroll
    for (int mi = 0; mi < 2; mi++) {
        float p0 = 0.f, p1 = 0.f;
#pragma unroll
        for (int nj = 0; nj < 8; nj++) {
            int col = wn * 64 + nj * 8 + tq * 2;
            float b0 = sBias[col], b1 = sBias[col + 1];
            float v0 = sV[col],    v1 = sV[col + 1];
            p0 += tanh_fast(acc[mi][nj][0] + b0) * v0 + tanh_fast(acc[mi][nj][1] + b1) * v1;
            p1 += tanh_fast(acc[mi][nj][2] + b0) * v0 + tanh_fast(acc[mi][nj][3] + b1) * v1;
        }
        p0 += __shfl_xor_sync(0xffffffffu, p0, 1);
        p0 += __shfl_xor_sync(0xffffffffu, p0, 2);
        p1 += __shfl_xor_sync(0xffffffffu, p1, 1);
        p1 += __shfl_xor_sync(0xffffffffu, p1, 2);
        if (tq == 0) {
            int r0 = wm * 32 + mi * 16 + gp;
            sPart[r0 * 2 + wn]       += p0;
            sPart[(r0 + 8) * 2 + wn] += p1;
        }
    }

    // ---------------- half 1: A fully resident ----------------
    CP_WAIT(0);
    __syncthreads();
#pragma unroll
    for (int mi = 0; mi < 2; mi++)
#pragma unroll
        for (int nj = 0; nj < 8; nj++) {
            acc[mi][nj][0] = 0.f; acc[mi][nj][1] = 0.f;
            acc[mi][nj][2] = 0.f; acc[mi][nj][3] = 0.f;
        }
    {
        const uint32_t wbBase = sbase + SW_OFF + SW_CHN + bLane;
#pragma unroll
        for (int ks = 0; ks < 16; ks++) {
            const uint32_t kOffA = (uint32_t)(ks * 32);
            uint32_t aF[2][4];
#pragma unroll
            for (int mi = 0; mi < 2; mi++) {
                uint32_t ad = aLaneOff + (uint32_t)(mi * 16 * A_ST * 2) + kOffA;
                LDSM_X4(aF[mi][0], aF[mi][1], aF[mi][2], aF[mi][3], aBase + ad);
            }
            uint32_t bF[8][2];
#pragma unroll
            for (int nb = 0; nb < 4; nb++) {
                uint32_t bd = (uint32_t)((wn * 64 + nb * 16) * WB_ST + ks * 32);
                uint32_t r0, r1, r2, r3;
                LDSM_X4(r0, r1, r2, r3, wbBase + bd);
                bF[2*nb][0] = r0; bF[2*nb][1] = r1;
                bF[2*nb+1][0] = r2; bF[2*nb+1][1] = r3;
            }
#pragma unroll
            for (int mi = 0; mi < 2; mi++)
#pragma unroll
                for (int nj = 0; nj < 8; nj++)
                    MMA_F16(acc[mi][nj], aF[mi], bF[nj]);
        }
    }
#pragma unroll
    for (int mi = 0; mi < 2; mi++) {
        float p0 = 0.f, p1 = 0.f;
#pragma unroll
        for (int nj = 0; nj < 8; nj++) {
            int col = 128 + wn * 64 + nj * 8 + tq * 2;
            float b0 = sBias[col], b1 = sBias[col + 1];
            float v0 = sV[col],    v1 = sV[col + 1];
            p0 += tanh_fast(acc[mi][nj][0] + b0) * v0 + tanh_fast(acc[mi][nj][1] + b1) * v1;
            p1 += tanh_fast(acc[mi][nj][2] + b0) * v0 + tanh_fast(acc[mi][nj][3] + b1) * v1;
        }
        p0 += __shfl_xor_sync(0xffffffffu, p0, 1);
        p0 += __shfl_xor_sync(0xffffffffu, p0, 2);
        p1 += __shfl_xor_sync(0xffffffffu, p1, 1);
        p1 += __shfl_xor_sync(0xffffffffu, p1, 2);
        if (tq == 0) {
            int r0 = wm * 32 + mi * 16 + gp;
            sPart[r0 * 2 + wn]       += p0;
            sPart[(r0 + 8) * 2 + wn] += p1;
        }
    }

    __syncthreads();
    if (tid < 128)
        A.sout[row0 + tid] = sPart[tid * 2] + sPart[tid * 2 + 1] + A.c[0];
}

// ---------------- pool phase 1: masked max + expsum per (pool, b) ----------------
struct PoolPtr {
    const float* feat;
    const int* mask;
    const float* scores;
    int S;
    int pretanh;
    int posttanh;
};

__global__ __launch_bounds__(256) void pool_p1(PoolPtr P0, PoolPtr P1, PoolPtr P2, PoolPtr P3) {
    int pool = blockIdx.x & 3;
    int b    = blockIdx.x >> 2;
    PoolPtr P = (pool == 0) ? P0 : (pool == 1) ? P1 : (pool == 2) ? P2 : P3;
    __shared__ float red[256];
    const int tid = threadIdx.x;
    const int S = P.S;
    const float* sc = P.scores + (size_t)b * S;
    const int* mk = P.mask + (size_t)b * S;

    float m = -3.4e38f;
    for (int s = tid; s < S; s += 256)
        m = fmaxf(m, mk[s] ? sc[s] : NEGV);
    red[tid] = m;
    __syncthreads();
    for (int st = 128; st > 0; st >>= 1) {
        if (tid < st) red[tid] = fmaxf(red[tid], red[tid + st]);
        __syncthreads();
    }
    m = red[0];
    __syncthreads();

    float e = 0.f;
    for (int s = tid; s < S; s += 256)
        e += mk[s] ? __expf(sc[s] - m) : 0.f;
    red[tid] = e;
    __syncthreads();
    for (int st = 128; st > 0; st >>= 1) {
        if (tid < st) red[tid] += red[tid + st];
        __syncthreads();
    }
    if (tid == 0) {
        g_msum[0][pool][b] = m;
        g_msum[1][pool][b] = red[0];
    }
}

// ---------------- pool phase 2: 256-position chunks, float4 per thread ----------------
// blocks 0..511: token (b=blk>>3, chunk=blk&7)
// blocks 512..895: pool 1+r/128, r%128: b=(r%128)>>1, chunk=r&1
__global__ __launch_bounds__(512) void pool_p2(PoolPtr P0, PoolPtr P1, PoolPtr P2, PoolPtr P3) {
    int blk = blockIdx.x;
    int pool, b, chunk;
    if (blk < 512) { pool = 0; b = blk >> 3; chunk = blk & 7; }
    else { int r = blk - 512; pool = 1 + (r >> 7); int wi = r & 127; b = wi >> 1; chunk = wi & 1; }
    PoolPtr P = (pool == 0) ? P0 : (pool == 1) ? P1 : (pool == 2) ? P2 : P3;

    __shared__ float w[256];
    __shared__ float4 red4[512];
    const int tid = threadIdx.x;
    const int s0 = chunk * 256;
    const float m = g_msum[0][pool][b];

    if (tid < 256) {
        const float* sc = P.scores + (size_t)b * P.S + s0;
        const int* mk = P.mask + (size_t)b * P.S + s0;
        w[tid] = mk[tid] ? __expf(sc[tid] - m) : 0.f;
    }
    __syncthreads();

    const int col4 = (tid & 63) * 4;
    const int stripe = tid >> 6;          // 8 s-stripes
    const float4* f = (const float4*)(P.feat + (size_t)b * P.S * HDIM + (size_t)s0 * HDIM + col4);
    float4 acc = make_float4(0.f, 0.f, 0.f, 0.f);
    if (P.pretanh) {
        for (int s = stripe; s < 256; s += 8) {
            float ws = w[s];
            float4 t = f[(size_t)s * (HDIM / 4)];
            acc.x += ws * tanh_fast(t.x); acc.y += ws * tanh_fast(t.y);
            acc.z += ws * tanh_fast(t.z); acc.w += ws * tanh_fast(t.w);
        }
    } else {
#pragma unroll 8
        for (int s = stripe; s < 256; s += 8) {
            float ws = w[s];
            float4 t = f[(size_t)s * (HDIM / 4)];
            acc.x += ws * t.x; acc.y += ws * t.y;
            acc.z += ws * t.z; acc.w += ws * t.w;
        }
    }
    red4[tid] = acc;
    __syncthreads();
    if (tid < 64) {
        float4 s = red4[tid];
#pragma unroll
        for (int g = 1; g < 8; g++) {
            float4 t = red4[tid + g * 64];
            s.x += t.x; s.y += t.y; s.z += t.z; s.w += t.w;
        }
        *(float4*)(g_part + (((pool * BATCH) + b) * 8 + chunk) * HDIM + tid * 4) = s;
    }
}

// ---------------- pooled value from g_part (inline combine) ----------------
__device__ __forceinline__ float pooled_val(int pool, int b, int col, int nch) {
    const float* pp = g_part + (((pool * BATCH) + b) * 8) * HDIM + col;
    float s = 0.f;
#pragma unroll 8
    for (int c = 0; c < nch; c++) s += pp[c * HDIM];
    return s / g_msum[1][pool][b];
}

// ---------------- code = tanh([tok, gr] @ Wf + bf); 512 blocks; folds p3 ----------------
__global__ __launch_bounds__(256) void code_kernel(const float* Wf, const float* bfv) {
    int b  = blockIdx.x >> 3;
    int cg = blockIdx.x & 7;
    const int tid = threadIdx.x;
    const int jg = tid >> 5;
    const int ci = tid & 31;
    const int col = cg * 32 + ci;
    __shared__ float cat[2 * HDIM];
    __shared__ float part[256];

    cat[tid]        = tanh_fast(pooled_val(0, b, tid, 8));
    cat[HDIM + tid] = tanh_fast(pooled_val(1, b, tid, 2));
    __syncthreads();

    float acc = 0.f;
    const float* wp = Wf + col;
    const int j0 = jg * 64;
#pragma unroll 8
    for (int j = 0; j < 64; j++)
        acc += cat[j0 + j] * wp[(size_t)(j0 + j) * HDIM];
    part[tid] = acc;
    __syncthreads();
    if (tid < 32) {
        float s = bfv[cg * 32 + tid];
#pragma unroll
        for (int g = 0; g < 8; g++) s += part[g * 32 + tid];
        g_code[b * HDIM + cg * 32 + tid] = tanh_fast(s);
    }
}

// ---------------- per-batch hinge; folds p3 for desc pools ----------------
__global__ __launch_bounds__(256) void loss1_kernel() {
    const int b = blockIdx.x;
    const int tid = threadIdx.x;
    const int warp = tid >> 5, lane = tid & 31;
    __shared__ float sm[8][5];

    float c = g_code[b * HDIM + tid];
    float a = tanh_fast(tanh_fast(pooled_val(2, b, tid, 2)));
    float n = tanh_fast(tanh_fast(pooled_val(3, b, tid, 2)));
    float s0 = c * c, s1 = a * a, s2 = n * n, s3 = c * a, s4 = c * n;
#pragma unroll
    for (int o = 16; o > 0; o >>= 1) {
        s0 += __shfl_xor_sync(0xffffffffu, s0, o);
        s1 += __shfl_xor_sync(0xffffffffu, s1, o);
        s2 += __shfl_xor_sync(0xffffffffu, s2, o);
        s3 += __shfl_xor_sync(0xffffffffu, s3, o);
        s4 += __shfl_xor_sync(0xffffffffu, s4, o);
    }
    if (lane == 0) {
        sm[warp][0] = s0; sm[warp][1] = s1; sm[warp][2] = s2;
        sm[warp][3] = s3; sm[warp][4] = s4;
    }
    __syncthreads();
    if (tid == 0) {
        float t0 = 0, t1 = 0, t2 = 0, t3 = 0, t4 = 0;
#pragma unroll
        for (int wv = 0; wv < 8; wv++) {
            t0 += sm[wv][0]; t1 += sm[wv][1]; t2 += sm[wv][2];
            t3 += sm[wv][3]; t4 += sm[wv][4];
        }
        float nc = sqrtf(t0);
        float sa = t3 / fmaxf(nc * sqrtf(t1), 1e-8f);
        float sn = t4 / fmaxf(nc * sqrtf(t2), 1e-8f);
        g_hinge[b] = fmaxf(0.6f - sa + sn, 0.f);
    }
}

__global__ void loss2_kernel(float* out) {
    int t = threadIdx.x;
    float v = g_hinge[t] + g_hinge[t + 32];
#pragma unroll
    for (int o = 16; o > 0; o >>= 1) v += __shfl_xor_sync(0xffffffffu, v, o);
    if (t == 0) out[0] = v / (float)BATCH;
}

// ---------------- launch ----------------
extern "C" void kernel_launch(void* const* d_in, const int* in_sizes, int n_in,
                              void* d_out, int out_size) {
    const float* token_feat = (const float*)d_in[0];
    const int*   token_mask = (const int*)d_in[1];
    const float* graph_feat = (const float*)d_in[2];
    const int*   graph_mask = (const int*)d_in[3];
    const float* da_feat    = (const float*)d_in[4];
    const int*   da_mask    = (const int*)d_in[5];
    const float* dn_feat    = (const float*)d_in[6];
    const int*   dn_mask    = (const int*)d_in[7];
    const float* Wt = (const float*)d_in[8];
    const float* bt = (const float*)d_in[9];
    const float* vt = (const float*)d_in[10];
    const float* ct = (const float*)d_in[11];
    const float* Wg = (const float*)d_in[12];
    const float* bg = (const float*)d_in[13];
    const float* vg = (const float*)d_in[14];
    const float* cg = (const float*)d_in[15];
    const float* Wd = (const float*)d_in[16];
    const float* bd = (const float*)d_in[17];
    const float* vd = (const float*)d_in[18];
    const float* cd = (const float*)d_in[19];
    const float* Wf = (const float*)d_in[20];
    const float* bf = (const float*)d_in[21];

    cudaFuncSetAttribute(score_tc, cudaFuncAttributeMaxDynamicSharedMemorySize, SCORE_SMEM);

    float* scores = nullptr;
    __half* wtp = nullptr;
    cudaGetSymbolAddress((void**)&scores, g_scores);
    cudaGetSymbolAddress((void**)&wtp, g_WT);

    float* s_tok = scores;
    float* s_gr  = scores + BATCH * S_TOK;
    float* s_da  = s_gr + BATCH * S_OTH;
    float* s_dn  = s_da + BATCH * S_OTH;

    wconv_kernel<<<dim3(256, 3), 256>>>(Wt, Wg, Wd);

    const int nTok = BATCH * S_TOK / 128;   // 1024
    const int nOth = BATCH * S_OTH / 128;   // 256

    ScoreArgs sa0 = {token_feat, bt, vt, ct, s_tok, 0, 0,               0};
    ScoreArgs sa1 = {graph_feat, bg, vg, cg, s_gr,  1, nTok,            65536};
    ScoreArgs sa2 = {da_feat,    bd, vd, cd, s_da,  0, nTok + nOth,     131072};
    ScoreArgs sa3 = {dn_feat,    bd, vd, cd, s_dn,  0, nTok + 2 * nOth, 131072};
    score_tc<<<nTok + 3 * nOth, 256, SCORE_SMEM>>>(sa0, sa1, sa2, sa3, wtp);

    PoolPtr p0 = {token_feat, token_mask, s_tok, S_TOK, 0, 1};
    PoolPtr p1 = {graph_feat, graph_mask, s_gr,  S_OTH, 1, 1};
    PoolPtr p2 = {da_feat,    da_mask,    s_da,  S_OTH, 0, 2};
    PoolPtr p3 = {dn_feat,    dn_mask,    s_dn,  S_OTH, 0, 2};

    pool_p1<<<4 * BATCH, 256>>>(p0, p1, p2, p3);
    pool_p2<<<896, 512>>>(p0, p1, p2, p3);

    code_kernel<<<8 * BATCH, 256>>>(Wf, bf);
    loss1_kernel<<<BATCH, 256>>>();
    loss2_kernel<<<1, 32>>>((float*)d_out);
}

// round 11
// speedup vs baseline: 5.0539x; 1.0970x over previous
#include <cuda_runtime.h>
#include <cuda_fp16.h>
#include <stdint.h>
#include <math.h>

#define HDIM 256
#define BATCH 64
#define S_TOK 2048
#define S_OTH 512
#define NEGV (-1e9f)

// ---------------- scratch (no allocations allowed) ----------------
__device__ float g_code[BATCH*HDIM];
__device__ float g_hinge[BATCH];
__device__ float g_pmax[4][BATCH][16];
__device__ float g_pesum[4][BATCH][16];
__device__ float g_psum[4*BATCH*16*HDIM];        // [pool][b][chunk][col]
__device__ __half g_WT[3 * 65536];               // W transposed fp16: [mat][n*256+k]

// ---------------- PTX helpers ----------------
__device__ __forceinline__ uint32_t smem_to_u32(const void* p) {
    uint32_t a;
    asm("{ .reg .u64 tmp; cvta.to.shared.u64 tmp, %1; cvt.u32.u64 %0, tmp; }" : "=r"(a) : "l"(p));
    return a;
}
__device__ __forceinline__ float tanh_fast(float x) {
    float y;
    asm("tanh.approx.f32 %0, %1;" : "=f"(y) : "f"(x));
    return y;
}
#define LDSM_X4(r0,r1,r2,r3,addr) \
    asm volatile("ldmatrix.sync.aligned.m8n8.x4.shared.b16 {%0,%1,%2,%3}, [%4];" \
        : "=r"(r0),"=r"(r1),"=r"(r2),"=r"(r3) : "r"(addr))
#define MMA_F16(c, a, b) \
    asm volatile("mma.sync.aligned.m16n8k16.row.col.f32.f16.f16.f32 " \
        "{%0,%1,%2,%3},{%4,%5,%6,%7},{%8,%9},{%0,%1,%2,%3};" \
        : "+f"((c)[0]),"+f"((c)[1]),"+f"((c)[2]),"+f"((c)[3]) \
        : "r"((a)[0]),"r"((a)[1]),"r"((a)[2]),"r"((a)[3]),"r"((b)[0]),"r"((b)[1]))
#define CP_ASYNC16(dst, src) \
    asm volatile("cp.async.cg.shared.global [%0], [%1], 16;" :: "r"(dst), "l"(src) : "memory")
#define CP_COMMIT() asm volatile("cp.async.commit_group;" ::: "memory")
#define CP_WAIT(n)  asm volatile("cp.async.wait_group %0;" :: "n"(n) : "memory")

// ---------------- W transpose to fp16 ----------------
__global__ void wconv_kernel(const float* Wt, const float* Wg, const float* Wd) {
    int mat = blockIdx.y;
    const float* W = (mat == 0) ? Wt : (mat == 1) ? Wg : Wd;
    int k = blockIdx.x, n = threadIdx.x;
    g_WT[mat * 65536 + n * 256 + k] = __float2half_rn(W[k * 256 + n]);
}

// ---------------- fused score + softmax-pool kernel ----------------
#define A_ST 264
#define WB_ST 528
#define SA_OFF 0
#define SW_OFF 67584
#define SW_CHN 67584
#define SBIAS 202752
#define SVV   203776
#define SPART 204800
#define SRED  205824          // 512 floats (2048 B)
#define SCORE_SMEM 207872

struct ScoreArgs {
    const float* feat;
    const int* mask;
    const float* bv;
    const float* v;
    const float* c;
    int pretanh;
    int blkStart;
    int wtOff;
    int pool;
    int S;
};

__device__ __forceinline__ void convert_sts_chunk(char* smem, const float4* av,
                                                  int r, int cbase, int pt) {
#pragma unroll
    for (int j = 0; j < 8; j++) {
        float4 t = av[j];
        if (pt) {
            t.x = tanh_fast(t.x); t.y = tanh_fast(t.y);
            t.z = tanh_fast(t.z); t.w = tanh_fast(t.w);
        }
        __half2 h0 = __float22half2_rn(make_float2(t.x, t.y));
        __half2 h1 = __float22half2_rn(make_float2(t.z, t.w));
        uint2 hu;
        hu.x = *(uint32_t*)&h0; hu.y = *(uint32_t*)&h1;
        *(uint2*)(smem + SA_OFF + (size_t)(r * A_ST + cbase + j * 4) * 2) = hu;
    }
}

__global__ __launch_bounds__(256, 1) void score_tc(ScoreArgs A0, ScoreArgs A1,
                                                   ScoreArgs A2, ScoreArgs A3,
                                                   const __half* WTg) {
    ScoreArgs A;
    int blk = blockIdx.x;
    if (blk >= A3.blkStart)      A = A3;
    else if (blk >= A2.blkStart) A = A2;
    else if (blk >= A1.blkStart) A = A1;
    else                         A = A0;
    const int row0 = (blk - A.blkStart) * 128;

    extern __shared__ char smem[];
    const uint32_t sbase = smem_to_u32(smem);
    float* sBias = (float*)(smem + SBIAS);
    float* sV    = (float*)(smem + SVV);
    float* sPart = (float*)(smem + SPART);

    const int tid  = threadIdx.x;
    const int warp = tid >> 5;
    const int lane = tid & 31;
    const int wm = warp & 3;
    const int wn = warp >> 2;
    const int tq = lane & 3;
    const int gp = lane >> 2;

    const __half* WT = WTg + A.wtOff;
    const int pt = A.pretanh;

#pragma unroll
    for (int hf = 0; hf < 2; hf++) {
        for (int i = tid; i < 4096; i += 256) {
            int r = i >> 5, j = i & 31;
            const __half* src = WT + (size_t)(hf * 128 + r) * 256 + j * 8;
            uint32_t dst = sbase + SW_OFF + hf * SW_CHN + (uint32_t)(r * WB_ST + j * 16);
            CP_ASYNC16(dst, src);
        }
        CP_COMMIT();
    }

    sBias[tid] = A.bv[tid];
    sV[tid]    = A.v[tid];
    if (tid < 128) { sPart[tid * 2] = 0.f; sPart[tid * 2 + 1] = 0.f; }

    const int ar = tid >> 1;
    const int ac = (tid & 1) * 32;
    const float* arow = A.feat + (size_t)(row0 + ar) * HDIM + ac;

    {
        float4 av[8];
#pragma unroll
        for (int j = 0; j < 8; j++) av[j] = ((const float4*)arow)[j];
        convert_sts_chunk(smem, av, ar, ac, pt);
    }

    CP_WAIT(1);
    __syncthreads();

    const uint32_t aBase = sbase + SA_OFF;
    const uint32_t aLaneOff = (uint32_t)(((wm * 32 + (lane & 15)) * A_ST + ((lane >> 4) << 3)) * 2);
    const uint32_t bLane = (uint32_t)(((lane & 7) + ((lane >> 4) << 3)) * WB_ST + (((lane >> 3) & 1) << 4));

    float acc[2][8][4];

    // ---------------- half 0: MMA pipelined with A chunk streaming ----------------
#pragma unroll
    for (int mi = 0; mi < 2; mi++)
#pragma unroll
        for (int nj = 0; nj < 8; nj++) {
            acc[mi][nj][0] = 0.f; acc[mi][nj][1] = 0.f;
            acc[mi][nj][2] = 0.f; acc[mi][nj][3] = 0.f;
        }
    {
        const uint32_t wbBase = sbase + SW_OFF + bLane;
        for (int kc = 0; kc < 4; kc++) {
            float4 av[8];
            if (kc < 3) {
                const float4* src = (const float4*)(arow + (kc + 1) * 64);
#pragma unroll
                for (int j = 0; j < 8; j++) av[j] = src[j];
            }
#pragma unroll
            for (int ks = 0; ks < 4; ks++) {
                const uint32_t kOffA = (uint32_t)((kc * 64 + ks * 16) * 2);
                const int ksab = kc * 4 + ks;
                uint32_t aF[2][4];
#pragma unroll
                for (int mi = 0; mi < 2; mi++) {
                    uint32_t ad = aLaneOff + (uint32_t)(mi * 16 * A_ST * 2) + kOffA;
                    LDSM_X4(aF[mi][0], aF[mi][1], aF[mi][2], aF[mi][3], aBase + ad);
                }
                uint32_t bF[8][2];
#pragma unroll
                for (int nb = 0; nb < 4; nb++) {
                    uint32_t bd = (uint32_t)((wn * 64 + nb * 16) * WB_ST + ksab * 32);
                    uint32_t r0, r1, r2, r3;
                    LDSM_X4(r0, r1, r2, r3, wbBase + bd);
                    bF[2*nb][0] = r0; bF[2*nb][1] = r1;
                    bF[2*nb+1][0] = r2; bF[2*nb+1][1] = r3;
                }
#pragma unroll
                for (int mi = 0; mi < 2; mi++)
#pragma unroll
                    for (int nj = 0; nj < 8; nj++)
                        MMA_F16(acc[mi][nj], aF[mi], bF[nj]);
            }
            if (kc < 3) {
                convert_sts_chunk(smem, av, ar, (kc + 1) * 64 + ac, pt);
                __syncthreads();
            }
        }
    }
#pragma unroll
    for (int mi = 0; mi < 2; mi++) {
        float p0 = 0.f, p1 = 0.f;
#pragma unroll
        for (int nj = 0; nj < 8; nj++) {
            int col = wn * 64 + nj * 8 + tq * 2;
            float b0 = sBias[col], b1 = sBias[col + 1];
            float v0 = sV[col],    v1 = sV[col + 1];
            p0 += tanh_fast(acc[mi][nj][0] + b0) * v0 + tanh_fast(acc[mi][nj][1] + b1) * v1;
            p1 += tanh_fast(acc[mi][nj][2] + b0) * v0 + tanh_fast(acc[mi][nj][3] + b1) * v1;
        }
        p0 += __shfl_xor_sync(0xffffffffu, p0, 1);
        p0 += __shfl_xor_sync(0xffffffffu, p0, 2);
        p1 += __shfl_xor_sync(0xffffffffu, p1, 1);
        p1 += __shfl_xor_sync(0xffffffffu, p1, 2);
        if (tq == 0) {
            int r0 = wm * 32 + mi * 16 + gp;
            sPart[r0 * 2 + wn]       += p0;
            sPart[(r0 + 8) * 2 + wn] += p1;
        }
    }

    // ---------------- half 1: A fully resident ----------------
    CP_WAIT(0);
    __syncthreads();
#pragma unroll
    for (int mi = 0; mi < 2; mi++)
#pragma unroll
        for (int nj = 0; nj < 8; nj++) {
            acc[mi][nj][0] = 0.f; acc[mi][nj][1] = 0.f;
            acc[mi][nj][2] = 0.f; acc[mi][nj][3] = 0.f;
        }
    {
        const uint32_t wbBase = sbase + SW_OFF + SW_CHN + bLane;
#pragma unroll
        for (int ks = 0; ks < 16; ks++) {
            const uint32_t kOffA = (uint32_t)(ks * 32);
            uint32_t aF[2][4];
#pragma unroll
            for (int mi = 0; mi < 2; mi++) {
                uint32_t ad = aLaneOff + (uint32_t)(mi * 16 * A_ST * 2) + kOffA;
                LDSM_X4(aF[mi][0], aF[mi][1], aF[mi][2], aF[mi][3], aBase + ad);
            }
            uint32_t bF[8][2];
#pragma unroll
            for (int nb = 0; nb < 4; nb++) {
                uint32_t bd = (uint32_t)((wn * 64 + nb * 16) * WB_ST + ks * 32);
                uint32_t r0, r1, r2, r3;
                LDSM_X4(r0, r1, r2, r3, wbBase + bd);
                bF[2*nb][0] = r0; bF[2*nb][1] = r1;
                bF[2*nb+1][0] = r2; bF[2*nb+1][1] = r3;
            }
#pragma unroll
            for (int mi = 0; mi < 2; mi++)
#pragma unroll
                for (int nj = 0; nj < 8; nj++)
                    MMA_F16(acc[mi][nj], aF[mi], bF[nj]);
        }
    }
#pragma unroll
    for (int mi = 0; mi < 2; mi++) {
        float p0 = 0.f, p1 = 0.f;
#pragma unroll
        for (int nj = 0; nj < 8; nj++) {
            int col = 128 + wn * 64 + nj * 8 + tq * 2;
            float b0 = sBias[col], b1 = sBias[col + 1];
            float v0 = sV[col],    v1 = sV[col + 1];
            p0 += tanh_fast(acc[mi][nj][0] + b0) * v0 + tanh_fast(acc[mi][nj][1] + b1) * v1;
            p1 += tanh_fast(acc[mi][nj][2] + b0) * v0 + tanh_fast(acc[mi][nj][3] + b1) * v1;
        }
        p0 += __shfl_xor_sync(0xffffffffu, p0, 1);
        p0 += __shfl_xor_sync(0xffffffffu, p0, 2);
        p1 += __shfl_xor_sync(0xffffffffu, p1, 1);
        p1 += __shfl_xor_sync(0xffffffffu, p1, 2);
        if (tq == 0) {
            int r0 = wm * 32 + mi * 16 + gp;
            sPart[r0 * 2 + wn]       += p0;
            sPart[(r0 + 8) * 2 + wn] += p1;
        }
    }
    __syncthreads();

    // ---------------- fused softmax-pool over this 128-row chunk ----------------
    float* sSc   = sBias;               // reuse: 128 weights/scores
    float* sRedS = sV;                  // reuse: reduce scratch
    if (tid < 128) {
        float s = sPart[tid * 2] + sPart[tid * 2 + 1] + A.c[0];
        int msk = A.mask[row0 + tid];
        sSc[tid] = msk ? s : NEGV;
    }
    __syncthreads();
    if (tid < 64) sRedS[tid] = fmaxf(sSc[tid], sSc[tid + 64]);
    __syncthreads();
    if (tid < 32) {
        float m = fmaxf(sRedS[tid], sRedS[tid + 32]);
#pragma unroll
        for (int o = 16; o > 0; o >>= 1) m = fmaxf(m, __shfl_xor_sync(0xffffffffu, m, o));
        if (tid == 0) sRedS[0] = m;
    }
    __syncthreads();
    const float lmax = sRedS[0];
    __syncthreads();
    if (tid < 128) {
        float s = sSc[tid];
        sSc[tid] = (s > -1e8f) ? __expf(s - lmax) : 0.f;
    }
    __syncthreads();
    if (tid < 64) sRedS[tid] = sSc[tid] + sSc[tid + 64];
    __syncthreads();
    if (tid < 32) {
        float e = sRedS[tid] + sRedS[tid + 32];
#pragma unroll
        for (int o = 16; o > 0; o >>= 1) e += __shfl_xor_sync(0xffffffffu, e, o);
        if (tid == 0) sRedS[0] = e;
    }
    __syncthreads();
    const float esum = sRedS[0];

    // weighted column sums from fp16 A in smem
    float2* sRed2 = (float2*)(smem + SRED);
    const int c2 = tid & 127;
    const int rh = tid >> 7;
    float ax = 0.f, ay = 0.f;
#pragma unroll 8
    for (int r = 0; r < 64; r++) {
        int row = rh * 64 + r;
        float wv = sSc[row];
        __half2 a2 = *(const __half2*)(smem + SA_OFF + (size_t)(row * A_ST + c2 * 2) * 2);
        float2 af = __half22float2(a2);
        ax += wv * af.x; ay += wv * af.y;
    }
    sRed2[tid] = make_float2(ax, ay);
    __syncthreads();
    if (tid < 128) {
        float2 lo = sRed2[tid], hi = sRed2[tid + 128];
        float2 out = make_float2(lo.x + hi.x, lo.y + hi.y);
        int b = row0 / A.S;
        int chunk = (row0 % A.S) >> 7;
        *(float2*)(g_psum + (((A.pool * BATCH) + b) * 16 + chunk) * HDIM + tid * 2) = out;
        if (tid == 0) {
            g_pmax[A.pool][b][chunk]  = lmax;
            g_pesum[A.pool][b][chunk] = esum;
        }
    }
}

// ---------------- chunk combine helpers ----------------
__device__ __forceinline__ void make_factors(int pool, int b, int nch,
                                             float* fac, float* invden) {
    float gmax = -3.4e38f;
    for (int c = 0; c < nch; c++) gmax = fmaxf(gmax, g_pmax[pool][b][c]);
    float den = 0.f;
    for (int c = 0; c < nch; c++) {
        float f = __expf(g_pmax[pool][b][c] - gmax);
        fac[c] = f;
        den += f * g_pesum[pool][b][c];
    }
    *invden = 1.f / den;
}

__device__ __forceinline__ float combine(int pool, int b, int col, int nch,
                                         const float* fac, float invden) {
    const float* pp = g_psum + (((pool * BATCH) + b) * 16) * HDIM + col;
    float s = 0.f;
#pragma unroll 4
    for (int c = 0; c < nch; c++) s += fac[c] * pp[c * HDIM];
    return s * invden;
}

// ---------------- code = tanh([tok, gr] @ Wf + bf); 512 blocks ----------------
__global__ __launch_bounds__(256) void code_kernel(const float* Wf, const float* bfv) {
    int b  = blockIdx.x >> 3;
    int cg = blockIdx.x & 7;
    const int tid = threadIdx.x;
    const int jg = tid >> 5;
    const int ci = tid & 31;
    const int col = cg * 32 + ci;
    __shared__ float cat[2 * HDIM];
    __shared__ float part[256];
    __shared__ float fac0[16], fac1[4];
    __shared__ float inv0, inv1;

    if (tid == 0) make_factors(0, b, 16, fac0, &inv0);
    if (tid == 32) make_factors(1, b, 4, fac1, &inv1);
    __syncthreads();

    cat[tid]        = tanh_fast(combine(0, b, tid, 16, fac0, inv0));
    cat[HDIM + tid] = tanh_fast(combine(1, b, tid, 4, fac1, inv1));
    __syncthreads();

    float acc = 0.f;
    const float* wp = Wf + col;
    const int j0 = jg * 64;
#pragma unroll 8
    for (int j = 0; j < 64; j++)
        acc += cat[j0 + j] * wp[(size_t)(j0 + j) * HDIM];
    part[tid] = acc;
    __syncthreads();
    if (tid < 32) {
        float s = bfv[cg * 32 + tid];
#pragma unroll
        for (int g = 0; g < 8; g++) s += part[g * 32 + tid];
        g_code[b * HDIM + cg * 32 + tid] = tanh_fast(s);
    }
}

// ---------------- per-batch hinge ----------------
__global__ __launch_bounds__(256) void loss1_kernel() {
    const int b = blockIdx.x;
    const int tid = threadIdx.x;
    const int warp = tid >> 5, lane = tid & 31;
    __shared__ float sm[8][5];
    __shared__ float fac2[4], fac3[4];
    __shared__ float inv2, inv3;

    if (tid == 0) make_factors(2, b, 4, fac2, &inv2);
    if (tid == 32) make_factors(3, b, 4, fac3, &inv3);
    __syncthreads();

    float c = g_code[b * HDIM + tid];
    float a = tanh_fast(tanh_fast(combine(2, b, tid, 4, fac2, inv2)));
    float n = tanh_fast(tanh_fast(combine(3, b, tid, 4, fac3, inv3)));
    float s0 = c * c, s1 = a * a, s2 = n * n, s3 = c * a, s4 = c * n;
#pragma unroll
    for (int o = 16; o > 0; o >>= 1) {
        s0 += __shfl_xor_sync(0xffffffffu, s0, o);
        s1 += __shfl_xor_sync(0xffffffffu, s1, o);
        s2 += __shfl_xor_sync(0xffffffffu, s2, o);
        s3 += __shfl_xor_sync(0xffffffffu, s3, o);
        s4 += __shfl_xor_sync(0xffffffffu, s4, o);
    }
    if (lane == 0) {
        sm[warp][0] = s0; sm[warp][1] = s1; sm[warp][2] = s2;
        sm[warp][3] = s3; sm[warp][4] = s4;
    }
    __syncthreads();
    if (tid == 0) {
        float t0 = 0, t1 = 0, t2 = 0, t3 = 0, t4 = 0;
#pragma unroll
        for (int wv = 0; wv < 8; wv++) {
            t0 += sm[wv][0]; t1 += sm[wv][1]; t2 += sm[wv][2];
            t3 += sm[wv][3]; t4 += sm[wv][4];
        }
        float nc = sqrtf(t0);
        float sa = t3 / fmaxf(nc * sqrtf(t1), 1e-8f);
        float sn = t4 / fmaxf(nc * sqrtf(t2), 1e-8f);
        g_hinge[b] = fmaxf(0.6f - sa + sn, 0.f);
    }
}

__global__ void loss2_kernel(float* out) {
    int t = threadIdx.x;
    float v = g_hinge[t] + g_hinge[t + 32];
#pragma unroll
    for (int o = 16; o > 0; o >>= 1) v += __shfl_xor_sync(0xffffffffu, v, o);
    if (t == 0) out[0] = v / (float)BATCH;
}

// ---------------- launch ----------------
extern "C" void kernel_launch(void* const* d_in, const int* in_sizes, int n_in,
                              void* d_out, int out_size) {
    const float* token_feat = (const float*)d_in[0];
    const int*   token_mask = (const int*)d_in[1];
    const float* graph_feat = (const float*)d_in[2];
    const int*   graph_mask = (const int*)d_in[3];
    const float* da_feat    = (const float*)d_in[4];
    const int*   da_mask    = (const int*)d_in[5];
    const float* dn_feat    = (const float*)d_in[6];
    const int*   dn_mask    = (const int*)d_in[7];
    const float* Wt = (const float*)d_in[8];
    const float* bt = (const float*)d_in[9];
    const float* vt = (const float*)d_in[10];
    const float* ct = (const float*)d_in[11];
    const float* Wg = (const float*)d_in[12];
    const float* bg = (const float*)d_in[13];
    const float* vg = (const float*)d_in[14];
    const float* cg = (const float*)d_in[15];
    const float* Wd = (const float*)d_in[16];
    const float* bd = (const float*)d_in[17];
    const float* vd = (const float*)d_in[18];
    const float* cd = (const float*)d_in[19];
    const float* Wf = (const float*)d_in[20];
    const float* bf = (const float*)d_in[21];

    cudaFuncSetAttribute(score_tc, cudaFuncAttributeMaxDynamicSharedMemorySize, SCORE_SMEM);

    __half* wtp = nullptr;
    cudaGetSymbolAddress((void**)&wtp, g_WT);

    wconv_kernel<<<dim3(256, 3), 256>>>(Wt, Wg, Wd);

    const int nTok = BATCH * S_TOK / 128;   // 1024
    const int nOth = BATCH * S_OTH / 128;   // 256

    ScoreArgs sa0 = {token_feat, token_mask, bt, vt, ct, 0, 0,               0,      0, S_TOK};
    ScoreArgs sa1 = {graph_feat, graph_mask, bg, vg, cg, 1, nTok,            65536,  1, S_OTH};
    ScoreArgs sa2 = {da_feat,    da_mask,    bd, vd, cd, 0, nTok + nOth,     131072, 2, S_OTH};
    ScoreArgs sa3 = {dn_feat,    dn_mask,    bd, vd, cd, 0, nTok + 2 * nOth, 131072, 3, S_OTH};
    score_tc<<<nTok + 3 * nOth, 256, SCORE_SMEM>>>(sa0, sa1, sa2, sa3, wtp);

    code_kernel<<<8 * BATCH, 256>>>(Wf, bf);
    loss1_kernel<<<BATCH, 256>>>();
    loss2_kernel<<<1, 32>>>((float*)d_out);
}

// round 12
// speedup vs baseline: 5.1529x; 1.0196x over previous
#include <cuda_runtime.h>
#include <cuda_fp16.h>
#include <stdint.h>
#include <math.h>

#define HDIM 256
#define BATCH 64
#define S_TOK 2048
#define S_OTH 512
#define NEGV (-1e9f)

// ---------------- scratch (no allocations allowed) ----------------
__device__ float g_code[BATCH*HDIM];
__device__ float g_hinge[BATCH];
__device__ float g_pmax[4][BATCH][32];
__device__ float g_pesum[4][BATCH][32];
__device__ float g_psum[4*BATCH*32*HDIM];        // [pool][b][chunk<32][col]
__device__ __half g_WT[3 * 65536];               // W transposed fp16: [mat][n*256+k]

// ---------------- PTX helpers ----------------
__device__ __forceinline__ uint32_t smem_to_u32(const void* p) {
    uint32_t a;
    asm("{ .reg .u64 tmp; cvta.to.shared.u64 tmp, %1; cvt.u32.u64 %0, tmp; }" : "=r"(a) : "l"(p));
    return a;
}
__device__ __forceinline__ float tanh_fast(float x) {
    float y;
    asm("tanh.approx.f32 %0, %1;" : "=f"(y) : "f"(x));
    return y;
}
#define LDSM_X4(r0,r1,r2,r3,addr) \
    asm volatile("ldmatrix.sync.aligned.m8n8.x4.shared.b16 {%0,%1,%2,%3}, [%4];" \
        : "=r"(r0),"=r"(r1),"=r"(r2),"=r"(r3) : "r"(addr))
#define MMA_F16(c, a, b) \
    asm volatile("mma.sync.aligned.m16n8k16.row.col.f32.f16.f16.f32 " \
        "{%0,%1,%2,%3},{%4,%5,%6,%7},{%8,%9},{%0,%1,%2,%3};" \
        : "+f"((c)[0]),"+f"((c)[1]),"+f"((c)[2]),"+f"((c)[3]) \
        : "r"((a)[0]),"r"((a)[1]),"r"((a)[2]),"r"((a)[3]),"r"((b)[0]),"r"((b)[1]))
#define CP_ASYNC16(dst, src) \
    asm volatile("cp.async.cg.shared.global [%0], [%1], 16;" :: "r"(dst), "l"(src) : "memory")
#define CP_COMMIT() asm volatile("cp.async.commit_group;" ::: "memory")
#define CP_WAIT(n)  asm volatile("cp.async.wait_group %0;" :: "n"(n) : "memory")

// ---------------- W transpose to fp16 ----------------
__global__ void wconv_kernel(const float* Wt, const float* Wg, const float* Wd) {
    int mat = blockIdx.y;
    const float* W = (mat == 0) ? Wt : (mat == 1) ? Wg : Wd;
    int k = blockIdx.x, n = threadIdx.x;
    g_WT[mat * 65536 + n * 256 + k] = __float2half_rn(W[k * 256 + n]);
}

// ---------------- fused score + softmax-pool kernel (M=64, 2 CTAs/SM) ----------------
#define A_ST 264                  // fp16 elems per A row (528 B)
#define WB_ST 272                 // bytes per W row (256 data + 16 pad), K=128 chunk
#define SA_OFF 0                  // 64*264*2 = 33792
#define SW_OFF 33792              // 2 buffers of 34816 (128 rows x 272 B)
#define SW_BUF 34816
#define SBIAS 103424              // 256 floats
#define SVV   104448              // 256 floats
#define SPART 105472              // 64*2 floats (512 B)
#define SRED  105984              // 256 float2 (2048 B)
#define SCORE_SMEM 108032

struct ScoreArgs {
    const float* feat;
    const int* mask;
    const float* bv;
    const float* v;
    const float* c;
    int pretanh;
    int blkStart;
    int wtOff;
    int pool;
    int S;
};

__global__ __launch_bounds__(256, 2) void score_tc(ScoreArgs A0, ScoreArgs A1,
                                                   ScoreArgs A2, ScoreArgs A3,
                                                   const __half* WTg) {
    ScoreArgs A;
    int blk = blockIdx.x;
    if (blk >= A3.blkStart)      A = A3;
    else if (blk >= A2.blkStart) A = A2;
    else if (blk >= A1.blkStart) A = A1;
    else                         A = A0;
    const int row0 = (blk - A.blkStart) * 64;

    extern __shared__ char smem[];
    const uint32_t sbase = smem_to_u32(smem);
    float* sBias = (float*)(smem + SBIAS);
    float* sV    = (float*)(smem + SVV);
    float* sPart = (float*)(smem + SPART);

    const int tid  = threadIdx.x;
    const int warp = tid >> 5;
    const int lane = tid & 31;
    const int wm = warp & 3;        // 4 m-warps (16 rows each)
    const int wn = warp >> 2;       // 2 n-warps (64 cols each within a 128-col half)
    const int tq = lane & 3;
    const int gp = lane >> 2;

    const __half* WT = WTg + A.wtOff;
    const int pt = A.pretanh;

    // prefetch W chunk q=0 (half 0, kh 0): 128 n-rows x 128 k
    for (int i = tid; i < 2048; i += 256) {
        int r = i >> 4, j = i & 15;
        const __half* src = WT + (size_t)r * 256 + j * 8;
        uint32_t dst = sbase + SW_OFF + (uint32_t)(r * WB_ST + j * 16);
        CP_ASYNC16(dst, src);
    }
    CP_COMMIT();

    sBias[tid] = A.bv[tid];
    sV[tid]    = A.v[tid];
    if (tid < 64) { sPart[tid * 2] = 0.f; sPart[tid * 2 + 1] = 0.f; }

    // ---- A: 64 rows x 256 cols fp32 -> fp16 into smem (full, high MLP) ----
    {
        const int ar = tid >> 2;
        const int ac = (tid & 3) * 64;
        const float4* src = (const float4*)(A.feat + (size_t)(row0 + ar) * HDIM + ac);
        float4 av[16];
#pragma unroll
        for (int j = 0; j < 16; j++) av[j] = src[j];
#pragma unroll
        for (int j = 0; j < 16; j++) {
            float4 t = av[j];
            if (pt) {
                t.x = tanh_fast(t.x); t.y = tanh_fast(t.y);
                t.z = tanh_fast(t.z); t.w = tanh_fast(t.w);
            }
            __half2 h0 = __float22half2_rn(make_float2(t.x, t.y));
            __half2 h1 = __float22half2_rn(make_float2(t.z, t.w));
            uint2 hu;
            hu.x = *(uint32_t*)&h0; hu.y = *(uint32_t*)&h1;
            *(uint2*)(smem + SA_OFF + (size_t)(ar * A_ST + ac + j * 4) * 2) = hu;
        }
    }

    const uint32_t aBase = sbase + SA_OFF;
    const uint32_t aLaneOff = (uint32_t)(((wm * 16 + (lane & 15)) * A_ST + ((lane >> 4) << 3)) * 2);
    const uint32_t bLane = (uint32_t)(((lane & 7) + ((lane >> 4) << 3)) * WB_ST + (((lane >> 3) & 1) << 4));

    float acc[8][4];

    for (int half = 0; half < 2; half++) {
#pragma unroll
        for (int nj = 0; nj < 8; nj++) {
            acc[nj][0] = 0.f; acc[nj][1] = 0.f;
            acc[nj][2] = 0.f; acc[nj][3] = 0.f;
        }
        for (int kh = 0; kh < 2; kh++) {
            const int q = half * 2 + kh;
            const int buf = q & 1;
            if (q < 3) {
                const int nh = (q + 1) >> 1, nkh = (q + 1) & 1, nb2 = (q + 1) & 1;
                for (int i = tid; i < 2048; i += 256) {
                    int r = i >> 4, j = i & 15;
                    const __half* src = WT + (size_t)(nh * 128 + r) * 256 + nkh * 128 + j * 8;
                    uint32_t dst = sbase + SW_OFF + nb2 * SW_BUF + (uint32_t)(r * WB_ST + j * 16);
                    CP_ASYNC16(dst, src);
                }
                CP_COMMIT();
                CP_WAIT(1);
            } else {
                CP_WAIT(0);
            }
            __syncthreads();

            const uint32_t wbBase = sbase + SW_OFF + buf * SW_BUF + bLane;

#pragma unroll
            for (int ks = 0; ks < 8; ks++) {
                const uint32_t kOffA = (uint32_t)(kh * 256 + ks * 32);
                uint32_t aF[4];
                LDSM_X4(aF[0], aF[1], aF[2], aF[3], aBase + aLaneOff + kOffA);
                uint32_t bF[8][2];
#pragma unroll
                for (int nb = 0; nb < 4; nb++) {
                    uint32_t bd = (uint32_t)((wn * 64 + nb * 16) * WB_ST + ks * 32);
                    uint32_t r0, r1, r2, r3;
                    LDSM_X4(r0, r1, r2, r3, wbBase + bd);
                    bF[2*nb][0] = r0; bF[2*nb][1] = r1;
                    bF[2*nb+1][0] = r2; bF[2*nb+1][1] = r3;
                }
#pragma unroll
                for (int nj = 0; nj < 8; nj++)
                    MMA_F16(acc[nj], aF, bF[nj]);
            }
            __syncthreads();   // all warps done with buf before its overwrite lands
        }

        // epilogue for this half: tanh(acc+b)*v, reduce over owned cols
        {
            float p0 = 0.f, p1 = 0.f;
#pragma unroll
            for (int nj = 0; nj < 8; nj++) {
                int col = half * 128 + wn * 64 + nj * 8 + tq * 2;
                float b0 = sBias[col], b1 = sBias[col + 1];
                float v0 = sV[col],    v1 = sV[col + 1];
                p0 += tanh_fast(acc[nj][0] + b0) * v0 + tanh_fast(acc[nj][1] + b1) * v1;
                p1 += tanh_fast(acc[nj][2] + b0) * v0 + tanh_fast(acc[nj][3] + b1) * v1;
            }
            p0 += __shfl_xor_sync(0xffffffffu, p0, 1);
            p0 += __shfl_xor_sync(0xffffffffu, p0, 2);
            p1 += __shfl_xor_sync(0xffffffffu, p1, 1);
            p1 += __shfl_xor_sync(0xffffffffu, p1, 2);
            if (tq == 0) {
                int r0 = wm * 16 + gp;
                sPart[r0 * 2 + wn]       += p0;
                sPart[(r0 + 8) * 2 + wn] += p1;
            }
        }
    }
    __syncthreads();

    // ---------------- fused softmax-pool over this 64-row chunk ----------------
    float* sSc   = sBias;               // reuse: 64 scores/weights
    float* sRedS = sV;                  // reuse
    if (tid < 64) {
        float s = sPart[tid * 2] + sPart[tid * 2 + 1] + A.c[0];
        int msk = A.mask[row0 + tid];
        sSc[tid] = msk ? s : NEGV;
    }
    __syncthreads();
    if (tid < 32) {
        float m = fmaxf(sSc[tid], sSc[tid + 32]);
#pragma unroll
        for (int o = 16; o > 0; o >>= 1) m = fmaxf(m, __shfl_xor_sync(0xffffffffu, m, o));
        if (tid == 0) sRedS[0] = m;
    }
    __syncthreads();
    const float lmax = sRedS[0];
    __syncthreads();
    if (tid < 64) {
        float s = sSc[tid];
        sSc[tid] = (s > -1e8f) ? __expf(s - lmax) : 0.f;
    }
    __syncthreads();
    if (tid < 32) {
        float e = sSc[tid] + sSc[tid + 32];
#pragma unroll
        for (int o = 16; o > 0; o >>= 1) e += __shfl_xor_sync(0xffffffffu, e, o);
        if (tid == 0) sRedS[0] = e;
    }
    __syncthreads();
    const float esum = sRedS[0];

    // weighted column sums from fp16 A in smem
    float2* sRed2 = (float2*)(smem + SRED);
    const int c2 = tid & 127;
    const int rh = tid >> 7;
    float ax = 0.f, ay = 0.f;
#pragma unroll 8
    for (int r = 0; r < 32; r++) {
        int row = rh * 32 + r;
        float wv = sSc[row];
        __half2 a2 = *(const __half2*)(smem + SA_OFF + (size_t)(row * A_ST + c2 * 2) * 2);
        float2 af = __half22float2(a2);
        ax += wv * af.x; ay += wv * af.y;
    }
    sRed2[tid] = make_float2(ax, ay);
    __syncthreads();
    if (tid < 128) {
        float2 lo = sRed2[tid], hi = sRed2[tid + 128];
        float2 out = make_float2(lo.x + hi.x, lo.y + hi.y);
        int b = row0 / A.S;
        int chunk = (row0 % A.S) >> 6;
        *(float2*)(g_psum + (((A.pool * BATCH) + b) * 32 + chunk) * HDIM + tid * 2) = out;
        if (tid == 0) {
            g_pmax[A.pool][b][chunk]  = lmax;
            g_pesum[A.pool][b][chunk] = esum;
        }
    }
}

// ---------------- chunk combine helpers ----------------
__device__ __forceinline__ void make_factors(int pool, int b, int nch,
                                             float* fac, float* invden) {
    float gmax = -3.4e38f;
    for (int c = 0; c < nch; c++) gmax = fmaxf(gmax, g_pmax[pool][b][c]);
    float den = 0.f;
    for (int c = 0; c < nch; c++) {
        float f = __expf(g_pmax[pool][b][c] - gmax);
        fac[c] = f;
        den += f * g_pesum[pool][b][c];
    }
    *invden = 1.f / den;
}

__device__ __forceinline__ float combine(int pool, int b, int col, int nch,
                                         const float* fac, float invden) {
    const float* pp = g_psum + (((pool * BATCH) + b) * 32) * HDIM + col;
    float s = 0.f;
#pragma unroll 8
    for (int c = 0; c < nch; c++) s += fac[c] * pp[c * HDIM];
    return s * invden;
}

// ---------------- code = tanh([tok, gr] @ Wf + bf); 512 blocks ----------------
__global__ __launch_bounds__(256) void code_kernel(const float* Wf, const float* bfv) {
    int b  = blockIdx.x >> 3;
    int cg = blockIdx.x & 7;
    const int tid = threadIdx.x;
    const int jg = tid >> 5;
    const int ci = tid & 31;
    const int col = cg * 32 + ci;
    __shared__ float cat[2 * HDIM];
    __shared__ float part[256];
    __shared__ float fac0[32], fac1[8];
    __shared__ float inv0, inv1;

    if (tid == 0) make_factors(0, b, 32, fac0, &inv0);
    if (tid == 32) make_factors(1, b, 8, fac1, &inv1);
    __syncthreads();

    cat[tid]        = tanh_fast(combine(0, b, tid, 32, fac0, inv0));
    cat[HDIM + tid] = tanh_fast(combine(1, b, tid, 8, fac1, inv1));
    __syncthreads();

    float acc = 0.f;
    const float* wp = Wf + col;
    const int j0 = jg * 64;
#pragma unroll 8
    for (int j = 0; j < 64; j++)
        acc += cat[j0 + j] * wp[(size_t)(j0 + j) * HDIM];
    part[tid] = acc;
    __syncthreads();
    if (tid < 32) {
        float s = bfv[cg * 32 + tid];
#pragma unroll
        for (int g = 0; g < 8; g++) s += part[g * 32 + tid];
        g_code[b * HDIM + cg * 32 + tid] = tanh_fast(s);
    }
}

// ---------------- per-batch hinge ----------------
__global__ __launch_bounds__(256) void loss1_kernel() {
    const int b = blockIdx.x;
    const int tid = threadIdx.x;
    const int warp = tid >> 5, lane = tid & 31;
    __shared__ float sm[8][5];
    __shared__ float fac2[8], fac3[8];
    __shared__ float inv2, inv3;

    if (tid == 0) make_factors(2, b, 8, fac2, &inv2);
    if (tid == 32) make_factors(3, b, 8, fac3, &inv3);
    __syncthreads();

    float c = g_code[b * HDIM + tid];
    float a = tanh_fast(tanh_fast(combine(2, b, tid, 8, fac2, inv2)));
    float n = tanh_fast(tanh_fast(combine(3, b, tid, 8, fac3, inv3)));
    float s0 = c * c, s1 = a * a, s2 = n * n, s3 = c * a, s4 = c * n;
#pragma unroll
    for (int o = 16; o > 0; o >>= 1) {
        s0 += __shfl_xor_sync(0xffffffffu, s0, o);
        s1 += __shfl_xor_sync(0xffffffffu, s1, o);
        s2 += __shfl_xor_sync(0xffffffffu, s2, o);
        s3 += __shfl_xor_sync(0xffffffffu, s3, o);
        s4 += __shfl_xor_sync(0xffffffffu, s4, o);
    }
    if (lane == 0) {
        sm[warp][0] = s0; sm[warp][1] = s1; sm[warp][2] = s2;
        sm[warp][3] = s3; sm[warp][4] = s4;
    }
    __syncthreads();
    if (tid == 0) {
        float t0 = 0, t1 = 0, t2 = 0, t3 = 0, t4 = 0;
#pragma unroll
        for (int wv = 0; wv < 8; wv++) {
            t0 += sm[wv][0]; t1 += sm[wv][1]; t2 += sm[wv][2];
            t3 += sm[wv][3]; t4 += sm[wv][4];
        }
        float nc = sqrtf(t0);
        float sa = t3 / fmaxf(nc * sqrtf(t1), 1e-8f);
        float sn = t4 / fmaxf(nc * sqrtf(t2), 1e-8f);
        g_hinge[b] = fmaxf(0.6f - sa + sn, 0.f);
    }
}

__global__ void loss2_kernel(float* out) {
    int t = threadIdx.x;
    float v = g_hinge[t] + g_hinge[t + 32];
#pragma unroll
    for (int o = 16; o > 0; o >>= 1) v += __shfl_xor_sync(0xffffffffu, v, o);
    if (t == 0) out[0] = v / (float)BATCH;
}

// ---------------- launch ----------------
extern "C" void kernel_launch(void* const* d_in, const int* in_sizes, int n_in,
                              void* d_out, int out_size) {
    const float* token_feat = (const float*)d_in[0];
    const int*   token_mask = (const int*)d_in[1];
    const float* graph_feat = (const float*)d_in[2];
    const int*   graph_mask = (const int*)d_in[3];
    const float* da_feat    = (const float*)d_in[4];
    const int*   da_mask    = (const int*)d_in[5];
    const float* dn_feat    = (const float*)d_in[6];
    const int*   dn_mask    = (const int*)d_in[7];
    const float* Wt = (const float*)d_in[8];
    const float* bt = (const float*)d_in[9];
    const float* vt = (const float*)d_in[10];
    const float* ct = (const float*)d_in[11];
    const float* Wg = (const float*)d_in[12];
    const float* bg = (const float*)d_in[13];
    const float* vg = (const float*)d_in[14];
    const float* cg = (const float*)d_in[15];
    const float* Wd = (const float*)d_in[16];
    const float* bd = (const float*)d_in[17];
    const float* vd = (const float*)d_in[18];
    const float* cd = (const float*)d_in[19];
    const float* Wf = (const float*)d_in[20];
    const float* bf = (const float*)d_in[21];

    cudaFuncSetAttribute(score_tc, cudaFuncAttributeMaxDynamicSharedMemorySize, SCORE_SMEM);

    __half* wtp = nullptr;
    cudaGetSymbolAddress((void**)&wtp, g_WT);

    wconv_kernel<<<dim3(256, 3), 256>>>(Wt, Wg, Wd);

    const int nTok = BATCH * S_TOK / 64;   // 2048
    const int nOth = BATCH * S_OTH / 64;   // 512

    ScoreArgs sa0 = {token_feat, token_mask, bt, vt, ct, 0, 0,               0,      0, S_TOK};
    ScoreArgs sa1 = {graph_feat, graph_mask, bg, vg, cg, 1, nTok,            65536,  1, S_OTH};
    ScoreArgs sa2 = {da_feat,    da_mask,    bd, vd, cd, 0, nTok + nOth,     131072, 2, S_OTH};
    ScoreArgs sa3 = {dn_feat,    dn_mask,    bd, vd, cd, 0, nTok + 2 * nOth, 131072, 3, S_OTH};
    score_tc<<<nTok + 3 * nOth, 256, SCORE_SMEM>>>(sa0, sa1, sa2, sa3, wtp);

    code_kernel<<<8 * BATCH, 256>>>(Wf, bf);
    loss1_kernel<<<BATCH, 256>>>();
    loss2_kernel<<<1, 32>>>((float*)d_out);
}

// round 13
// speedup vs baseline: 5.4170x; 1.0513x over previous
#include <cuda_runtime.h>
#include <cuda_fp16.h>
#include <stdint.h>
#include <math.h>

#define HDIM 256
#define BATCH 64
#define S_TOK 2048
#define S_OTH 512
#define NEGV (-1e9f)

// ---------------- scratch (no allocations allowed) ----------------
__device__ float g_code[BATCH*HDIM];
__device__ float g_hinge[BATCH];
__device__ int   g_cnt;
__device__ float g_pmax[4][BATCH][16];
__device__ float g_pesum[4][BATCH][16];
__device__ float g_psum[4*BATCH*16*HDIM];        // [pool][b][chunk<16][col]
__device__ __half g_WT[3 * 65536];               // W transposed fp16: [mat][n*256+k]

// ---------------- PTX helpers ----------------
__device__ __forceinline__ uint32_t smem_to_u32(const void* p) {
    uint32_t a;
    asm("{ .reg .u64 tmp; cvta.to.shared.u64 tmp, %1; cvt.u32.u64 %0, tmp; }" : "=r"(a) : "l"(p));
    return a;
}
__device__ __forceinline__ float tanh_fast(float x) {
    float y;
    asm("tanh.approx.f32 %0, %1;" : "=f"(y) : "f"(x));
    return y;
}
#define LDSM_X4(r0,r1,r2,r3,addr) \
    asm volatile("ldmatrix.sync.aligned.m8n8.x4.shared.b16 {%0,%1,%2,%3}, [%4];" \
        : "=r"(r0),"=r"(r1),"=r"(r2),"=r"(r3) : "r"(addr))
#define MMA_F16(c, a, b) \
    asm volatile("mma.sync.aligned.m16n8k16.row.col.f32.f16.f16.f32 " \
        "{%0,%1,%2,%3},{%4,%5,%6,%7},{%8,%9},{%0,%1,%2,%3};" \
        : "+f"((c)[0]),"+f"((c)[1]),"+f"((c)[2]),"+f"((c)[3]) \
        : "r"((a)[0]),"r"((a)[1]),"r"((a)[2]),"r"((a)[3]),"r"((b)[0]),"r"((b)[1]))
#define CP_ASYNC16(dst, src) \
    asm volatile("cp.async.cg.shared.global [%0], [%1], 16;" :: "r"(dst), "l"(src) : "memory")
#define CP_COMMIT() asm volatile("cp.async.commit_group;" ::: "memory")
#define CP_WAIT(n)  asm volatile("cp.async.wait_group %0;" :: "n"(n) : "memory")

// ---------------- W transpose to fp16 ----------------
__global__ void wconv_kernel(const float* Wt, const float* Wg, const float* Wd) {
    int mat = blockIdx.y;
    const float* W = (mat == 0) ? Wt : (mat == 1) ? Wg : Wd;
    int k = blockIdx.x, n = threadIdx.x;
    g_WT[mat * 65536 + n * 256 + k] = __float2half_rn(W[k * 256 + n]);
}

// ---------------- fused score + softmax-pool (M=128, 512 threads, 16 warps) ----------------
#define A_ST 264                  // fp16 elems per A row (528 B)
#define WB_ST 272                 // bytes per W row (256 data + 16 pad), K=128 chunk
#define SA_OFF 0                  // 128*264*2 = 67584
#define SW_OFF 67584              // 2 buffers of 34816 (128 rows x 272 B)
#define SW_BUF 34816
#define SBIAS 137216              // 256 floats
#define SVV   138240              // 256 floats
#define SPART 139264              // 512 floats (2048 B)
#define SRED  141312              // 512 float2 (4096 B)
#define SCORE_SMEM 145408

struct ScoreArgs {
    const float* feat;
    const int* mask;
    const float* bv;
    const float* v;
    const float* c;
    int pretanh;
    int blkStart;
    int wtOff;
    int pool;
    int S;
};

__global__ __launch_bounds__(512, 1) void score_tc(ScoreArgs A0, ScoreArgs A1,
                                                   ScoreArgs A2, ScoreArgs A3,
                                                   const __half* WTg) {
    ScoreArgs A;
    int blk = blockIdx.x;
    if (blk >= A3.blkStart)      A = A3;
    else if (blk >= A2.blkStart) A = A2;
    else if (blk >= A1.blkStart) A = A1;
    else                         A = A0;
    const int row0 = (blk - A.blkStart) * 128;

    extern __shared__ char smem[];
    const uint32_t sbase = smem_to_u32(smem);
    float* sBias = (float*)(smem + SBIAS);
    float* sV    = (float*)(smem + SVV);
    float* sPart = (float*)(smem + SPART);

    const int tid  = threadIdx.x;
    const int warp = tid >> 5;
    const int lane = tid & 31;
    const int wm = warp & 3;        // 4 m-warps (32 rows each)
    const int wn = warp >> 2;       // 4 n-warps (32 cols each within a 128-col half)
    const int tq = lane & 3;
    const int gp = lane >> 2;

    const __half* WT = WTg + A.wtOff;
    const int pt = A.pretanh;

    // prefetch W chunk q=0 (half 0, kh 0): 128 n-rows x 128 k
    for (int i = tid; i < 2048; i += 512) {
        int r = i >> 4, j = i & 15;
        const __half* src = WT + (size_t)r * 256 + j * 8;
        uint32_t dst = sbase + SW_OFF + (uint32_t)(r * WB_ST + j * 16);
        CP_ASYNC16(dst, src);
    }
    CP_COMMIT();

    if (tid < 256) { sBias[tid] = A.bv[tid]; sV[tid] = A.v[tid]; }
    sPart[tid] = 0.f;

    // ---- A: 128 rows x 256 cols fp32 -> fp16 into smem ----
    {
        const int ar = tid >> 2;
        const int ac = (tid & 3) * 64;
        const float4* src = (const float4*)(A.feat + (size_t)(row0 + ar) * HDIM + ac);
        float4 av[16];
#pragma unroll
        for (int j = 0; j < 16; j++) av[j] = src[j];
#pragma unroll
        for (int j = 0; j < 16; j++) {
            float4 t = av[j];
            if (pt) {
                t.x = tanh_fast(t.x); t.y = tanh_fast(t.y);
                t.z = tanh_fast(t.z); t.w = tanh_fast(t.w);
            }
            __half2 h0 = __float22half2_rn(make_float2(t.x, t.y));
            __half2 h1 = __float22half2_rn(make_float2(t.z, t.w));
            uint2 hu;
            hu.x = *(uint32_t*)&h0; hu.y = *(uint32_t*)&h1;
            *(uint2*)(smem + SA_OFF + (size_t)(ar * A_ST + ac + j * 4) * 2) = hu;
        }
    }

    const uint32_t aBase = sbase + SA_OFF;
    const uint32_t aLaneOff = (uint32_t)(((wm * 32 + (lane & 15)) * A_ST + ((lane >> 4) << 3)) * 2);
    const uint32_t bLane = (uint32_t)(((lane & 7) + ((lane >> 4) << 3)) * WB_ST + (((lane >> 3) & 1) << 4));

    float acc[2][4][4];

    for (int half = 0; half < 2; half++) {
#pragma unroll
        for (int mi = 0; mi < 2; mi++)
#pragma unroll
            for (int nj = 0; nj < 4; nj++) {
                acc[mi][nj][0] = 0.f; acc[mi][nj][1] = 0.f;
                acc[mi][nj][2] = 0.f; acc[mi][nj][3] = 0.f;
            }
        for (int kh = 0; kh < 2; kh++) {
            const int q = half * 2 + kh;
            const int buf = q & 1;
            if (q < 3) {
                const int nh = (q + 1) >> 1, nkh = (q + 1) & 1, nb2 = (q + 1) & 1;
                for (int i = tid; i < 2048; i += 512) {
                    int r = i >> 4, j = i & 15;
                    const __half* src = WT + (size_t)(nh * 128 + r) * 256 + nkh * 128 + j * 8;
                    uint32_t dst = sbase + SW_OFF + nb2 * SW_BUF + (uint32_t)(r * WB_ST + j * 16);
                    CP_ASYNC16(dst, src);
                }
                CP_COMMIT();
                CP_WAIT(1);
            } else {
                CP_WAIT(0);
            }
            __syncthreads();

            const uint32_t wbBase = sbase + SW_OFF + buf * SW_BUF + bLane;

#pragma unroll
            for (int ks = 0; ks < 8; ks++) {
                const uint32_t kOffA = (uint32_t)(kh * 256 + ks * 32);
                uint32_t aF[2][4];
#pragma unroll
                for (int mi = 0; mi < 2; mi++) {
                    uint32_t ad = aLaneOff + (uint32_t)(mi * 16 * A_ST * 2) + kOffA;
                    LDSM_X4(aF[mi][0], aF[mi][1], aF[mi][2], aF[mi][3], aBase + ad);
                }
                uint32_t bF[4][2];
#pragma unroll
                for (int nb = 0; nb < 2; nb++) {
                    uint32_t bd = (uint32_t)((wn * 32 + nb * 16) * WB_ST + ks * 32);
                    uint32_t r0, r1, r2, r3;
                    LDSM_X4(r0, r1, r2, r3, wbBase + bd);
                    bF[2*nb][0] = r0; bF[2*nb][1] = r1;
                    bF[2*nb+1][0] = r2; bF[2*nb+1][1] = r3;
                }
#pragma unroll
                for (int mi = 0; mi < 2; mi++)
#pragma unroll
                    for (int nj = 0; nj < 4; nj++)
                        MMA_F16(acc[mi][nj], aF[mi], bF[nj]);
            }
            __syncthreads();
        }

        // epilogue for this half
#pragma unroll
        for (int mi = 0; mi < 2; mi++) {
            float p0 = 0.f, p1 = 0.f;
#pragma unroll
            for (int nj = 0; nj < 4; nj++) {
                int col = half * 128 + wn * 32 + nj * 8 + tq * 2;
                float b0 = sBias[col], b1 = sBias[col + 1];
                float v0 = sV[col],    v1 = sV[col + 1];
                p0 += tanh_fast(acc[mi][nj][0] + b0) * v0 + tanh_fast(acc[mi][nj][1] + b1) * v1;
                p1 += tanh_fast(acc[mi][nj][2] + b0) * v0 + tanh_fast(acc[mi][nj][3] + b1) * v1;
            }
            p0 += __shfl_xor_sync(0xffffffffu, p0, 1);
            p0 += __shfl_xor_sync(0xffffffffu, p0, 2);
            p1 += __shfl_xor_sync(0xffffffffu, p1, 1);
            p1 += __shfl_xor_sync(0xffffffffu, p1, 2);
            if (tq == 0) {
                int r0 = wm * 32 + mi * 16 + gp;
                sPart[r0 * 4 + wn]       += p0;
                sPart[(r0 + 8) * 4 + wn] += p1;
            }
        }
    }
    __syncthreads();

    // ---------------- fused softmax-pool over this 128-row chunk ----------------
    float* sSc   = sBias;
    float* sRedS = sV;
    if (tid < 128) {
        float s = sPart[tid * 4] + sPart[tid * 4 + 1] + sPart[tid * 4 + 2] + sPart[tid * 4 + 3] + A.c[0];
        int msk = A.mask[row0 + tid];
        sSc[tid] = msk ? s : NEGV;
    }
    __syncthreads();
    if (tid < 64) sRedS[tid] = fmaxf(sSc[tid], sSc[tid + 64]);
    __syncthreads();
    if (tid < 32) {
        float m = fmaxf(sRedS[tid], sRedS[tid + 32]);
#pragma unroll
        for (int o = 16; o > 0; o >>= 1) m = fmaxf(m, __shfl_xor_sync(0xffffffffu, m, o));
        if (tid == 0) sRedS[0] = m;
    }
    __syncthreads();
    const float lmax = sRedS[0];
    __syncthreads();
    if (tid < 128) {
        float s = sSc[tid];
        sSc[tid] = (s > -1e8f) ? __expf(s - lmax) : 0.f;
    }
    __syncthreads();
    if (tid < 64) sRedS[tid] = sSc[tid] + sSc[tid + 64];
    __syncthreads();
    if (tid < 32) {
        float e = sRedS[tid] + sRedS[tid + 32];
#pragma unroll
        for (int o = 16; o > 0; o >>= 1) e += __shfl_xor_sync(0xffffffffu, e, o);
        if (tid == 0) sRedS[0] = e;
    }
    __syncthreads();
    const float esum = sRedS[0];

    // weighted column sums from fp16 A in smem (4 row-stripes of 32)
    float2* sRed2 = (float2*)(smem + SRED);
    const int c2 = tid & 127;
    const int rh = tid >> 7;
    float ax = 0.f, ay = 0.f;
#pragma unroll 8
    for (int r = 0; r < 32; r++) {
        int row = rh * 32 + r;
        float wv = sSc[row];
        __half2 a2 = *(const __half2*)(smem + SA_OFF + (size_t)(row * A_ST + c2 * 2) * 2);
        float2 af = __half22float2(a2);
        ax += wv * af.x; ay += wv * af.y;
    }
    sRed2[tid] = make_float2(ax, ay);
    __syncthreads();
    if (tid < 128) {
        float2 s0 = sRed2[tid], s1 = sRed2[tid + 128];
        float2 s2 = sRed2[tid + 256], s3 = sRed2[tid + 384];
        float2 out = make_float2(s0.x + s1.x + s2.x + s3.x, s0.y + s1.y + s2.y + s3.y);
        int b = row0 / A.S;
        int chunk = (row0 % A.S) >> 7;
        *(float2*)(g_psum + (((A.pool * BATCH) + b) * 16 + chunk) * HDIM + tid * 2) = out;
        if (tid == 0) {
            g_pmax[A.pool][b][chunk]  = lmax;
            g_pesum[A.pool][b][chunk] = esum;
        }
    }
}

// ---------------- chunk combine helpers ----------------
__device__ __forceinline__ void make_factors(int pool, int b, int nch,
                                             float* fac, float* invden) {
    float gmax = -3.4e38f;
    for (int c = 0; c < nch; c++) gmax = fmaxf(gmax, g_pmax[pool][b][c]);
    float den = 0.f;
    for (int c = 0; c < nch; c++) {
        float f = __expf(g_pmax[pool][b][c] - gmax);
        fac[c] = f;
        den += f * g_pesum[pool][b][c];
    }
    *invden = 1.f / den;
}

__device__ __forceinline__ float combine(int pool, int b, int col, int nch,
                                         const float* fac, float invden) {
    const float* pp = g_psum + (((pool * BATCH) + b) * 16) * HDIM + col;
    float s = 0.f;
#pragma unroll 4
    for (int c = 0; c < nch; c++) s += fac[c] * pp[c * HDIM];
    return s * invden;
}

// ---------------- code = tanh([tok, gr] @ Wf + bf); 512 blocks ----------------
__global__ __launch_bounds__(256) void code_kernel(const float* Wf, const float* bfv) {
    int b  = blockIdx.x >> 3;
    int cg = blockIdx.x & 7;
    const int tid = threadIdx.x;
    const int jg = tid >> 5;
    const int ci = tid & 31;
    const int col = cg * 32 + ci;
    __shared__ float cat[2 * HDIM];
    __shared__ float part[256];
    __shared__ float fac0[16], fac1[4];
    __shared__ float inv0, inv1;

    if (tid == 0) make_factors(0, b, 16, fac0, &inv0);
    if (tid == 32) make_factors(1, b, 4, fac1, &inv1);
    __syncthreads();

    cat[tid]        = tanh_fast(combine(0, b, tid, 16, fac0, inv0));
    cat[HDIM + tid] = tanh_fast(combine(1, b, tid, 4, fac1, inv1));
    __syncthreads();

    float acc = 0.f;
    const float* wp = Wf + col;
    const int j0 = jg * 64;
#pragma unroll 8
    for (int j = 0; j < 64; j++)
        acc += cat[j0 + j] * wp[(size_t)(j0 + j) * HDIM];
    part[tid] = acc;
    __syncthreads();
    if (tid < 32) {
        float s = bfv[cg * 32 + tid];
#pragma unroll
        for (int g = 0; g < 8; g++) s += part[g * 32 + tid];
        g_code[b * HDIM + cg * 32 + tid] = tanh_fast(s);
    }
}

// ---------------- per-batch hinge + last-block finalize ----------------
__global__ __launch_bounds__(256) void loss1_kernel(float* out) {
    const int b = blockIdx.x;
    const int tid = threadIdx.x;
    const int warp = tid >> 5, lane = tid & 31;
    __shared__ float sm[8][5];
    __shared__ float fac2[4], fac3[4];
    __shared__ float inv2, inv3;
    __shared__ int isLast;

    if (tid == 0) make_factors(2, b, 4, fac2, &inv2);
    if (tid == 32) make_factors(3, b, 4, fac3, &inv3);
    __syncthreads();

    float c = g_code[b * HDIM + tid];
    float a = tanh_fast(tanh_fast(combine(2, b, tid, 4, fac2, inv2)));
    float n = tanh_fast(tanh_fast(combine(3, b, tid, 4, fac3, inv3)));
    float s0 = c * c, s1 = a * a, s2 = n * n, s3 = c * a, s4 = c * n;
#pragma unroll
    for (int o = 16; o > 0; o >>= 1) {
        s0 += __shfl_xor_sync(0xffffffffu, s0, o);
        s1 += __shfl_xor_sync(0xffffffffu, s1, o);
        s2 += __shfl_xor_sync(0xffffffffu, s2, o);
        s3 += __shfl_xor_sync(0xffffffffu, s3, o);
        s4 += __shfl_xor_sync(0xffffffffu, s4, o);
    }
    if (lane == 0) {
        sm[warp][0] = s0; sm[warp][1] = s1; sm[warp][2] = s2;
        sm[warp][3] = s3; sm[warp][4] = s4;
    }
    __syncthreads();
    if (tid == 0) {
        float t0 = 0, t1 = 0, t2 = 0, t3 = 0, t4 = 0;
#pragma unroll
        for (int wv = 0; wv < 8; wv++) {
            t0 += sm[wv][0]; t1 += sm[wv][1]; t2 += sm[wv][2];
            t3 += sm[wv][3]; t4 += sm[wv][4];
        }
        float nc = sqrtf(t0);
        float sa = t3 / fmaxf(nc * sqrtf(t1), 1e-8f);
        float sn = t4 / fmaxf(nc * sqrtf(t2), 1e-8f);
        g_hinge[b] = fmaxf(0.6f - sa + sn, 0.f);
        __threadfence();
        isLast = (atomicAdd(&g_cnt, 1) == BATCH - 1) ? 1 : 0;
    }
    __syncthreads();
    if (isLast && tid < 32) {
        float v = g_hinge[tid] + g_hinge[tid + 32];
#pragma unroll
        for (int o = 16; o > 0; o >>= 1) v += __shfl_xor_sync(0xffffffffu, v, o);
        if (tid == 0) {
            out[0] = v / (float)BATCH;
            g_cnt = 0;       // reset for graph replay
        }
    }
}

// ---------------- launch ----------------
extern "C" void kernel_launch(void* const* d_in, const int* in_sizes, int n_in,
                              void* d_out, int out_size) {
    const float* token_feat = (const float*)d_in[0];
    const int*   token_mask = (const int*)d_in[1];
    const float* graph_feat = (const float*)d_in[2];
    const int*   graph_mask = (const int*)d_in[3];
    const float* da_feat    = (const float*)d_in[4];
    const int*   da_mask    = (const int*)d_in[5];
    const float* dn_feat    = (const float*)d_in[6];
    const int*   dn_mask    = (const int*)d_in[7];
    const float* Wt = (const float*)d_in[8];
    const float* bt = (const float*)d_in[9];
    const float* vt = (const float*)d_in[10];
    const float* ct = (const float*)d_in[11];
    const float* Wg = (const float*)d_in[12];
    const float* bg = (const float*)d_in[13];
    const float* vg = (const float*)d_in[14];
    const float* cg = (const float*)d_in[15];
    const float* Wd = (const float*)d_in[16];
    const float* bd = (const float*)d_in[17];
    const float* vd = (const float*)d_in[18];
    const float* cd = (const float*)d_in[19];
    const float* Wf = (const float*)d_in[20];
    const float* bf = (const float*)d_in[21];

    cudaFuncSetAttribute(score_tc, cudaFuncAttributeMaxDynamicSharedMemorySize, SCORE_SMEM);

    __half* wtp = nullptr;
    cudaGetSymbolAddress((void**)&wtp, g_WT);

    wconv_kernel<<<dim3(256, 3), 256>>>(Wt, Wg, Wd);

    const int nTok = BATCH * S_TOK / 128;   // 1024
    const int nOth = BATCH * S_OTH / 128;   // 256

    ScoreArgs sa0 = {token_feat, token_mask, bt, vt, ct, 0, 0,               0,      0, S_TOK};
    ScoreArgs sa1 = {graph_feat, graph_mask, bg, vg, cg, 1, nTok,            65536,  1, S_OTH};
    ScoreArgs sa2 = {da_feat,    da_mask,    bd, vd, cd, 0, nTok + nOth,     131072, 2, S_OTH};
    ScoreArgs sa3 = {dn_feat,    dn_mask,    bd, vd, cd, 0, nTok + 2 * nOth, 131072, 3, S_OTH};
    score_tc<<<nTok + 3 * nOth, 512, SCORE_SMEM>>>(sa0, sa1, sa2, sa3, wtp);

    code_kernel<<<8 * BATCH, 256>>>(Wf, bf);
    loss1_kernel<<<BATCH, 256>>>((float*)d_out);
}

// round 14
// speedup vs baseline: 8.1165x; 1.4983x over previous
#include <cuda_runtime.h>
#include <cuda_fp16.h>
#include <stdint.h>
#include <math.h>

#define HDIM 256
#define BATCH 64
#define S_TOK 2048
#define S_OTH 512
#define NEGV (-1e9f)

// ---------------- scratch (no allocations allowed) ----------------
__device__ float g_code[BATCH*HDIM];
__device__ float g_hinge[BATCH];
__device__ int   g_cnt;
__device__ float g_pmax[4][BATCH][16];
__device__ float g_pesum[4][BATCH][16];
__device__ float g_psum[4*BATCH*16*HDIM];        // [pool][b][chunk<16][col]
__device__ __half g_WT[3 * 65536];               // W transposed fp16: [mat][n*256+k]

// ---------------- PTX helpers ----------------
__device__ __forceinline__ uint32_t smem_to_u32(const void* p) {
    uint32_t a;
    asm("{ .reg .u64 tmp; cvta.to.shared.u64 tmp, %1; cvt.u32.u64 %0, tmp; }" : "=r"(a) : "l"(p));
    return a;
}
__device__ __forceinline__ float tanh_fast(float x) {
    float y;
    asm("tanh.approx.f32 %0, %1;" : "=f"(y) : "f"(x));
    return y;
}
#define LDSM_X4(r0,r1,r2,r3,addr) \
    asm volatile("ldmatrix.sync.aligned.m8n8.x4.shared.b16 {%0,%1,%2,%3}, [%4];" \
        : "=r"(r0),"=r"(r1),"=r"(r2),"=r"(r3) : "r"(addr))
#define MMA_F16(c, a, b) \
    asm volatile("mma.sync.aligned.m16n8k16.row.col.f32.f16.f16.f32 " \
        "{%0,%1,%2,%3},{%4,%5,%6,%7},{%8,%9},{%0,%1,%2,%3};" \
        : "+f"((c)[0]),"+f"((c)[1]),"+f"((c)[2]),"+f"((c)[3]) \
        : "r"((a)[0]),"r"((a)[1]),"r"((a)[2]),"r"((a)[3]),"r"((b)[0]),"r"((b)[1]))
#define CP_ASYNC16(dst, src) \
    asm volatile("cp.async.cg.shared.global [%0], [%1], 16;" :: "r"(dst), "l"(src) : "memory")
#define CP_COMMIT() asm volatile("cp.async.commit_group;" ::: "memory")
#define CP_WAIT(n)  asm volatile("cp.async.wait_group %0;" :: "n"(n) : "memory")

// ---------------- W transpose to fp16 ----------------
__global__ void wconv_kernel(const float* Wt, const float* Wg, const float* Wd) {
    int mat = blockIdx.y;
    const float* W = (mat == 0) ? Wt : (mat == 1) ? Wg : Wd;
    int k = blockIdx.x, n = threadIdx.x;
    g_WT[mat * 65536 + n * 256 + k] = __float2half_rn(W[k * 256 + n]);
}

// ---------------- fused score + softmax-pool (M=128, 512 threads, 16 warps) ----------------
#define A_ST 264                  // fp16 elems per A row (528 B)
#define WB_ST 272                 // bytes per W row (256 data + 16 pad), K=128 chunk
#define SA_OFF 0                  // 128*264*2 = 67584
#define SW_OFF 67584              // 2 buffers of 34816 (128 rows x 272 B)
#define SW_BUF 34816
#define SBIAS 137216              // 256 floats
#define SVV   138240              // 256 floats
#define SPART 139264              // 512 floats (2048 B)
#define SRED  141312              // 512 float2 (4096 B)
#define SCORE_SMEM 145408

struct ScoreArgs {
    const float* feat;
    const int* mask;
    const float* bv;
    const float* v;
    const float* c;
    int pretanh;
    int blkStart;
    int wtOff;
    int pool;
    int S;
};

__global__ __launch_bounds__(512, 1) void score_tc(ScoreArgs A0, ScoreArgs A1,
                                                   ScoreArgs A2, ScoreArgs A3,
                                                   const __half* WTg) {
    ScoreArgs A;
    int blk = blockIdx.x;
    if (blk >= A3.blkStart)      A = A3;
    else if (blk >= A2.blkStart) A = A2;
    else if (blk >= A1.blkStart) A = A1;
    else                         A = A0;
    const int row0 = (blk - A.blkStart) * 128;

    const int tid  = threadIdx.x;

    // ---- early exit: ragged-prefix mask means mask[row0]==0 => whole chunk masked ----
    {
        int b = row0 / A.S;
        int chunk = (row0 % A.S) >> 7;
        if (A.mask[row0] == 0) {
            if (tid < 128)
                *(float2*)(g_psum + (((A.pool * BATCH) + b) * 16 + chunk) * HDIM + tid * 2)
                    = make_float2(0.f, 0.f);
            if (tid == 0) {
                g_pmax[A.pool][b][chunk]  = NEGV;
                g_pesum[A.pool][b][chunk] = 0.f;
            }
            return;
        }
    }

    extern __shared__ char smem[];
    const uint32_t sbase = smem_to_u32(smem);
    float* sBias = (float*)(smem + SBIAS);
    float* sV    = (float*)(smem + SVV);
    float* sPart = (float*)(smem + SPART);

    const int warp = tid >> 5;
    const int lane = tid & 31;
    const int wm = warp & 3;        // 4 m-warps (32 rows each)
    const int wn = warp >> 2;       // 4 n-warps (32 cols each within a 128-col half)
    const int tq = lane & 3;
    const int gp = lane >> 2;

    const __half* WT = WTg + A.wtOff;
    const int pt = A.pretanh;

    // prefetch W chunk q=0 (half 0, kh 0): 128 n-rows x 128 k
    for (int i = tid; i < 2048; i += 512) {
        int r = i >> 4, j = i & 15;
        const __half* src = WT + (size_t)r * 256 + j * 8;
        uint32_t dst = sbase + SW_OFF + (uint32_t)(r * WB_ST + j * 16);
        CP_ASYNC16(dst, src);
    }
    CP_COMMIT();

    if (tid < 256) { sBias[tid] = A.bv[tid]; sV[tid] = A.v[tid]; }
    sPart[tid] = 0.f;

    // ---- A: 128 rows x 256 cols fp32 -> fp16 into smem ----
    {
        const int ar = tid >> 2;
        const int ac = (tid & 3) * 64;
        const float4* src = (const float4*)(A.feat + (size_t)(row0 + ar) * HDIM + ac);
        float4 av[16];
#pragma unroll
        for (int j = 0; j < 16; j++) av[j] = src[j];
#pragma unroll
        for (int j = 0; j < 16; j++) {
            float4 t = av[j];
            if (pt) {
                t.x = tanh_fast(t.x); t.y = tanh_fast(t.y);
                t.z = tanh_fast(t.z); t.w = tanh_fast(t.w);
            }
            __half2 h0 = __float22half2_rn(make_float2(t.x, t.y));
            __half2 h1 = __float22half2_rn(make_float2(t.z, t.w));
            uint2 hu;
            hu.x = *(uint32_t*)&h0; hu.y = *(uint32_t*)&h1;
            *(uint2*)(smem + SA_OFF + (size_t)(ar * A_ST + ac + j * 4) * 2) = hu;
        }
    }

    const uint32_t aBase = sbase + SA_OFF;
    const uint32_t aLaneOff = (uint32_t)(((wm * 32 + (lane & 15)) * A_ST + ((lane >> 4) << 3)) * 2);
    const uint32_t bLane = (uint32_t)(((lane & 7) + ((lane >> 4) << 3)) * WB_ST + (((lane >> 3) & 1) << 4));

    float acc[2][4][4];

    for (int half = 0; half < 2; half++) {
#pragma unroll
        for (int mi = 0; mi < 2; mi++)
#pragma unroll
            for (int nj = 0; nj < 4; nj++) {
                acc[mi][nj][0] = 0.f; acc[mi][nj][1] = 0.f;
                acc[mi][nj][2] = 0.f; acc[mi][nj][3] = 0.f;
            }
        for (int kh = 0; kh < 2; kh++) {
            const int q = half * 2 + kh;
            const int buf = q & 1;
            if (q < 3) {
                const int nh = (q + 1) >> 1, nkh = (q + 1) & 1, nb2 = (q + 1) & 1;
                for (int i = tid; i < 2048; i += 512) {
                    int r = i >> 4, j = i & 15;
                    const __half* src = WT + (size_t)(nh * 128 + r) * 256 + nkh * 128 + j * 8;
                    uint32_t dst = sbase + SW_OFF + nb2 * SW_BUF + (uint32_t)(r * WB_ST + j * 16);
                    CP_ASYNC16(dst, src);
                }
                CP_COMMIT();
                CP_WAIT(1);
            } else {
                CP_WAIT(0);
            }
            __syncthreads();

            const uint32_t wbBase = sbase + SW_OFF + buf * SW_BUF + bLane;

#pragma unroll
            for (int ks = 0; ks < 8; ks++) {
                const uint32_t kOffA = (uint32_t)(kh * 256 + ks * 32);
                uint32_t aF[2][4];
#pragma unroll
                for (int mi = 0; mi < 2; mi++) {
                    uint32_t ad = aLaneOff + (uint32_t)(mi * 16 * A_ST * 2) + kOffA;
                    LDSM_X4(aF[mi][0], aF[mi][1], aF[mi][2], aF[mi][3], aBase + ad);
                }
                uint32_t bF[4][2];
#pragma unroll
                for (int nb = 0; nb < 2; nb++) {
                    uint32_t bd = (uint32_t)((wn * 32 + nb * 16) * WB_ST + ks * 32);
                    uint32_t r0, r1, r2, r3;
                    LDSM_X4(r0, r1, r2, r3, wbBase + bd);
                    bF[2*nb][0] = r0; bF[2*nb][1] = r1;
                    bF[2*nb+1][0] = r2; bF[2*nb+1][1] = r3;
                }
#pragma unroll
                for (int mi = 0; mi < 2; mi++)
#pragma unroll
                    for (int nj = 0; nj < 4; nj++)
                        MMA_F16(acc[mi][nj], aF[mi], bF[nj]);
            }
            __syncthreads();
        }

        // epilogue for this half
#pragma unroll
        for (int mi = 0; mi < 2; mi++) {
            float p0 = 0.f, p1 = 0.f;
#pragma unroll
            for (int nj = 0; nj < 4; nj++) {
                int col = half * 128 + wn * 32 + nj * 8 + tq * 2;
                float b0 = sBias[col], b1 = sBias[col + 1];
                float v0 = sV[col],    v1 = sV[col + 1];
                p0 += tanh_fast(acc[mi][nj][0] + b0) * v0 + tanh_fast(acc[mi][nj][1] + b1) * v1;
                p1 += tanh_fast(acc[mi][nj][2] + b0) * v0 + tanh_fast(acc[mi][nj][3] + b1) * v1;
            }
            p0 += __shfl_xor_sync(0xffffffffu, p0, 1);
            p0 += __shfl_xor_sync(0xffffffffu, p0, 2);
            p1 += __shfl_xor_sync(0xffffffffu, p1, 1);
            p1 += __shfl_xor_sync(0xffffffffu, p1, 2);
            if (tq == 0) {
                int r0 = wm * 32 + mi * 16 + gp;
                sPart[r0 * 4 + wn]       += p0;
                sPart[(r0 + 8) * 4 + wn] += p1;
            }
        }
    }
    __syncthreads();

    // ---------------- fused softmax-pool over this 128-row chunk ----------------
    float* sSc   = sBias;
    float* sRedS = sV;
    if (tid < 128) {
        float s = sPart[tid * 4] + sPart[tid * 4 + 1] + sPart[tid * 4 + 2] + sPart[tid * 4 + 3] + A.c[0];
        int msk = A.mask[row0 + tid];
        sSc[tid] = msk ? s : NEGV;
    }
    __syncthreads();
    if (tid < 64) sRedS[tid] = fmaxf(sSc[tid], sSc[tid + 64]);
    __syncthreads();
    if (tid < 32) {
        float m = fmaxf(sRedS[tid], sRedS[tid + 32]);
#pragma unroll
        for (int o = 16; o > 0; o >>= 1) m = fmaxf(m, __shfl_xor_sync(0xffffffffu, m, o));
        if (tid == 0) sRedS[0] = m;
    }
    __syncthreads();
    const float lmax = sRedS[0];
    __syncthreads();
    if (tid < 128) {
        float s = sSc[tid];
        sSc[tid] = (s > -1e8f) ? __expf(s - lmax) : 0.f;
    }
    __syncthreads();
    if (tid < 64) sRedS[tid] = sSc[tid] + sSc[tid + 64];
    __syncthreads();
    if (tid < 32) {
        float e = sRedS[tid] + sRedS[tid + 32];
#pragma unroll
        for (int o = 16; o > 0; o >>= 1) e += __shfl_xor_sync(0xffffffffu, e, o);
        if (tid == 0) sRedS[0] = e;
    }
    __syncthreads();
    const float esum = sRedS[0];

    // weighted column sums from fp16 A in smem (4 row-stripes of 32)
    float2* sRed2 = (float2*)(smem + SRED);
    const int c2 = tid & 127;
    const int rh = tid >> 7;
    float ax = 0.f, ay = 0.f;
#pragma unroll 8
    for (int r = 0; r < 32; r++) {
        int row = rh * 32 + r;
        float wv = sSc[row];
        __half2 a2 = *(const __half2*)(smem + SA_OFF + (size_t)(row * A_ST + c2 * 2) * 2);
        float2 af = __half22float2(a2);
        ax += wv * af.x; ay += wv * af.y;
    }
    sRed2[tid] = make_float2(ax, ay);
    __syncthreads();
    if (tid < 128) {
        float2 s0 = sRed2[tid], s1 = sRed2[tid + 128];
        float2 s2 = sRed2[tid + 256], s3 = sRed2[tid + 384];
        float2 out = make_float2(s0.x + s1.x + s2.x + s3.x, s0.y + s1.y + s2.y + s3.y);
        int b = row0 / A.S;
        int chunk = (row0 % A.S) >> 7;
        *(float2*)(g_psum + (((A.pool * BATCH) + b) * 16 + chunk) * HDIM + tid * 2) = out;
        if (tid == 0) {
            g_pmax[A.pool][b][chunk]  = lmax;
            g_pesum[A.pool][b][chunk] = esum;
        }
    }
}

// ---------------- chunk combine helpers ----------------
__device__ __forceinline__ void make_factors(int pool, int b, int nch,
                                             float* fac, float* invden) {
    float gmax = -3.4e38f;
    for (int c = 0; c < nch; c++) gmax = fmaxf(gmax, g_pmax[pool][b][c]);
    float den = 0.f;
    for (int c = 0; c < nch; c++) {
        float f = __expf(g_pmax[pool][b][c] - gmax);
        fac[c] = f;
        den += f * g_pesum[pool][b][c];
    }
    *invden = 1.f / den;
}

__device__ __forceinline__ float combine(int pool, int b, int col, int nch,
                                         const float* fac, float invden) {
    const float* pp = g_psum + (((pool * BATCH) + b) * 16) * HDIM + col;
    float s = 0.f;
#pragma unroll 4
    for (int c = 0; c < nch; c++) s += fac[c] * pp[c * HDIM];
    return s * invden;
}

// ---------------- code = tanh([tok, gr] @ Wf + bf); 512 blocks ----------------
__global__ __launch_bounds__(256) void code_kernel(const float* Wf, const float* bfv) {
    int b  = blockIdx.x >> 3;
    int cg = blockIdx.x & 7;
    const int tid = threadIdx.x;
    const int jg = tid >> 5;
    const int ci = tid & 31;
    const int col = cg * 32 + ci;
    __shared__ float cat[2 * HDIM];
    __shared__ float part[256];
    __shared__ float fac0[16], fac1[4];
    __shared__ float inv0, inv1;

    if (tid == 0) make_factors(0, b, 16, fac0, &inv0);
    if (tid == 32) make_factors(1, b, 4, fac1, &inv1);
    __syncthreads();

    cat[tid]        = tanh_fast(combine(0, b, tid, 16, fac0, inv0));
    cat[HDIM + tid] = tanh_fast(combine(1, b, tid, 4, fac1, inv1));
    __syncthreads();

    float acc = 0.f;
    const float* wp = Wf + col;
    const int j0 = jg * 64;
#pragma unroll 8
    for (int j = 0; j < 64; j++)
        acc += cat[j0 + j] * wp[(size_t)(j0 + j) * HDIM];
    part[tid] = acc;
    __syncthreads();
    if (tid < 32) {
        float s = bfv[cg * 32 + tid];
#pragma unroll
        for (int g = 0; g < 8; g++) s += part[g * 32 + tid];
        g_code[b * HDIM + cg * 32 + tid] = tanh_fast(s);
    }
}

// ---------------- per-batch hinge + last-block finalize ----------------
__global__ __launch_bounds__(256) void loss1_kernel(float* out) {
    const int b = blockIdx.x;
    const int tid = threadIdx.x;
    const int warp = tid >> 5, lane = tid & 31;
    __shared__ float sm[8][5];
    __shared__ float fac2[4], fac3[4];
    __shared__ float inv2, inv3;
    __shared__ int isLast;

    if (tid == 0) make_factors(2, b, 4, fac2, &inv2);
    if (tid == 32) make_factors(3, b, 4, fac3, &inv3);
    __syncthreads();

    float c = g_code[b * HDIM + tid];
    float a = tanh_fast(tanh_fast(combine(2, b, tid, 4, fac2, inv2)));
    float n = tanh_fast(tanh_fast(combine(3, b, tid, 4, fac3, inv3)));
    float s0 = c * c, s1 = a * a, s2 = n * n, s3 = c * a, s4 = c * n;
#pragma unroll
    for (int o = 16; o > 0; o >>= 1) {
        s0 += __shfl_xor_sync(0xffffffffu, s0, o);
        s1 += __shfl_xor_sync(0xffffffffu, s1, o);
        s2 += __shfl_xor_sync(0xffffffffu, s2, o);
        s3 += __shfl_xor_sync(0xffffffffu, s3, o);
        s4 += __shfl_xor_sync(0xffffffffu, s4, o);
    }
    if (lane == 0) {
        sm[warp][0] = s0; sm[warp][1] = s1; sm[warp][2] = s2;
        sm[warp][3] = s3; sm[warp][4] = s4;
    }
    __syncthreads();
    if (tid == 0) {
        float t0 = 0, t1 = 0, t2 = 0, t3 = 0, t4 = 0;
#pragma unroll
        for (int wv = 0; wv < 8; wv++) {
            t0 += sm[wv][0]; t1 += sm[wv][1]; t2 += sm[wv][2];
            t3 += sm[wv][3]; t4 += sm[wv][4];
        }
        float nc = sqrtf(t0);
        float sa = t3 / fmaxf(nc * sqrtf(t1), 1e-8f);
        float sn = t4 / fmaxf(nc * sqrtf(t2), 1e-8f);
        g_hinge[b] = fmaxf(0.6f - sa + sn, 0.f);
        __threadfence();
        isLast = (atomicAdd(&g_cnt, 1) == BATCH - 1) ? 1 : 0;
    }
    __syncthreads();
    if (isLast && tid < 32) {
        float v = g_hinge[tid] + g_hinge[tid + 32];
#pragma unroll
        for (int o = 16; o > 0; o >>= 1) v += __shfl_xor_sync(0xffffffffu, v, o);
        if (tid == 0) {
            out[0] = v / (float)BATCH;
            g_cnt = 0;       // reset for graph replay
        }
    }
}

// ---------------- launch ----------------
extern "C" void kernel_launch(void* const* d_in, const int* in_sizes, int n_in,
                              void* d_out, int out_size) {
    const float* token_feat = (const float*)d_in[0];
    const int*   token_mask = (const int*)d_in[1];
    const float* graph_feat = (const float*)d_in[2];
    const int*   graph_mask = (const int*)d_in[3];
    const float* da_feat    = (const float*)d_in[4];
    const int*   da_mask    = (const int*)d_in[5];
    const float* dn_feat    = (const float*)d_in[6];
    const int*   dn_mask    = (const int*)d_in[7];
    const float* Wt = (const float*)d_in[8];
    const float* bt = (const float*)d_in[9];
    const float* vt = (const float*)d_in[10];
    const float* ct = (const float*)d_in[11];
    const float* Wg = (const float*)d_in[12];
    const float* bg = (const float*)d_in[13];
    const float* vg = (const float*)d_in[14];
    const float* cg = (const float*)d_in[15];
    const float* Wd = (const float*)d_in[16];
    const float* bd = (const float*)d_in[17];
    const float* vd = (const float*)d_in[18];
    const float* cd = (const float*)d_in[19];
    const float* Wf = (const float*)d_in[20];
    const float* bf = (const float*)d_in[21];

    cudaFuncSetAttribute(score_tc, cudaFuncAttributeMaxDynamicSharedMemorySize, SCORE_SMEM);

    __half* wtp = nullptr;
    cudaGetSymbolAddress((void**)&wtp, g_WT);

    wconv_kernel<<<dim3(256, 3), 256>>>(Wt, Wg, Wd);

    const int nTok = BATCH * S_TOK / 128;   // 1024
    const int nOth = BATCH * S_OTH / 128;   // 256

    ScoreArgs sa0 = {token_feat, token_mask, bt, vt, ct, 0, 0,               0,      0, S_TOK};
    ScoreArgs sa1 = {graph_feat, graph_mask, bg, vg, cg, 1, nTok,            65536,  1, S_OTH};
    ScoreArgs sa2 = {da_feat,    da_mask,    bd, vd, cd, 0, nTok + nOth,     131072, 2, S_OTH};
    ScoreArgs sa3 = {dn_feat,    dn_mask,    bd, vd, cd, 0, nTok + 2 * nOth, 131072, 3, S_OTH};
    score_tc<<<nTok + 3 * nOth, 512, SCORE_SMEM>>>(sa0, sa1, sa2, sa3, wtp);

    code_kernel<<<8 * BATCH, 256>>>(Wf, bf);
    loss1_kernel<<<BATCH, 256>>>((float*)d_out);
}

// round 15
// speedup vs baseline: 8.1346x; 1.0022x over previous
#include <cuda_runtime.h>
#include <cuda_fp16.h>
#include <stdint.h>
#include <math.h>

#define HDIM 256
#define BATCH 64
#define S_TOK 2048
#define S_OTH 512
#define NEGV (-1e9f)

// ---------------- scratch (no allocations allowed) ----------------
__device__ float g_code[BATCH*HDIM];
__device__ float g_hinge[BATCH];
__device__ int   g_cnt;
__device__ int   g_bcnt[BATCH];
__device__ float g_pmax[4][BATCH][16];
__device__ float g_pesum[4][BATCH][16];
__device__ float g_psum[4*BATCH*16*HDIM];        // [pool][b][chunk<16][col]
__device__ __half g_WT[3 * 65536];               // W transposed fp16: [mat][n*256+k]

// ---------------- PTX helpers ----------------
__device__ __forceinline__ uint32_t smem_to_u32(const void* p) {
    uint32_t a;
    asm("{ .reg .u64 tmp; cvta.to.shared.u64 tmp, %1; cvt.u32.u64 %0, tmp; }" : "=r"(a) : "l"(p));
    return a;
}
__device__ __forceinline__ float tanh_fast(float x) {
    float y;
    asm("tanh.approx.f32 %0, %1;" : "=f"(y) : "f"(x));
    return y;
}
#define LDSM_X4(r0,r1,r2,r3,addr) \
    asm volatile("ldmatrix.sync.aligned.m8n8.x4.shared.b16 {%0,%1,%2,%3}, [%4];" \
        : "=r"(r0),"=r"(r1),"=r"(r2),"=r"(r3) : "r"(addr))
#define MMA_F16(c, a, b) \
    asm volatile("mma.sync.aligned.m16n8k16.row.col.f32.f16.f16.f32 " \
        "{%0,%1,%2,%3},{%4,%5,%6,%7},{%8,%9},{%0,%1,%2,%3};" \
        : "+f"((c)[0]),"+f"((c)[1]),"+f"((c)[2]),"+f"((c)[3]) \
        : "r"((a)[0]),"r"((a)[1]),"r"((a)[2]),"r"((a)[3]),"r"((b)[0]),"r"((b)[1]))
#define CP_ASYNC16(dst, src) \
    asm volatile("cp.async.cg.shared.global [%0], [%1], 16;" :: "r"(dst), "l"(src) : "memory")
#define CP_COMMIT() asm volatile("cp.async.commit_group;" ::: "memory")
#define CP_WAIT(n)  asm volatile("cp.async.wait_group %0;" :: "n"(n) : "memory")

// ---------------- W transpose to fp16 ----------------
__global__ void wconv_kernel(const float* Wt, const float* Wg, const float* Wd) {
    int mat = blockIdx.y;
    const float* W = (mat == 0) ? Wt : (mat == 1) ? Wg : Wd;
    int k = blockIdx.x, n = threadIdx.x;
    g_WT[mat * 65536 + n * 256 + k] = __float2half_rn(W[k * 256 + n]);
}

// ---------------- fused score + softmax-pool (M=128, 512 threads, 16 warps) ----------------
#define A_ST 264                  // fp16 elems per A row (528 B)
#define WB_ST 272                 // bytes per W row (256 data + 16 pad), K=128 chunk
#define SA_OFF 0                  // 128*264*2 = 67584
#define SW_OFF 67584              // 2 buffers of 34816 (128 rows x 272 B)
#define SW_BUF 34816
#define SBIAS 137216              // 256 floats
#define SVV   138240              // 256 floats
#define SPART 139264              // 512 floats (2048 B)
#define SRED  141312              // 512 float2 (4096 B)
#define SCORE_SMEM 145408

struct ScoreArgs {
    const float* feat;
    const int* mask;
    const float* bv;
    const float* v;
    const float* c;
    int pretanh;
    int blkStart;
    int wtOff;
    int pool;
    int S;
};

__global__ __launch_bounds__(512, 1) void score_tc(ScoreArgs A0, ScoreArgs A1,
                                                   ScoreArgs A2, ScoreArgs A3,
                                                   const __half* WTg) {
    ScoreArgs A;
    int blk = blockIdx.x;
    if (blk >= A3.blkStart)      A = A3;
    else if (blk >= A2.blkStart) A = A2;
    else if (blk >= A1.blkStart) A = A1;
    else                         A = A0;
    const int row0 = (blk - A.blkStart) * 128;

    const int tid  = threadIdx.x;

    // ---- early exit: ragged-prefix mask means mask[row0]==0 => whole chunk masked ----
    {
        int b = row0 / A.S;
        int chunk = (row0 % A.S) >> 7;
        if (A.mask[row0] == 0) {
            if (tid < 128)
                *(float2*)(g_psum + (((A.pool * BATCH) + b) * 16 + chunk) * HDIM + tid * 2)
                    = make_float2(0.f, 0.f);
            if (tid == 0) {
                g_pmax[A.pool][b][chunk]  = NEGV;
                g_pesum[A.pool][b][chunk] = 0.f;
            }
            return;
        }
    }

    extern __shared__ char smem[];
    const uint32_t sbase = smem_to_u32(smem);
    float* sBias = (float*)(smem + SBIAS);
    float* sV    = (float*)(smem + SVV);
    float* sPart = (float*)(smem + SPART);

    const int warp = tid >> 5;
    const int lane = tid & 31;
    const int wm = warp & 3;        // 4 m-warps (32 rows each)
    const int wn = warp >> 2;       // 4 n-warps (32 cols each within a 128-col half)
    const int tq = lane & 3;
    const int gp = lane >> 2;

    const __half* WT = WTg + A.wtOff;
    const int pt = A.pretanh;

    // prefetch W chunk q=0 (half 0, kh 0): 128 n-rows x 128 k
    for (int i = tid; i < 2048; i += 512) {
        int r = i >> 4, j = i & 15;
        const __half* src = WT + (size_t)r * 256 + j * 8;
        uint32_t dst = sbase + SW_OFF + (uint32_t)(r * WB_ST + j * 16);
        CP_ASYNC16(dst, src);
    }
    CP_COMMIT();

    if (tid < 256) { sBias[tid] = A.bv[tid]; sV[tid] = A.v[tid]; }
    sPart[tid] = 0.f;

    // ---- A: 128 rows x 256 cols fp32 -> fp16 into smem ----
    {
        const int ar = tid >> 2;
        const int ac = (tid & 3) * 64;
        const float4* src = (const float4*)(A.feat + (size_t)(row0 + ar) * HDIM + ac);
        float4 av[16];
#pragma unroll
        for (int j = 0; j < 16; j++) av[j] = src[j];
#pragma unroll
        for (int j = 0; j < 16; j++) {
            float4 t = av[j];
            if (pt) {
                t.x = tanh_fast(t.x); t.y = tanh_fast(t.y);
                t.z = tanh_fast(t.z); t.w = tanh_fast(t.w);
            }
            __half2 h0 = __float22half2_rn(make_float2(t.x, t.y));
            __half2 h1 = __float22half2_rn(make_float2(t.z, t.w));
            uint2 hu;
            hu.x = *(uint32_t*)&h0; hu.y = *(uint32_t*)&h1;
            *(uint2*)(smem + SA_OFF + (size_t)(ar * A_ST + ac + j * 4) * 2) = hu;
        }
    }

    const uint32_t aBase = sbase + SA_OFF;
    const uint32_t aLaneOff = (uint32_t)(((wm * 32 + (lane & 15)) * A_ST + ((lane >> 4) << 3)) * 2);
    const uint32_t bLane = (uint32_t)(((lane & 7) + ((lane >> 4) << 3)) * WB_ST + (((lane >> 3) & 1) << 4));

    float acc[2][4][4];

    for (int half = 0; half < 2; half++) {
#pragma unroll
        for (int mi = 0; mi < 2; mi++)
#pragma unroll
            for (int nj = 0; nj < 4; nj++) {
                acc[mi][nj][0] = 0.f; acc[mi][nj][1] = 0.f;
                acc[mi][nj][2] = 0.f; acc[mi][nj][3] = 0.f;
            }
        for (int kh = 0; kh < 2; kh++) {
            const int q = half * 2 + kh;
            const int buf = q & 1;
            if (q < 3) {
                const int nh = (q + 1) >> 1, nkh = (q + 1) & 1, nb2 = (q + 1) & 1;
                for (int i = tid; i < 2048; i += 512) {
                    int r = i >> 4, j = i & 15;
                    const __half* src = WT + (size_t)(nh * 128 + r) * 256 + nkh * 128 + j * 8;
                    uint32_t dst = sbase + SW_OFF + nb2 * SW_BUF + (uint32_t)(r * WB_ST + j * 16);
                    CP_ASYNC16(dst, src);
                }
                CP_COMMIT();
                CP_WAIT(1);
            } else {
                CP_WAIT(0);
            }
            __syncthreads();

            const uint32_t wbBase = sbase + SW_OFF + buf * SW_BUF + bLane;

#pragma unroll
            for (int ks = 0; ks < 8; ks++) {
                const uint32_t kOffA = (uint32_t)(kh * 256 + ks * 32);
                uint32_t aF[2][4];
#pragma unroll
                for (int mi = 0; mi < 2; mi++) {
                    uint32_t ad = aLaneOff + (uint32_t)(mi * 16 * A_ST * 2) + kOffA;
                    LDSM_X4(aF[mi][0], aF[mi][1], aF[mi][2], aF[mi][3], aBase + ad);
                }
                uint32_t bF[4][2];
#pragma unroll
                for (int nb = 0; nb < 2; nb++) {
                    uint32_t bd = (uint32_t)((wn * 32 + nb * 16) * WB_ST + ks * 32);
                    uint32_t r0, r1, r2, r3;
                    LDSM_X4(r0, r1, r2, r3, wbBase + bd);
                    bF[2*nb][0] = r0; bF[2*nb][1] = r1;
                    bF[2*nb+1][0] = r2; bF[2*nb+1][1] = r3;
                }
#pragma unroll
                for (int mi = 0; mi < 2; mi++)
#pragma unroll
                    for (int nj = 0; nj < 4; nj++)
                        MMA_F16(acc[mi][nj], aF[mi], bF[nj]);
            }
            __syncthreads();
        }

        // epilogue for this half
#pragma unroll
        for (int mi = 0; mi < 2; mi++) {
            float p0 = 0.f, p1 = 0.f;
#pragma unroll
            for (int nj = 0; nj < 4; nj++) {
                int col = half * 128 + wn * 32 + nj * 8 + tq * 2;
                float b0 = sBias[col], b1 = sBias[col + 1];
                float v0 = sV[col],    v1 = sV[col + 1];
                p0 += tanh_fast(acc[mi][nj][0] + b0) * v0 + tanh_fast(acc[mi][nj][1] + b1) * v1;
                p1 += tanh_fast(acc[mi][nj][2] + b0) * v0 + tanh_fast(acc[mi][nj][3] + b1) * v1;
            }
            p0 += __shfl_xor_sync(0xffffffffu, p0, 1);
            p0 += __shfl_xor_sync(0xffffffffu, p0, 2);
            p1 += __shfl_xor_sync(0xffffffffu, p1, 1);
            p1 += __shfl_xor_sync(0xffffffffu, p1, 2);
            if (tq == 0) {
                int r0 = wm * 32 + mi * 16 + gp;
                sPart[r0 * 4 + wn]       += p0;
                sPart[(r0 + 8) * 4 + wn] += p1;
            }
        }
    }
    __syncthreads();

    // ---------------- fused softmax-pool over this 128-row chunk ----------------
    float* sSc   = sBias;
    float* sRedS = sV;
    if (tid < 128) {
        float s = sPart[tid * 4] + sPart[tid * 4 + 1] + sPart[tid * 4 + 2] + sPart[tid * 4 + 3] + A.c[0];
        int msk = A.mask[row0 + tid];
        sSc[tid] = msk ? s : NEGV;
    }
    __syncthreads();
    if (tid < 64) sRedS[tid] = fmaxf(sSc[tid], sSc[tid + 64]);
    __syncthreads();
    if (tid < 32) {
        float m = fmaxf(sRedS[tid], sRedS[tid + 32]);
#pragma unroll
        for (int o = 16; o > 0; o >>= 1) m = fmaxf(m, __shfl_xor_sync(0xffffffffu, m, o));
        if (tid == 0) sRedS[0] = m;
    }
    __syncthreads();
    const float lmax = sRedS[0];
    __syncthreads();
    if (tid < 128) {
        float s = sSc[tid];
        sSc[tid] = (s > -1e8f) ? __expf(s - lmax) : 0.f;
    }
    __syncthreads();
    if (tid < 64) sRedS[tid] = sSc[tid] + sSc[tid + 64];
    __syncthreads();
    if (tid < 32) {
        float e = sRedS[tid] + sRedS[tid + 32];
#pragma unroll
        for (int o = 16; o > 0; o >>= 1) e += __shfl_xor_sync(0xffffffffu, e, o);
        if (tid == 0) sRedS[0] = e;
    }
    __syncthreads();
    const float esum = sRedS[0];

    // weighted column sums from fp16 A in smem (4 row-stripes of 32)
    float2* sRed2 = (float2*)(smem + SRED);
    const int c2 = tid & 127;
    const int rh = tid >> 7;
    float ax = 0.f, ay = 0.f;
#pragma unroll 8
    for (int r = 0; r < 32; r++) {
        int row = rh * 32 + r;
        float wv = sSc[row];
        __half2 a2 = *(const __half2*)(smem + SA_OFF + (size_t)(row * A_ST + c2 * 2) * 2);
        float2 af = __half22float2(a2);
        ax += wv * af.x; ay += wv * af.y;
    }
    sRed2[tid] = make_float2(ax, ay);
    __syncthreads();
    if (tid < 128) {
        float2 s0 = sRed2[tid], s1 = sRed2[tid + 128];
        float2 s2 = sRed2[tid + 256], s3 = sRed2[tid + 384];
        float2 out = make_float2(s0.x + s1.x + s2.x + s3.x, s0.y + s1.y + s2.y + s3.y);
        int b = row0 / A.S;
        int chunk = (row0 % A.S) >> 7;
        *(float2*)(g_psum + (((A.pool * BATCH) + b) * 16 + chunk) * HDIM + tid * 2) = out;
        if (tid == 0) {
            g_pmax[A.pool][b][chunk]  = lmax;
            g_pesum[A.pool][b][chunk] = esum;
        }
    }
}

// ---------------- chunk combine helpers ----------------
__device__ __forceinline__ void make_factors(int pool, int b, int nch,
                                             float* fac, float* invden) {
    float gmax = -3.4e38f;
    for (int c = 0; c < nch; c++) gmax = fmaxf(gmax, g_pmax[pool][b][c]);
    float den = 0.f;
    for (int c = 0; c < nch; c++) {
        float f = __expf(g_pmax[pool][b][c] - gmax);
        fac[c] = f;
        den += f * g_pesum[pool][b][c];
    }
    *invden = 1.f / den;
}

__device__ __forceinline__ float combine(int pool, int b, int col, int nch,
                                         const float* fac, float invden) {
    const float* pp = g_psum + (((pool * BATCH) + b) * 16) * HDIM + col;
    float s = 0.f;
#pragma unroll 4
    for (int c = 0; c < nch; c++) s += fac[c] * pp[c * HDIM];
    return s * invden;
}

// ---------------- fused code + hinge + finalize (512 blocks) ----------------
__global__ __launch_bounds__(256) void tail_kernel(const float* Wf, const float* bfv,
                                                   float* out) {
    int b  = blockIdx.x >> 3;
    int cg = blockIdx.x & 7;
    const int tid = threadIdx.x;
    const int jg = tid >> 5;
    const int ci = tid & 31;
    const int col = cg * 32 + ci;
    __shared__ float cat[2 * HDIM];
    __shared__ float part[256];
    __shared__ float fac0[16], fac1[4];
    __shared__ float inv0, inv1;
    __shared__ int doHinge;

    if (tid == 0) make_factors(0, b, 16, fac0, &inv0);
    if (tid == 32) make_factors(1, b, 4, fac1, &inv1);
    __syncthreads();

    cat[tid]        = tanh_fast(combine(0, b, tid, 16, fac0, inv0));
    cat[HDIM + tid] = tanh_fast(combine(1, b, tid, 4, fac1, inv1));
    __syncthreads();

    float acc = 0.f;
    const float* wp = Wf + col;
    const int j0 = jg * 64;
#pragma unroll 8
    for (int j = 0; j < 64; j++)
        acc += cat[j0 + j] * wp[(size_t)(j0 + j) * HDIM];
    part[tid] = acc;
    __syncthreads();
    if (tid < 32) {
        float s = bfv[cg * 32 + tid];
#pragma unroll
        for (int g = 0; g < 8; g++) s += part[g * 32 + tid];
        g_code[b * HDIM + cg * 32 + tid] = tanh_fast(s);
    }

    // ---- last-block-per-batch computes hinge for b ----
    __syncthreads();
    if (tid == 0) {
        __threadfence();
        doHinge = (atomicAdd(&g_bcnt[b], 1) == 7) ? 1 : 0;
    }
    __syncthreads();
    if (!doHinge) return;

    // this block sees all 8 code-column groups of batch b
    {
        __shared__ float sm[8][5];
        __shared__ float fac2[4], fac3[4];
        __shared__ float inv2, inv3;
        __shared__ int isLast;
        const int warp = tid >> 5, lane = tid & 31;

        if (tid == 0) { make_factors(2, b, 4, fac2, &inv2); g_bcnt[b] = 0; }
        if (tid == 32) make_factors(3, b, 4, fac3, &inv3);
        __syncthreads();

        float c = g_code[b * HDIM + tid];
        float a = tanh_fast(tanh_fast(combine(2, b, tid, 4, fac2, inv2)));
        float n = tanh_fast(tanh_fast(combine(3, b, tid, 4, fac3, inv3)));
        float s0 = c * c, s1 = a * a, s2 = n * n, s3 = c * a, s4 = c * n;
#pragma unroll
        for (int o = 16; o > 0; o >>= 1) {
            s0 += __shfl_xor_sync(0xffffffffu, s0, o);
            s1 += __shfl_xor_sync(0xffffffffu, s1, o);
            s2 += __shfl_xor_sync(0xffffffffu, s2, o);
            s3 += __shfl_xor_sync(0xffffffffu, s3, o);
            s4 += __shfl_xor_sync(0xffffffffu, s4, o);
        }
        if (lane == 0) {
            sm[warp][0] = s0; sm[warp][1] = s1; sm[warp][2] = s2;
            sm[warp][3] = s3; sm[warp][4] = s4;
        }
        __syncthreads();
        if (tid == 0) {
            float t0 = 0, t1 = 0, t2 = 0, t3 = 0, t4 = 0;
#pragma unroll
            for (int wv = 0; wv < 8; wv++) {
                t0 += sm[wv][0]; t1 += sm[wv][1]; t2 += sm[wv][2];
                t3 += sm[wv][3]; t4 += sm[wv][4];
            }
            float nc = sqrtf(t0);
            float sa = t3 / fmaxf(nc * sqrtf(t1), 1e-8f);
            float sn = t4 / fmaxf(nc * sqrtf(t2), 1e-8f);
            g_hinge[b] = fmaxf(0.6f - sa + sn, 0.f);
            __threadfence();
            isLast = (atomicAdd(&g_cnt, 1) == BATCH - 1) ? 1 : 0;
        }
        __syncthreads();
        if (isLast && tid < 32) {
            float v = g_hinge[tid] + g_hinge[tid + 32];
#pragma unroll
            for (int o = 16; o > 0; o >>= 1) v += __shfl_xor_sync(0xffffffffu, v, o);
            if (tid == 0) {
                out[0] = v / (float)BATCH;
                g_cnt = 0;       // reset for graph replay
            }
        }
    }
}

// ---------------- launch ----------------
extern "C" void kernel_launch(void* const* d_in, const int* in_sizes, int n_in,
                              void* d_out, int out_size) {
    const float* token_feat = (const float*)d_in[0];
    const int*   token_mask = (const int*)d_in[1];
    const float* graph_feat = (const float*)d_in[2];
    const int*   graph_mask = (const int*)d_in[3];
    const float* da_feat    = (const float*)d_in[4];
    const int*   da_mask    = (const int*)d_in[5];
    const float* dn_feat    = (const float*)d_in[6];
    const int*   dn_mask    = (const int*)d_in[7];
    const float* Wt = (const float*)d_in[8];
    const float* bt = (const float*)d_in[9];
    const float* vt = (const float*)d_in[10];
    const float* ct = (const float*)d_in[11];
    const float* Wg = (const float*)d_in[12];
    const float* bg = (const float*)d_in[13];
    const float* vg = (const float*)d_in[14];
    const float* cg = (const float*)d_in[15];
    const float* Wd = (const float*)d_in[16];
    const float* bd = (const float*)d_in[17];
    const float* vd = (const float*)d_in[18];
    const float* cd = (const float*)d_in[19];
    const float* Wf = (const float*)d_in[20];
    const float* bf = (const float*)d_in[21];

    cudaFuncSetAttribute(score_tc, cudaFuncAttributeMaxDynamicSharedMemorySize, SCORE_SMEM);

    __half* wtp = nullptr;
    cudaGetSymbolAddress((void**)&wtp, g_WT);

    wconv_kernel<<<dim3(256, 3), 256>>>(Wt, Wg, Wd);

    const int nTok = BATCH * S_TOK / 128;   // 1024
    const int nOth = BATCH * S_OTH / 128;   // 256

    ScoreArgs sa0 = {token_feat, token_mask, bt, vt, ct, 0, 0,               0,      0, S_TOK};
    ScoreArgs sa1 = {graph_feat, graph_mask, bg, vg, cg, 1, nTok,            65536,  1, S_OTH};
    ScoreArgs sa2 = {da_feat,    da_mask,    bd, vd, cd, 0, nTok + nOth,     131072, 2, S_OTH};
    ScoreArgs sa3 = {dn_feat,    dn_mask,    bd, vd, cd, 0, nTok + 2 * nOth, 131072, 3, S_OTH};
    score_tc<<<nTok + 3 * nOth, 512, SCORE_SMEM>>>(sa0, sa1, sa2, sa3, wtp);

    tail_kernel<<<8 * BATCH, 256>>>(Wf, bf, (float*)d_out);
}

// round 16
// speedup vs baseline: 8.1473x; 1.0016x over previous
#include <cuda_runtime.h>
#include <cuda_fp16.h>
#include <stdint.h>
#include <math.h>

#define HDIM 256
#define BATCH 64
#define S_TOK 2048
#define S_OTH 512
#define NEGV (-1e9f)

// ---------------- scratch (no allocations allowed) ----------------
__device__ float g_code[BATCH*HDIM];
__device__ float g_hinge[BATCH];
__device__ int   g_cnt;
__device__ int   g_bcnt[BATCH];
__device__ float g_pmax[4][BATCH][16];
__device__ float g_pesum[4][BATCH][16];
__device__ float g_psum[4*BATCH*16*HDIM];        // [pool][b][chunk<16][col]
__device__ __half g_WT[3 * 65536];               // W transposed fp16: [mat][n*256+k]

// ---------------- PTX helpers ----------------
__device__ __forceinline__ uint32_t smem_to_u32(const void* p) {
    uint32_t a;
    asm("{ .reg .u64 tmp; cvta.to.shared.u64 tmp, %1; cvt.u32.u64 %0, tmp; }" : "=r"(a) : "l"(p));
    return a;
}
__device__ __forceinline__ float tanh_fast(float x) {
    float y;
    asm("tanh.approx.f32 %0, %1;" : "=f"(y) : "f"(x));
    return y;
}
#define LDSM_X4(r0,r1,r2,r3,addr) \
    asm volatile("ldmatrix.sync.aligned.m8n8.x4.shared.b16 {%0,%1,%2,%3}, [%4];" \
        : "=r"(r0),"=r"(r1),"=r"(r2),"=r"(r3) : "r"(addr))
#define MMA_F16(c, a, b) \
    asm volatile("mma.sync.aligned.m16n8k16.row.col.f32.f16.f16.f32 " \
        "{%0,%1,%2,%3},{%4,%5,%6,%7},{%8,%9},{%0,%1,%2,%3};" \
        : "+f"((c)[0]),"+f"((c)[1]),"+f"((c)[2]),"+f"((c)[3]) \
        : "r"((a)[0]),"r"((a)[1]),"r"((a)[2]),"r"((a)[3]),"r"((b)[0]),"r"((b)[1]))
#define CP_ASYNC16(dst, src) \
    asm volatile("cp.async.cg.shared.global [%0], [%1], 16;" :: "r"(dst), "l"(src) : "memory")
#define CP_COMMIT() asm volatile("cp.async.commit_group;" ::: "memory")
#define CP_WAIT(n)  asm volatile("cp.async.wait_group %0;" :: "n"(n) : "memory")

// ---------------- W transpose to fp16 (coalesced via smem tile) ----------------
// grid: (64 tiles, 3 mats); block 256 = 32x8. Tile = 32x32.
__global__ __launch_bounds__(256) void wconv_kernel(const float* Wt, const float* Wg,
                                                    const float* Wd) {
    int mat = blockIdx.y;
    const float* W = (mat == 0) ? Wt : (mat == 1) ? Wg : Wd;
    int tk0 = (blockIdx.x >> 3) * 32;     // k-tile origin (row of W)
    int tn0 = (blockIdx.x & 7) * 32;      // n-tile origin (col of W)

    __shared__ __half tile[32][33];

    const int tx = threadIdx.x & 31;      // within-row
    const int ty = threadIdx.x >> 5;      // row group (8 rows at a time)

    // coalesced read: rows of W (k-major), convert to fp16
#pragma unroll
    for (int r = 0; r < 4; r++) {
        int k = tk0 + ty + r * 8;
        tile[ty + r * 8][tx] = __float2half_rn(W[(size_t)k * 256 + tn0 + tx]);
    }
    __syncthreads();

    // coalesced write: rows of WT (n-major)
#pragma unroll
    for (int r = 0; r < 4; r++) {
        int n = tn0 + ty + r * 8;
        g_WT[mat * 65536 + (size_t)n * 256 + tk0 + tx] = tile[tx][ty + r * 8];
    }
}

// ---------------- fused score + softmax-pool (M=128, 512 threads, 16 warps) ----------------
#define A_ST 264                  // fp16 elems per A row (528 B)
#define WB_ST 272                 // bytes per W row (256 data + 16 pad), K=128 chunk
#define SA_OFF 0                  // 128*264*2 = 67584
#define SW_OFF 67584              // 2 buffers of 34816 (128 rows x 272 B)
#define SW_BUF 34816
#define SBIAS 137216              // 256 floats
#define SVV   138240              // 256 floats
#define SPART 139264              // 512 floats (2048 B)
#define SRED  141312              // 512 float2 (4096 B)
#define SCORE_SMEM 145408

struct ScoreArgs {
    const float* feat;
    const int* mask;
    const float* bv;
    const float* v;
    const float* c;
    int pretanh;
    int blkStart;
    int wtOff;
    int pool;
    int S;
};

__global__ __launch_bounds__(512, 1) void score_tc(ScoreArgs A0, ScoreArgs A1,
                                                   ScoreArgs A2, ScoreArgs A3,
                                                   const __half* WTg) {
    ScoreArgs A;
    int blk = blockIdx.x;
    if (blk >= A3.blkStart)      A = A3;
    else if (blk >= A2.blkStart) A = A2;
    else if (blk >= A1.blkStart) A = A1;
    else                         A = A0;
    const int row0 = (blk - A.blkStart) * 128;

    const int tid  = threadIdx.x;

    // ---- early exit: ragged-prefix mask means mask[row0]==0 => whole chunk masked ----
    {
        int b = row0 / A.S;
        int chunk = (row0 % A.S) >> 7;
        if (A.mask[row0] == 0) {
            if (tid < 128)
                *(float2*)(g_psum + (((A.pool * BATCH) + b) * 16 + chunk) * HDIM + tid * 2)
                    = make_float2(0.f, 0.f);
            if (tid == 0) {
                g_pmax[A.pool][b][chunk]  = NEGV;
                g_pesum[A.pool][b][chunk] = 0.f;
            }
            return;
        }
    }

    extern __shared__ char smem[];
    const uint32_t sbase = smem_to_u32(smem);
    float* sBias = (float*)(smem + SBIAS);
    float* sV    = (float*)(smem + SVV);
    float* sPart = (float*)(smem + SPART);

    const int warp = tid >> 5;
    const int lane = tid & 31;
    const int wm = warp & 3;        // 4 m-warps (32 rows each)
    const int wn = warp >> 2;       // 4 n-warps (32 cols each within a 128-col half)
    const int tq = lane & 3;
    const int gp = lane >> 2;

    const __half* WT = WTg + A.wtOff;
    const int pt = A.pretanh;

    // prefetch W chunk q=0 (half 0, kh 0): 128 n-rows x 128 k
    for (int i = tid; i < 2048; i += 512) {
        int r = i >> 4, j = i & 15;
        const __half* src = WT + (size_t)r * 256 + j * 8;
        uint32_t dst = sbase + SW_OFF + (uint32_t)(r * WB_ST + j * 16);
        CP_ASYNC16(dst, src);
    }
    CP_COMMIT();

    if (tid < 256) { sBias[tid] = A.bv[tid]; sV[tid] = A.v[tid]; }
    sPart[tid] = 0.f;

    // ---- A: 128 rows x 256 cols fp32 -> fp16 into smem ----
    {
        const int ar = tid >> 2;
        const int ac = (tid & 3) * 64;
        const float4* src = (const float4*)(A.feat + (size_t)(row0 + ar) * HDIM + ac);
        float4 av[16];
#pragma unroll
        for (int j = 0; j < 16; j++) av[j] = src[j];
#pragma unroll
        for (int j = 0; j < 16; j++) {
            float4 t = av[j];
            if (pt) {
                t.x = tanh_fast(t.x); t.y = tanh_fast(t.y);
                t.z = tanh_fast(t.z); t.w = tanh_fast(t.w);
            }
            __half2 h0 = __float22half2_rn(make_float2(t.x, t.y));
            __half2 h1 = __float22half2_rn(make_float2(t.z, t.w));
            uint2 hu;
            hu.x = *(uint32_t*)&h0; hu.y = *(uint32_t*)&h1;
            *(uint2*)(smem + SA_OFF + (size_t)(ar * A_ST + ac + j * 4) * 2) = hu;
        }
    }

    const uint32_t aBase = sbase + SA_OFF;
    const uint32_t aLaneOff = (uint32_t)(((wm * 32 + (lane & 15)) * A_ST + ((lane >> 4) << 3)) * 2);
    const uint32_t bLane = (uint32_t)(((lane & 7) + ((lane >> 4) << 3)) * WB_ST + (((lane >> 3) & 1) << 4));

    float acc[2][4][4];

    for (int half = 0; half < 2; half++) {
#pragma unroll
        for (int mi = 0; mi < 2; mi++)
#pragma unroll
            for (int nj = 0; nj < 4; nj++) {
                acc[mi][nj][0] = 0.f; acc[mi][nj][1] = 0.f;
                acc[mi][nj][2] = 0.f; acc[mi][nj][3] = 0.f;
            }
        for (int kh = 0; kh < 2; kh++) {
            const int q = half * 2 + kh;
            const int buf = q & 1;
            if (q < 3) {
                const int nh = (q + 1) >> 1, nkh = (q + 1) & 1, nb2 = (q + 1) & 1;
                for (int i = tid; i < 2048; i += 512) {
                    int r = i >> 4, j = i & 15;
                    const __half* src = WT + (size_t)(nh * 128 + r) * 256 + nkh * 128 + j * 8;
                    uint32_t dst = sbase + SW_OFF + nb2 * SW_BUF + (uint32_t)(r * WB_ST + j * 16);
                    CP_ASYNC16(dst, src);
                }
                CP_COMMIT();
                CP_WAIT(1);
            } else {
                CP_WAIT(0);
            }
            __syncthreads();

            const uint32_t wbBase = sbase + SW_OFF + buf * SW_BUF + bLane;

#pragma unroll
            for (int ks = 0; ks < 8; ks++) {
                const uint32_t kOffA = (uint32_t)(kh * 256 + ks * 32);
                uint32_t aF[2][4];
#pragma unroll
                for (int mi = 0; mi < 2; mi++) {
                    uint32_t ad = aLaneOff + (uint32_t)(mi * 16 * A_ST * 2) + kOffA;
                    LDSM_X4(aF[mi][0], aF[mi][1], aF[mi][2], aF[mi][3], aBase + ad);
                }
                uint32_t bF[4][2];
#pragma unroll
                for (int nb = 0; nb < 2; nb++) {
                    uint32_t bd = (uint32_t)((wn * 32 + nb * 16) * WB_ST + ks * 32);
                    uint32_t r0, r1, r2, r3;
                    LDSM_X4(r0, r1, r2, r3, wbBase + bd);
                    bF[2*nb][0] = r0; bF[2*nb][1] = r1;
                    bF[2*nb+1][0] = r2; bF[2*nb+1][1] = r3;
                }
#pragma unroll
                for (int mi = 0; mi < 2; mi++)
#pragma unroll
                    for (int nj = 0; nj < 4; nj++)
                        MMA_F16(acc[mi][nj], aF[mi], bF[nj]);
            }
            __syncthreads();
        }

        // epilogue for this half
#pragma unroll
        for (int mi = 0; mi < 2; mi++) {
            float p0 = 0.f, p1 = 0.f;
#pragma unroll
            for (int nj = 0; nj < 4; nj++) {
                int col = half * 128 + wn * 32 + nj * 8 + tq * 2;
                float b0 = sBias[col], b1 = sBias[col + 1];
                float v0 = sV[col],    v1 = sV[col + 1];
                p0 += tanh_fast(acc[mi][nj][0] + b0) * v0 + tanh_fast(acc[mi][nj][1] + b1) * v1;
                p1 += tanh_fast(acc[mi][nj][2] + b0) * v0 + tanh_fast(acc[mi][nj][3] + b1) * v1;
            }
            p0 += __shfl_xor_sync(0xffffffffu, p0, 1);
            p0 += __shfl_xor_sync(0xffffffffu, p0, 2);
            p1 += __shfl_xor_sync(0xffffffffu, p1, 1);
            p1 += __shfl_xor_sync(0xffffffffu, p1, 2);
            if (tq == 0) {
                int r0 = wm * 32 + mi * 16 + gp;
                sPart[r0 * 4 + wn]       += p0;
                sPart[(r0 + 8) * 4 + wn] += p1;
            }
        }
    }
    __syncthreads();

    // ---------------- fused softmax-pool over this 128-row chunk ----------------
    float* sSc   = sBias;
    float* sRedS = sV;
    if (tid < 128) {
        float s = sPart[tid * 4] + sPart[tid * 4 + 1] + sPart[tid * 4 + 2] + sPart[tid * 4 + 3] + A.c[0];
        int msk = A.mask[row0 + tid];
        sSc[tid] = msk ? s : NEGV;
    }
    __syncthreads();
    if (tid < 64) sRedS[tid] = fmaxf(sSc[tid], sSc[tid + 64]);
    __syncthreads();
    if (tid < 32) {
        float m = fmaxf(sRedS[tid], sRedS[tid + 32]);
#pragma unroll
        for (int o = 16; o > 0; o >>= 1) m = fmaxf(m, __shfl_xor_sync(0xffffffffu, m, o));
        if (tid == 0) sRedS[0] = m;
    }
    __syncthreads();
    const float lmax = sRedS[0];
    __syncthreads();
    if (tid < 128) {
        float s = sSc[tid];
        sSc[tid] = (s > -1e8f) ? __expf(s - lmax) : 0.f;
    }
    __syncthreads();
    if (tid < 64) sRedS[tid] = sSc[tid] + sSc[tid + 64];
    __syncthreads();
    if (tid < 32) {
        float e = sRedS[tid] + sRedS[tid + 32];
#pragma unroll
        for (int o = 16; o > 0; o >>= 1) e += __shfl_xor_sync(0xffffffffu, e, o);
        if (tid == 0) sRedS[0] = e;
    }
    __syncthreads();
    const float esum = sRedS[0];

    // weighted column sums from fp16 A in smem (4 row-stripes of 32)
    float2* sRed2 = (float2*)(smem + SRED);
    const int c2 = tid & 127;
    const int rh = tid >> 7;
    float ax = 0.f, ay = 0.f;
#pragma unroll 8
    for (int r = 0; r < 32; r++) {
        int row = rh * 32 + r;
        float wv = sSc[row];
        __half2 a2 = *(const __half2*)(smem + SA_OFF + (size_t)(row * A_ST + c2 * 2) * 2);
        float2 af = __half22float2(a2);
        ax += wv * af.x; ay += wv * af.y;
    }
    sRed2[tid] = make_float2(ax, ay);
    __syncthreads();
    if (tid < 128) {
        float2 s0 = sRed2[tid], s1 = sRed2[tid + 128];
        float2 s2 = sRed2[tid + 256], s3 = sRed2[tid + 384];
        float2 out = make_float2(s0.x + s1.x + s2.x + s3.x, s0.y + s1.y + s2.y + s3.y);
        int b = row0 / A.S;
        int chunk = (row0 % A.S) >> 7;
        *(float2*)(g_psum + (((A.pool * BATCH) + b) * 16 + chunk) * HDIM + tid * 2) = out;
        if (tid == 0) {
            g_pmax[A.pool][b][chunk]  = lmax;
            g_pesum[A.pool][b][chunk] = esum;
        }
    }
}

// ---------------- chunk combine helpers ----------------
__device__ __forceinline__ void make_factors(int pool, int b, int nch,
                                             float* fac, float* invden) {
    float gmax = -3.4e38f;
    for (int c = 0; c < nch; c++) gmax = fmaxf(gmax, g_pmax[pool][b][c]);
    float den = 0.f;
    for (int c = 0; c < nch; c++) {
        float f = __expf(g_pmax[pool][b][c] - gmax);
        fac[c] = f;
        den += f * g_pesum[pool][b][c];
    }
    *invden = 1.f / den;
}

__device__ __forceinline__ float combine(int pool, int b, int col, int nch,
                                         const float* fac, float invden) {
    const float* pp = g_psum + (((pool * BATCH) + b) * 16) * HDIM + col;
    float s = 0.f;
#pragma unroll 4
    for (int c = 0; c < nch; c++) s += fac[c] * pp[c * HDIM];
    return s * invden;
}

// ---------------- fused code + hinge + finalize (512 blocks) ----------------
__global__ __launch_bounds__(256) void tail_kernel(const float* Wf, const float* bfv,
                                                   float* out) {
    int b  = blockIdx.x >> 3;
    int cg = blockIdx.x & 7;
    const int tid = threadIdx.x;
    const int jg = tid >> 5;
    const int ci = tid & 31;
    const int col = cg * 32 + ci;
    __shared__ float cat[2 * HDIM];
    __shared__ float part[256];
    __shared__ float fac0[16], fac1[4];
    __shared__ float inv0, inv1;
    __shared__ int doHinge;

    if (tid == 0) make_factors(0, b, 16, fac0, &inv0);
    if (tid == 32) make_factors(1, b, 4, fac1, &inv1);
    __syncthreads();

    cat[tid]        = tanh_fast(combine(0, b, tid, 16, fac0, inv0));
    cat[HDIM + tid] = tanh_fast(combine(1, b, tid, 4, fac1, inv1));
    __syncthreads();

    float acc = 0.f;
    const float* wp = Wf + col;
    const int j0 = jg * 64;
#pragma unroll 8
    for (int j = 0; j < 64; j++)
        acc += cat[j0 + j] * wp[(size_t)(j0 + j) * HDIM];
    part[tid] = acc;
    __syncthreads();
    if (tid < 32) {
        float s = bfv[cg * 32 + tid];
#pragma unroll
        for (int g = 0; g < 8; g++) s += part[g * 32 + tid];
        g_code[b * HDIM + cg * 32 + tid] = tanh_fast(s);
    }

    // ---- last-block-per-batch computes hinge for b ----
    __syncthreads();
    if (tid == 0) {
        __threadfence();
        doHinge = (atomicAdd(&g_bcnt[b], 1) == 7) ? 1 : 0;
    }
    __syncthreads();
    if (!doHinge) return;

    {
        __shared__ float sm[8][5];
        __shared__ float fac2[4], fac3[4];
        __shared__ float inv2, inv3;
        __shared__ int isLast;
        const int warp = tid >> 5, lane = tid & 31;

        if (tid == 0) { make_factors(2, b, 4, fac2, &inv2); g_bcnt[b] = 0; }
        if (tid == 32) make_factors(3, b, 4, fac3, &inv3);
        __syncthreads();

        float c = g_code[b * HDIM + tid];
        float a = tanh_fast(tanh_fast(combine(2, b, tid, 4, fac2, inv2)));
        float n = tanh_fast(tanh_fast(combine(3, b, tid, 4, fac3, inv3)));
        float s0 = c * c, s1 = a * a, s2 = n * n, s3 = c * a, s4 = c * n;
#pragma unroll
        for (int o = 16; o > 0; o >>= 1) {
            s0 += __shfl_xor_sync(0xffffffffu, s0, o);
            s1 += __shfl_xor_sync(0xffffffffu, s1, o);
            s2 += __shfl_xor_sync(0xffffffffu, s2, o);
            s3 += __shfl_xor_sync(0xffffffffu, s3, o);
            s4 += __shfl_xor_sync(0xffffffffu, s4, o);
        }
        if (lane == 0) {
            sm[warp][0] = s0; sm[warp][1] = s1; sm[warp][2] = s2;
            sm[warp][3] = s3; sm[warp][4] = s4;
        }
        __syncthreads();
        if (tid == 0) {
            float t0 = 0, t1 = 0, t2 = 0, t3 = 0, t4 = 0;
#pragma unroll
            for (int wv = 0; wv < 8; wv++) {
                t0 += sm[wv][0]; t1 += sm[wv][1]; t2 += sm[wv][2];
                t3 += sm[wv][3]; t4 += sm[wv][4];
            }
            float nc = sqrtf(t0);
            float sa = t3 / fmaxf(nc * sqrtf(t1), 1e-8f);
            float sn = t4 / fmaxf(nc * sqrtf(t2), 1e-8f);
            g_hinge[b] = fmaxf(0.6f - sa + sn, 0.f);
            __threadfence();
            isLast = (atomicAdd(&g_cnt, 1) == BATCH - 1) ? 1 : 0;
        }
        __syncthreads();
        if (isLast && tid < 32) {
            float v = g_hinge[tid] + g_hinge[tid + 32];
#pragma unroll
            for (int o = 16; o > 0; o >>= 1) v += __shfl_xor_sync(0xffffffffu, v, o);
            if (tid == 0) {
                out[0] = v / (float)BATCH;
                g_cnt = 0;       // reset for graph replay
            }
        }
    }
}

// ---------------- launch ----------------
extern "C" void kernel_launch(void* const* d_in, const int* in_sizes, int n_in,
                              void* d_out, int out_size) {
    const float* token_feat = (const float*)d_in[0];
    const int*   token_mask = (const int*)d_in[1];
    const float* graph_feat = (const float*)d_in[2];
    const int*   graph_mask = (const int*)d_in[3];
    const float* da_feat    = (const float*)d_in[4];
    const int*   da_mask    = (const int*)d_in[5];
    const float* dn_feat    = (const float*)d_in[6];
    const int*   dn_mask    = (const int*)d_in[7];
    const float* Wt = (const float*)d_in[8];
    const float* bt = (const float*)d_in[9];
    const float* vt = (const float*)d_in[10];
    const float* ct = (const float*)d_in[11];
    const float* Wg = (const float*)d_in[12];
    const float* bg = (const float*)d_in[13];
    const float* vg = (const float*)d_in[14];
    const float* cg = (const float*)d_in[15];
    const float* Wd = (const float*)d_in[16];
    const float* bd = (const float*)d_in[17];
    const float* vd = (const float*)d_in[18];
    const float* cd = (const float*)d_in[19];
    const float* Wf = (const float*)d_in[20];
    const float* bf = (const float*)d_in[21];

    cudaFuncSetAttribute(score_tc, cudaFuncAttributeMaxDynamicSharedMemorySize, SCORE_SMEM);

    __half* wtp = nullptr;
    cudaGetSymbolAddress((void**)&wtp, g_WT);

    wconv_kernel<<<dim3(64, 3), 256>>>(Wt, Wg, Wd);

    const int nTok = BATCH * S_TOK / 128;   // 1024
    const int nOth = BATCH * S_OTH / 128;   // 256

    ScoreArgs sa0 = {token_feat, token_mask, bt, vt, ct, 0, 0,               0,      0, S_TOK};
    ScoreArgs sa1 = {graph_feat, graph_mask, bg, vg, cg, 1, nTok,            65536,  1, S_OTH};
    ScoreArgs sa2 = {da_feat,    da_mask,    bd, vd, cd, 0, nTok + nOth,     131072, 2, S_OTH};
    ScoreArgs sa3 = {dn_feat,    dn_mask,    bd, vd, cd, 0, nTok + 2 * nOth, 131072, 3, S_OTH};
    score_tc<<<nTok + 3 * nOth, 512, SCORE_SMEM>>>(sa0, sa1, sa2, sa3, wtp);

    tail_kernel<<<8 * BATCH, 256>>>(Wf, bf, (float*)d_out);
}

// round 17
// speedup vs baseline: 8.4838x; 1.0413x over previous
#include <cuda_runtime.h>
#include <cuda_fp16.h>
#include <stdint.h>
#include <math.h>

#define HDIM 256
#define BATCH 64
#define S_TOK 2048
#define S_OTH 512
#define NEGV (-1e9f)

// ---------------- scratch (no allocations allowed) ----------------
__device__ float g_code[BATCH*HDIM];
__device__ float g_hinge[BATCH];
__device__ int   g_cnt;
__device__ int   g_bcnt[BATCH];
__device__ float g_pmax[4][BATCH][16];
__device__ float g_pesum[4][BATCH][16];
__device__ float g_psum[4*BATCH*16*HDIM];        // [pool][b][chunk<16][col]
__device__ __half g_WT[3 * 65536];               // W transposed fp16: [mat][n*256+k]

// ---------------- PTX helpers ----------------
__device__ __forceinline__ uint32_t smem_to_u32(const void* p) {
    uint32_t a;
    asm("{ .reg .u64 tmp; cvta.to.shared.u64 tmp, %1; cvt.u32.u64 %0, tmp; }" : "=r"(a) : "l"(p));
    return a;
}
__device__ __forceinline__ float tanh_fast(float x) {
    float y;
    asm("tanh.approx.f32 %0, %1;" : "=f"(y) : "f"(x));
    return y;
}
#define LDSM_X4(r0,r1,r2,r3,addr) \
    asm volatile("ldmatrix.sync.aligned.m8n8.x4.shared.b16 {%0,%1,%2,%3}, [%4];" \
        : "=r"(r0),"=r"(r1),"=r"(r2),"=r"(r3) : "r"(addr))
#define MMA_F16(c, a, b) \
    asm volatile("mma.sync.aligned.m16n8k16.row.col.f32.f16.f16.f32 " \
        "{%0,%1,%2,%3},{%4,%5,%6,%7},{%8,%9},{%0,%1,%2,%3};" \
        : "+f"((c)[0]),"+f"((c)[1]),"+f"((c)[2]),"+f"((c)[3]) \
        : "r"((a)[0]),"r"((a)[1]),"r"((a)[2]),"r"((a)[3]),"r"((b)[0]),"r"((b)[1]))
#define CP_ASYNC16(dst, src) \
    asm volatile("cp.async.cg.shared.global [%0], [%1], 16;" :: "r"(dst), "l"(src) : "memory")
#define CP_COMMIT() asm volatile("cp.async.commit_group;" ::: "memory")
#define CP_WAIT(n)  asm volatile("cp.async.wait_group %0;" :: "n"(n) : "memory")

// ---------------- W transpose to fp16 (coalesced via smem tile) ----------------
__global__ __launch_bounds__(256) void wconv_kernel(const float* Wt, const float* Wg,
                                                    const float* Wd) {
    int mat = blockIdx.y;
    const float* W = (mat == 0) ? Wt : (mat == 1) ? Wg : Wd;
    int tk0 = (blockIdx.x >> 3) * 32;
    int tn0 = (blockIdx.x & 7) * 32;

    __shared__ __half tile[32][33];

    const int tx = threadIdx.x & 31;
    const int ty = threadIdx.x >> 5;

#pragma unroll
    for (int r = 0; r < 4; r++) {
        int k = tk0 + ty + r * 8;
        tile[ty + r * 8][tx] = __float2half_rn(W[(size_t)k * 256 + tn0 + tx]);
    }
    __syncthreads();
#pragma unroll
    for (int r = 0; r < 4; r++) {
        int n = tn0 + ty + r * 8;
        g_WT[mat * 65536 + (size_t)n * 256 + tk0 + tx] = tile[tx][ty + r * 8];
    }
}

// ---------------- fused score + softmax-pool (M=128, 512 threads, 16 warps) ----------------
#define A_ST 264
#define WB_ST 272
#define SA_OFF 0
#define SW_OFF 67584
#define SW_BUF 34816
#define SBIAS 137216
#define SVV   138240
#define SPART 139264
#define SRED  141312
#define SCORE_SMEM 145408

struct ScoreArgs {
    const float* feat;
    const int* mask;
    const float* bv;
    const float* v;
    const float* c;
    int pretanh;
    int blkStart;
    int wtOff;
    int pool;
    int S;
};

__global__ __launch_bounds__(512, 1) void score_tc(ScoreArgs A0, ScoreArgs A1,
                                                   ScoreArgs A2, ScoreArgs A3,
                                                   const __half* WTg) {
    ScoreArgs A;
    int blk = blockIdx.x;
    if (blk >= A3.blkStart)      A = A3;
    else if (blk >= A2.blkStart) A = A2;
    else if (blk >= A1.blkStart) A = A1;
    else                         A = A0;
    const int row0 = (blk - A.blkStart) * 128;

    const int tid  = threadIdx.x;

    // ---- early exit: ragged-prefix mask means mask[row0]==0 => whole chunk masked ----
    {
        int b = row0 / A.S;
        int chunk = (row0 % A.S) >> 7;
        if (A.mask[row0] == 0) {
            if (tid < 128)
                *(float2*)(g_psum + (((A.pool * BATCH) + b) * 16 + chunk) * HDIM + tid * 2)
                    = make_float2(0.f, 0.f);
            if (tid == 0) {
                g_pmax[A.pool][b][chunk]  = NEGV;
                g_pesum[A.pool][b][chunk] = 0.f;
            }
            return;
        }
    }

    extern __shared__ char smem[];
    const uint32_t sbase = smem_to_u32(smem);
    float* sBias = (float*)(smem + SBIAS);
    float* sV    = (float*)(smem + SVV);
    float* sPart = (float*)(smem + SPART);

    const int warp = tid >> 5;
    const int lane = tid & 31;
    const int wm = warp >> 2;       // 4 m-groups (32 rows each), spread across SMSPs
    const int wn = warp & 3;        // 4 n-warps (32 cols each) = SMSP index
    const int tq = lane & 3;
    const int gp = lane >> 2;

    // ragged prefix: if this warp's first row is masked, its whole 32-row group is masked
    const int mActive = (wm == 0) || (A.mask[row0 + wm * 32] != 0);

    const __half* WT = WTg + A.wtOff;
    const int pt = A.pretanh;

    // prefetch W chunk q=0 (half 0, kh 0): 128 n-rows x 128 k
    for (int i = tid; i < 2048; i += 512) {
        int r = i >> 4, j = i & 15;
        const __half* src = WT + (size_t)r * 256 + j * 8;
        uint32_t dst = sbase + SW_OFF + (uint32_t)(r * WB_ST + j * 16);
        CP_ASYNC16(dst, src);
    }
    CP_COMMIT();

    if (tid < 256) { sBias[tid] = A.bv[tid]; sV[tid] = A.v[tid]; }
    sPart[tid] = 0.f;

    // ---- A: 128 rows x 256 cols fp32 -> fp16 into smem ----
    {
        const int ar = tid >> 2;
        const int ac = (tid & 3) * 64;
        const float4* src = (const float4*)(A.feat + (size_t)(row0 + ar) * HDIM + ac);
        float4 av[16];
#pragma unroll
        for (int j = 0; j < 16; j++) av[j] = src[j];
#pragma unroll
        for (int j = 0; j < 16; j++) {
            float4 t = av[j];
            if (pt) {
                t.x = tanh_fast(t.x); t.y = tanh_fast(t.y);
                t.z = tanh_fast(t.z); t.w = tanh_fast(t.w);
            }
            __half2 h0 = __float22half2_rn(make_float2(t.x, t.y));
            __half2 h1 = __float22half2_rn(make_float2(t.z, t.w));
            uint2 hu;
            hu.x = *(uint32_t*)&h0; hu.y = *(uint32_t*)&h1;
            *(uint2*)(smem + SA_OFF + (size_t)(ar * A_ST + ac + j * 4) * 2) = hu;
        }
    }

    const uint32_t aBase = sbase + SA_OFF;
    const uint32_t aLaneOff = (uint32_t)(((wm * 32 + (lane & 15)) * A_ST + ((lane >> 4) << 3)) * 2);
    const uint32_t bLane = (uint32_t)(((lane & 7) + ((lane >> 4) << 3)) * WB_ST + (((lane >> 3) & 1) << 4));

    float acc[2][4][4];

    for (int half = 0; half < 2; half++) {
#pragma unroll
        for (int mi = 0; mi < 2; mi++)
#pragma unroll
            for (int nj = 0; nj < 4; nj++) {
                acc[mi][nj][0] = 0.f; acc[mi][nj][1] = 0.f;
                acc[mi][nj][2] = 0.f; acc[mi][nj][3] = 0.f;
            }
        for (int kh = 0; kh < 2; kh++) {
            const int q = half * 2 + kh;
            const int buf = q & 1;
            if (q < 3) {
                const int nh = (q + 1) >> 1, nkh = (q + 1) & 1, nb2 = (q + 1) & 1;
                for (int i = tid; i < 2048; i += 512) {
                    int r = i >> 4, j = i & 15;
                    const __half* src = WT + (size_t)(nh * 128 + r) * 256 + nkh * 128 + j * 8;
                    uint32_t dst = sbase + SW_OFF + nb2 * SW_BUF + (uint32_t)(r * WB_ST + j * 16);
                    CP_ASYNC16(dst, src);
                }
                CP_COMMIT();
                CP_WAIT(1);
            } else {
                CP_WAIT(0);
            }
            __syncthreads();

            if (mActive) {
                const uint32_t wbBase = sbase + SW_OFF + buf * SW_BUF + bLane;
#pragma unroll
                for (int ks = 0; ks < 8; ks++) {
                    const uint32_t kOffA = (uint32_t)(kh * 256 + ks * 32);
                    uint32_t aF[2][4];
#pragma unroll
                    for (int mi = 0; mi < 2; mi++) {
                        uint32_t ad = aLaneOff + (uint32_t)(mi * 16 * A_ST * 2) + kOffA;
                        LDSM_X4(aF[mi][0], aF[mi][1], aF[mi][2], aF[mi][3], aBase + ad);
                    }
                    uint32_t bF[4][2];
#pragma unroll
                    for (int nb = 0; nb < 2; nb++) {
                        uint32_t bd = (uint32_t)((wn * 32 + nb * 16) * WB_ST + ks * 32);
                        uint32_t r0, r1, r2, r3;
                        LDSM_X4(r0, r1, r2, r3, wbBase + bd);
                        bF[2*nb][0] = r0; bF[2*nb][1] = r1;
                        bF[2*nb+1][0] = r2; bF[2*nb+1][1] = r3;
                    }
#pragma unroll
                    for (int mi = 0; mi < 2; mi++)
#pragma unroll
                        for (int nj = 0; nj < 4; nj++)
                            MMA_F16(acc[mi][nj], aF[mi], bF[nj]);
                }
            }
            __syncthreads();
        }

        // epilogue for this half
        if (mActive) {
#pragma unroll
            for (int mi = 0; mi < 2; mi++) {
                float p0 = 0.f, p1 = 0.f;
#pragma unroll
                for (int nj = 0; nj < 4; nj++) {
                    int col = half * 128 + wn * 32 + nj * 8 + tq * 2;
                    float b0 = sBias[col], b1 = sBias[col + 1];
                    float v0 = sV[col],    v1 = sV[col + 1];
                    p0 += tanh_fast(acc[mi][nj][0] + b0) * v0 + tanh_fast(acc[mi][nj][1] + b1) * v1;
                    p1 += tanh_fast(acc[mi][nj][2] + b0) * v0 + tanh_fast(acc[mi][nj][3] + b1) * v1;
                }
                p0 += __shfl_xor_sync(0xffffffffu, p0, 1);
                p0 += __shfl_xor_sync(0xffffffffu, p0, 2);
                p1 += __shfl_xor_sync(0xffffffffu, p1, 1);
                p1 += __shfl_xor_sync(0xffffffffu, p1, 2);
                if (tq == 0) {
                    int r0 = wm * 32 + mi * 16 + gp;
                    sPart[r0 * 4 + wn]       += p0;
                    sPart[(r0 + 8) * 4 + wn] += p1;
                }
            }
        }
    }
    __syncthreads();

    // ---------------- fused softmax-pool over this 128-row chunk ----------------
    float* sSc   = sBias;
    float* sRedS = sV;
    if (tid < 128) {
        float s = sPart[tid * 4] + sPart[tid * 4 + 1] + sPart[tid * 4 + 2] + sPart[tid * 4 + 3] + A.c[0];
        int msk = A.mask[row0 + tid];
        sSc[tid] = msk ? s : NEGV;
    }
    __syncthreads();
    if (tid < 64) sRedS[tid] = fmaxf(sSc[tid], sSc[tid + 64]);
    __syncthreads();
    if (tid < 32) {
        float m = fmaxf(sRedS[tid], sRedS[tid + 32]);
#pragma unroll
        for (int o = 16; o > 0; o >>= 1) m = fmaxf(m, __shfl_xor_sync(0xffffffffu, m, o));
        if (tid == 0) sRedS[0] = m;
    }
    __syncthreads();
    const float lmax = sRedS[0];
    __syncthreads();
    if (tid < 128) {
        float s = sSc[tid];
        sSc[tid] = (s > -1e8f) ? __expf(s - lmax) : 0.f;
    }
    __syncthreads();
    if (tid < 64) sRedS[tid] = sSc[tid] + sSc[tid + 64];
    __syncthreads();
    if (tid < 32) {
        float e = sRedS[tid] + sRedS[tid + 32];
#pragma unroll
        for (int o = 16; o > 0; o >>= 1) e += __shfl_xor_sync(0xffffffffu, e, o);
        if (tid == 0) sRedS[0] = e;
    }
    __syncthreads();
    const float esum = sRedS[0];

    // weighted column sums from fp16 A in smem (4 row-stripes of 32)
    float2* sRed2 = (float2*)(smem + SRED);
    const int c2 = tid & 127;
    const int rh = tid >> 7;
    float ax = 0.f, ay = 0.f;
#pragma unroll 8
    for (int r = 0; r < 32; r++) {
        int row = rh * 32 + r;
        float wv = sSc[row];
        __half2 a2 = *(const __half2*)(smem + SA_OFF + (size_t)(row * A_ST + c2 * 2) * 2);
        float2 af = __half22float2(a2);
        ax += wv * af.x; ay += wv * af.y;
    }
    sRed2[tid] = make_float2(ax, ay);
    __syncthreads();
    if (tid < 128) {
        float2 s0 = sRed2[tid], s1 = sRed2[tid + 128];
        float2 s2 = sRed2[tid + 256], s3 = sRed2[tid + 384];
        float2 out = make_float2(s0.x + s1.x + s2.x + s3.x, s0.y + s1.y + s2.y + s3.y);
        int b = row0 / A.S;
        int chunk = (row0 % A.S) >> 7;
        *(float2*)(g_psum + (((A.pool * BATCH) + b) * 16 + chunk) * HDIM + tid * 2) = out;
        if (tid == 0) {
            g_pmax[A.pool][b][chunk]  = lmax;
            g_pesum[A.pool][b][chunk] = esum;
        }
    }
}

// ---------------- chunk combine helpers ----------------
__device__ __forceinline__ void make_factors(int pool, int b, int nch,
                                             float* fac, float* invden) {
    float gmax = -3.4e38f;
    for (int c = 0; c < nch; c++) gmax = fmaxf(gmax, g_pmax[pool][b][c]);
    float den = 0.f;
    for (int c = 0; c < nch; c++) {
        float f = __expf(g_pmax[pool][b][c] - gmax);
        fac[c] = f;
        den += f * g_pesum[pool][b][c];
    }
    *invden = 1.f / den;
}

__device__ __forceinline__ float combine(int pool, int b, int col, int nch,
                                         const float* fac, float invden) {
    const float* pp = g_psum + (((pool * BATCH) + b) * 16) * HDIM + col;
    float s = 0.f;
#pragma unroll 4
    for (int c = 0; c < nch; c++) s += fac[c] * pp[c * HDIM];
    return s * invden;
}

// ---------------- fused code + hinge + finalize (512 blocks) ----------------
__global__ __launch_bounds__(256) void tail_kernel(const float* Wf, const float* bfv,
                                                   float* out) {
    int b  = blockIdx.x >> 3;
    int cg = blockIdx.x & 7;
    const int tid = threadIdx.x;
    const int jg = tid >> 5;
    const int ci = tid & 31;
    const int col = cg * 32 + ci;
    __shared__ float cat[2 * HDIM];
    __shared__ float part[256];
    __shared__ float fac0[16], fac1[4];
    __shared__ float inv0, inv1;
    __shared__ int doHinge;

    if (tid == 0) make_factors(0, b, 16, fac0, &inv0);
    if (tid == 32) make_factors(1, b, 4, fac1, &inv1);
    __syncthreads();

    cat[tid]        = tanh_fast(combine(0, b, tid, 16, fac0, inv0));
    cat[HDIM + tid] = tanh_fast(combine(1, b, tid, 4, fac1, inv1));
    __syncthreads();

    float acc = 0.f;
    const float* wp = Wf + col;
    const int j0 = jg * 64;
#pragma unroll 8
    for (int j = 0; j < 64; j++)
        acc += cat[j0 + j] * wp[(size_t)(j0 + j) * HDIM];
    part[tid] = acc;
    __syncthreads();
    if (tid < 32) {
        float s = bfv[cg * 32 + tid];
#pragma unroll
        for (int g = 0; g < 8; g++) s += part[g * 32 + tid];
        g_code[b * HDIM + cg * 32 + tid] = tanh_fast(s);
    }

    __syncthreads();
    if (tid == 0) {
        __threadfence();
        doHinge = (atomicAdd(&g_bcnt[b], 1) == 7) ? 1 : 0;
    }
    __syncthreads();
    if (!doHinge) return;

    {
        __shared__ float sm[8][5];
        __shared__ float fac2[4], fac3[4];
        __shared__ float inv2, inv3;
        __shared__ int isLast;
        const int warp = tid >> 5, lane = tid & 31;

        if (tid == 0) { make_factors(2, b, 4, fac2, &inv2); g_bcnt[b] = 0; }
        if (tid == 32) make_factors(3, b, 4, fac3, &inv3);
        __syncthreads();

        float c = g_code[b * HDIM + tid];
        float a = tanh_fast(tanh_fast(combine(2, b, tid, 4, fac2, inv2)));
        float n = tanh_fast(tanh_fast(combine(3, b, tid, 4, fac3, inv3)));
        float s0 = c * c, s1 = a * a, s2 = n * n, s3 = c * a, s4 = c * n;
#pragma unroll
        for (int o = 16; o > 0; o >>= 1) {
            s0 += __shfl_xor_sync(0xffffffffu, s0, o);
            s1 += __shfl_xor_sync(0xffffffffu, s1, o);
            s2 += __shfl_xor_sync(0xffffffffu, s2, o);
            s3 += __shfl_xor_sync(0xffffffffu, s3, o);
            s4 += __shfl_xor_sync(0xffffffffu, s4, o);
        }
        if (lane == 0) {
            sm[warp][0] = s0; sm[warp][1] = s1; sm[warp][2] = s2;
            sm[warp][3] = s3; sm[warp][4] = s4;
        }
        __syncthreads();
        if (tid == 0) {
            float t0 = 0, t1 = 0, t2 = 0, t3 = 0, t4 = 0;
#pragma unroll
            for (int wv = 0; wv < 8; wv++) {
                t0 += sm[wv][0]; t1 += sm[wv][1]; t2 += sm[wv][2];
                t3 += sm[wv][3]; t4 += sm[wv][4];
            }
            float nc = sqrtf(t0);
            float sa = t3 / fmaxf(nc * sqrtf(t1), 1e-8f);
            float sn = t4 / fmaxf(nc * sqrtf(t2), 1e-8f);
            g_hinge[b] = fmaxf(0.6f - sa + sn, 0.f);
            __threadfence();
            isLast = (atomicAdd(&g_cnt, 1) == BATCH - 1) ? 1 : 0;
        }
        __syncthreads();
        if (isLast && tid < 32) {
            float v = g_hinge[tid] + g_hinge[tid + 32];
#pragma unroll
            for (int o = 16; o > 0; o >>= 1) v += __shfl_xor_sync(0xffffffffu, v, o);
            if (tid == 0) {
                out[0] = v / (float)BATCH;
                g_cnt = 0;       // reset for graph replay
            }
        }
    }
}

// ---------------- launch ----------------
extern "C" void kernel_launch(void* const* d_in, const int* in_sizes, int n_in,
                              void* d_out, int out_size) {
    const float* token_feat = (const float*)d_in[0];
    const int*   token_mask = (const int*)d_in[1];
    const float* graph_feat = (const float*)d_in[2];
    const int*   graph_mask = (const int*)d_in[3];
    const float* da_feat    = (const float*)d_in[4];
    const int*   da_mask    = (const int*)d_in[5];
    const float* dn_feat    = (const float*)d_in[6];
    const int*   dn_mask    = (const int*)d_in[7];
    const float* Wt = (const float*)d_in[8];
    const float* bt = (const float*)d_in[9];
    const float* vt = (const float*)d_in[10];
    const float* ct = (const float*)d_in[11];
    const float* Wg = (const float*)d_in[12];
    const float* bg = (const float*)d_in[13];
    const float* vg = (const float*)d_in[14];
    const float* cg = (const float*)d_in[15];
    const float* Wd = (const float*)d_in[16];
    const float* bd = (const float*)d_in[17];
    const float* vd = (const float*)d_in[18];
    const float* cd = (const float*)d_in[19];
    const float* Wf = (const float*)d_in[20];
    const float* bf = (const float*)d_in[21];

    cudaFuncSetAttribute(score_tc, cudaFuncAttributeMaxDynamicSharedMemorySize, SCORE_SMEM);

    __half* wtp = nullptr;
    cudaGetSymbolAddress((void**)&wtp, g_WT);

    wconv_kernel<<<dim3(64, 3), 256>>>(Wt, Wg, Wd);

    const int nTok = BATCH * S_TOK / 128;   // 1024
    const int nOth = BATCH * S_OTH / 128;   // 256

    ScoreArgs sa0 = {token_feat, token_mask, bt, vt, ct, 0, 0,               0,      0, S_TOK};
    ScoreArgs sa1 = {graph_feat, graph_mask, bg, vg, cg, 1, nTok,            65536,  1, S_OTH};
    ScoreArgs sa2 = {da_feat,    da_mask,    bd, vd, cd, 0, nTok + nOth,     131072, 2, S_OTH};
    ScoreArgs sa3 = {dn_feat,    dn_mask,    bd, vd, cd, 0, nTok + 2 * nOth, 131072, 3, S_OTH};
    score_tc<<<nTok + 3 * nOth, 512, SCORE_SMEM>>>(sa0, sa1, sa2, sa3, wtp);

    tail_kernel<<<8 * BATCH, 256>>>(Wf, bf, (float*)d_out);
}